// round 1
// baseline (speedup 1.0000x reference)
#include <cuda_runtime.h>
#include <math.h>
#include <stdint.h>

// ---------------------------------------------------------------------------
// Problem max sizes (from reference setup_inputs)
// ---------------------------------------------------------------------------
#define NMAX   50000
#define MMAX   20000
#define NNZMAX 400000
#define HMAX   256

// ---------------------------------------------------------------------------
// Scratch (device globals: allocation-free rule)
// ---------------------------------------------------------------------------
__device__ float g_Xinit[NMAX * HMAX];
__device__ float g_Xfeat[NMAX * HMAX];
__device__ float g_Xacc [NMAX * HMAX];
__device__ float g_hbuf [NMAX * HMAX];
__device__ float g_Ye   [MMAX * HMAX];
__device__ float g_Ye2  [MMAX * HMAX];
__device__ float g_score[NMAX];
__device__ float g_ex   [NNZMAX];
__device__ float g_emax [MMAX];
__device__ float g_eden [MMAX];
__device__ float g_cntV [NMAX];
__device__ float g_cntE [MMAX];
__device__ float g_sumDv[MMAX];

// ---------------------------------------------------------------------------
// Small helpers
// ---------------------------------------------------------------------------
__device__ __forceinline__ float eluf(float x) {
    return x > 0.f ? x : expm1f(x);
}
__device__ __forceinline__ float leakyf(float x) {
    return x > 0.f ? x : 0.2f * x;
}
__device__ __forceinline__ void atomicMaxF(float* addr, float val) {
    int old = __float_as_int(*addr);
    while (__int_as_float(old) < val) {
        int assumed = old;
        old = atomicCAS((int*)addr, assumed, __float_as_int(val));
        if (old == assumed) break;
    }
}

__global__ void fillk(float* __restrict__ p, float v, long n) {
    long i = (long)blockIdx.x * blockDim.x + threadIdx.x;
    long stride = (long)gridDim.x * blockDim.x;
    for (; i < n; i += stride) p[i] = v;
}

__global__ void elu_inplace(float* __restrict__ p, long n) {
    long i = (long)blockIdx.x * blockDim.x + threadIdx.x;
    long stride = (long)gridDim.x * blockDim.x;
    for (; i < n; i += stride) p[i] = eluf(p[i]);
}

// ---------------------------------------------------------------------------
// SGEMM: C[M,N] = A[M,K] @ B[K,N] (+ bias[N]) (+= C if ACCUM)
// Requires N % 128 == 0, K % 16 == 0. M arbitrary.
// ---------------------------------------------------------------------------
template <bool ACCUM>
__global__ __launch_bounds__(256)
void sgemm128(const float* __restrict__ A, const float* __restrict__ B,
              const float* __restrict__ bias, float* __restrict__ C,
              int M, int N, int K)
{
    constexpr int BM = 128, BN = 128, BK = 16;
    __shared__ float As[BK][BM + 4];
    __shared__ float Bs[BK][BN + 4];

    const int tid  = threadIdx.x;
    const int row0 = blockIdx.y * BM;
    const int col0 = blockIdx.x * BN;
    const int tx   = tid & 15;   // 0..15 -> 8 output cols each
    const int ty   = tid >> 4;   // 0..15 -> 8 output rows each

    float acc[8][8];
#pragma unroll
    for (int i = 0; i < 8; i++)
#pragma unroll
        for (int j = 0; j < 8; j++) acc[i][j] = 0.f;

    for (int k0 = 0; k0 < K; k0 += BK) {
        // A tile: 128 rows x 16 cols = 512 float4 loads (transposed store)
#pragma unroll
        for (int t = 0; t < 2; t++) {
            int l = tid + t * 256;
            int r = l >> 2;
            int c = (l & 3) << 2;
            float4 v = make_float4(0.f, 0.f, 0.f, 0.f);
            int gr = row0 + r;
            if (gr < M) v = *reinterpret_cast<const float4*>(A + (size_t)gr * K + (k0 + c));
            As[c + 0][r] = v.x; As[c + 1][r] = v.y;
            As[c + 2][r] = v.z; As[c + 3][r] = v.w;
        }
        // B tile: 16 rows x 128 cols = 512 float4 loads
#pragma unroll
        for (int t = 0; t < 2; t++) {
            int l = tid + t * 256;
            int r = l >> 5;
            int c = (l & 31) << 2;
            float4 v = *reinterpret_cast<const float4*>(B + (size_t)(k0 + r) * N + (col0 + c));
            Bs[r][c + 0] = v.x; Bs[r][c + 1] = v.y;
            Bs[r][c + 2] = v.z; Bs[r][c + 3] = v.w;
        }
        __syncthreads();

#pragma unroll
        for (int k = 0; k < BK; k++) {
            float ra[8], rb[8];
            float4 a0 = *reinterpret_cast<const float4*>(&As[k][ty * 8]);
            float4 a1 = *reinterpret_cast<const float4*>(&As[k][ty * 8 + 4]);
            float4 b0 = *reinterpret_cast<const float4*>(&Bs[k][tx * 8]);
            float4 b1 = *reinterpret_cast<const float4*>(&Bs[k][tx * 8 + 4]);
            ra[0] = a0.x; ra[1] = a0.y; ra[2] = a0.z; ra[3] = a0.w;
            ra[4] = a1.x; ra[5] = a1.y; ra[6] = a1.z; ra[7] = a1.w;
            rb[0] = b0.x; rb[1] = b0.y; rb[2] = b0.z; rb[3] = b0.w;
            rb[4] = b1.x; rb[5] = b1.y; rb[6] = b1.z; rb[7] = b1.w;
#pragma unroll
            for (int i = 0; i < 8; i++)
#pragma unroll
                for (int j = 0; j < 8; j++)
                    acc[i][j] = fmaf(ra[i], rb[j], acc[i][j]);
        }
        __syncthreads();
    }

#pragma unroll
    for (int i = 0; i < 8; i++) {
        int gr = row0 + ty * 8 + i;
        if (gr >= M) continue;
        float* crow = C + (size_t)gr * N + col0 + tx * 8;
#pragma unroll
        for (int j = 0; j < 8; j++) {
            float v = acc[i][j];
            if (bias) v += bias[col0 + tx * 8 + j];
            if (ACCUM) v += crow[j];
            crow[j] = v;
        }
    }
}

// ---------------------------------------------------------------------------
// score[n] = dot(Xfeat[n,:], a)   (one warp per node)
// ---------------------------------------------------------------------------
__global__ void score_kernel(const float* __restrict__ Xfeat, const float* __restrict__ a,
                             float* __restrict__ score, int N, int H)
{
    int warp = (blockIdx.x * blockDim.x + threadIdx.x) >> 5;
    int lane = threadIdx.x & 31;
    if (warp >= N) return;
    const float4* row = reinterpret_cast<const float4*>(Xfeat + (size_t)warp * H);
    const float4* av  = reinterpret_cast<const float4*>(a);
    float s = 0.f;
    for (int c4 = lane; c4 < H / 4; c4 += 32) {
        float4 x = row[c4];
        float4 w = av[c4];
        s += x.x * w.x + x.y * w.y + x.z * w.z + x.w * w.w;
    }
#pragma unroll
    for (int o = 16; o > 0; o >>= 1) s += __shfl_xor_sync(0xffffffffu, s, o);
    if (lane == 0) score[warp] = s;
}

// ---------------------------------------------------------------------------
// Segment softmax passes over incidences
// ---------------------------------------------------------------------------
__global__ void edge_max_kernel(const int* __restrict__ V, const int* __restrict__ E,
                                const float* __restrict__ score, float* __restrict__ emax, int nnz)
{
    int i = blockIdx.x * blockDim.x + threadIdx.x;
    if (i >= nnz) return;
    float s = leakyf(score[V[i]]);
    atomicMaxF(&emax[E[i]], s);
}

__global__ void edge_exp_kernel(const int* __restrict__ V, const int* __restrict__ E,
                                const float* __restrict__ score, const float* __restrict__ emax,
                                float* __restrict__ ex, float* __restrict__ eden, int nnz)
{
    int i = blockIdx.x * blockDim.x + threadIdx.x;
    if (i >= nnz) return;
    float s = leakyf(score[V[i]]);
    float e = expf(s - emax[E[i]]);
    ex[i] = e;
    atomicAdd(&eden[E[i]], e);
}

// ---------------------------------------------------------------------------
// Weighted node->edge scatter: Ye[E[i],:] += Xfeat[V[i],:] * (ex[i]/eden[E[i]])
// One warp per incidence.
// ---------------------------------------------------------------------------
__global__ void scatter_v2e_w(const float* __restrict__ Xfeat,
                              const int* __restrict__ V, const int* __restrict__ E,
                              const float* __restrict__ ex, const float* __restrict__ eden,
                              float* __restrict__ Ye, int nnz, int H)
{
    int warp = (blockIdx.x * blockDim.x + threadIdx.x) >> 5;
    int lane = threadIdx.x & 31;
    if (warp >= nnz) return;
    int v = V[warp], e = E[warp];
    float w = ex[warp] / eden[e];
    const float4* src = reinterpret_cast<const float4*>(Xfeat + (size_t)v * H);
    float* dst = Ye + (size_t)e * H;
    for (int c4 = lane; c4 < H / 4; c4 += 32) {
        float4 x = src[c4];
        int c = c4 * 4;
        atomicAdd(dst + c + 0, x.x * w);
        atomicAdd(dst + c + 1, x.y * w);
        atomicAdd(dst + c + 2, x.z * w);
        atomicAdd(dst + c + 3, x.w * w);
    }
}

// Generic unweighted scatter: dst[sidx[i],:] += src[gidx[i],:]
__global__ void scatter_rows(const float* __restrict__ src,
                             const int* __restrict__ gidx, const int* __restrict__ sidx,
                             float* __restrict__ dst, int nnz, int C)
{
    int warp = (blockIdx.x * blockDim.x + threadIdx.x) >> 5;
    int lane = threadIdx.x & 31;
    if (warp >= nnz) return;
    int g = gidx[warp], s = sidx[warp];
    const float4* srow = reinterpret_cast<const float4*>(src + (size_t)g * C);
    float* drow = dst + (size_t)s * C;
    for (int c4 = lane; c4 < C / 4; c4 += 32) {
        float4 x = srow[c4];
        int c = c4 * 4;
        atomicAdd(drow + c + 0, x.x);
        atomicAdd(drow + c + 1, x.y);
        atomicAdd(drow + c + 2, x.z);
        atomicAdd(drow + c + 3, x.w);
    }
}

// ---------------------------------------------------------------------------
// Degree kernels
// ---------------------------------------------------------------------------
__global__ void deg_kernel(const int* __restrict__ V, const int* __restrict__ E,
                           float* __restrict__ cntV, float* __restrict__ cntE, int nnz)
{
    int i = blockIdx.x * blockDim.x + threadIdx.x;
    if (i >= nnz) return;
    atomicAdd(&cntV[V[i]], 1.f);
    atomicAdd(&cntE[E[i]], 1.f);
}

__global__ void sumdv_kernel(const int* __restrict__ V, const int* __restrict__ E,
                             const float* __restrict__ cntV, float* __restrict__ sumDv, int nnz)
{
    int i = blockIdx.x * blockDim.x + threadIdx.x;
    if (i >= nnz) return;
    atomicAdd(&sumDv[E[i]], cntV[V[i]]);
}

// ---------------------------------------------------------------------------
// Epilogues
// ---------------------------------------------------------------------------
// h = elu(seg_mean) + Xinit
__global__ void node_finish(const float* __restrict__ Xacc, const float* __restrict__ Xinit,
                            const float* __restrict__ cntV, float* __restrict__ h,
                            int N, int H)
{
    long total = (long)N * H;
    long i = (long)blockIdx.x * blockDim.x + threadIdx.x;
    long stride = (long)gridDim.x * blockDim.x;
    for (; i < total; i += stride) {
        int n = (int)(i / H);
        float c = cntV[n];
        float m = (c > 0.f) ? Xacc[i] / c : 0.f;
        h[i] = eluf(m) + Xinit[i];
    }
}

// Ye = De_inv * seg_mean(...)
__global__ void hyper_edge_finish(float* __restrict__ Ye, const float* __restrict__ cntE,
                                  const float* __restrict__ sumDv, int M, int O)
{
    long total = (long)M * O;
    long i = (long)blockIdx.x * blockDim.x + threadIdx.x;
    long stride = (long)gridDim.x * blockDim.x;
    for (; i < total; i += stride) {
        int e = (int)(i / O);
        float ce = cntE[e];
        float mean = (ce > 0.f) ? Ye[i] / ce : 0.f;
        float de = sumDv[e] / (ce + 1.f);
        float dinv = (de > 0.f) ? rsqrtf(de) : 1.f;
        Ye[i] = mean * dinv;
    }
}

__global__ void hyper_node_finish(const float* __restrict__ Xacc, const float* __restrict__ cntV,
                                  float* __restrict__ out, int N, int O)
{
    long total = (long)N * O;
    long i = (long)blockIdx.x * blockDim.x + threadIdx.x;
    long stride = (long)gridDim.x * blockDim.x;
    for (; i < total; i += stride) {
        int n = (int)(i / O);
        float dv = cntV[n];
        float dinv = (dv > 0.f) ? rsqrtf(dv) : 0.f;
        out[i] = Xacc[i] * dinv;
    }
}

// ---------------------------------------------------------------------------
// Host
// ---------------------------------------------------------------------------
static inline int ceil_div(int a, int b) { return (a + b - 1) / b; }

static inline void launch_fill(float* p, float v, long n) {
    int blocks = (int)((n + 255) / 256);
    if (blocks > 4096) blocks = 4096;
    fillk<<<blocks, 256>>>(p, v, n);
}

extern "C" void kernel_launch(void* const* d_in, const int* in_sizes, int n_in,
                              void* d_out, int out_size)
{
    const float* X   = (const float*)d_in[0];
    const int*   V   = (const int*)  d_in[1];
    const int*   E   = (const int*)  d_in[2];
    const float* S   = (const float*)d_in[3];
    const float* Wx0 = (const float*)d_in[4];
    const float* bx0 = (const float*)d_in[5];
    const float* Wv0 = (const float*)d_in[6];
    const float* bv0 = (const float*)d_in[7];
    const float* a0  = (const float*)d_in[8];
    const float* Wt0 = (const float*)d_in[9];
    const float* bt0 = (const float*)d_in[10];
    const float* Wx1 = (const float*)d_in[11];
    const float* bx1 = (const float*)d_in[12];
    const float* Wv1 = (const float*)d_in[13];
    const float* bv1 = (const float*)d_in[14];
    const float* a1  = (const float*)d_in[15];
    const float* Wt1 = (const float*)d_in[16];
    const float* bt1 = (const float*)d_in[17];
    const float* Wf  = (const float*)d_in[18];
    const float* bf  = (const float*)d_in[19];

    const int H    = in_sizes[5];              // 256
    const int IN   = in_sizes[4] / H;          // 128
    const int N    = in_sizes[0] / IN;         // 50000
    const int NNZ  = in_sizes[1];              // 400000
    const int HS   = in_sizes[9] / H;          // 320
    const int STAR = HS - H;                   // 64
    const int M    = in_sizes[3] / STAR;       // 20000
    const int OUT  = in_sizes[19];             // 128

    void* p;
    cudaGetSymbolAddress(&p, g_Xinit); float* Xinit = (float*)p;
    cudaGetSymbolAddress(&p, g_Xfeat); float* Xfeat = (float*)p;
    cudaGetSymbolAddress(&p, g_Xacc ); float* Xacc  = (float*)p;
    cudaGetSymbolAddress(&p, g_hbuf ); float* hbuf  = (float*)p;
    cudaGetSymbolAddress(&p, g_Ye   ); float* Ye    = (float*)p;
    cudaGetSymbolAddress(&p, g_Ye2  ); float* Ye2   = (float*)p;
    cudaGetSymbolAddress(&p, g_score); float* score = (float*)p;
    cudaGetSymbolAddress(&p, g_ex   ); float* ex    = (float*)p;
    cudaGetSymbolAddress(&p, g_emax ); float* emax  = (float*)p;
    cudaGetSymbolAddress(&p, g_eden ); float* eden  = (float*)p;
    cudaGetSymbolAddress(&p, g_cntV ); float* cntV  = (float*)p;
    cudaGetSymbolAddress(&p, g_cntE ); float* cntE  = (float*)p;
    cudaGetSymbolAddress(&p, g_sumDv); float* sumDv = (float*)p;

    const int nnzBlocks  = ceil_div(NNZ, 256);
    const int warpBlocks = ceil_div(NNZ, 8);   // one warp per incidence

    // ---- degrees (V,E static per launch) ----
    launch_fill(cntV, 0.f, N);
    launch_fill(cntE, 0.f, M);
    launch_fill(sumDv, 0.f, M);
    deg_kernel<<<nnzBlocks, 256>>>(V, E, cntV, cntE, NNZ);
    sumdv_kernel<<<nnzBlocks, 256>>>(V, E, cntV, sumDv, NNZ);

    // ---- one DPHGNN layer ----
    auto layer = [&](const float* Xin, int Kin,
                     const float* Wx, const float* bx,
                     const float* Wv, const float* bv, const float* av,
                     const float* Wt, const float* bt, float* hout)
    {
        dim3 gN(ceil_div(H, 128), ceil_div(N, 128));
        sgemm128<false><<<gN, 256>>>(Xin, Wx, bx, Xinit, N, H, Kin);
        sgemm128<false><<<gN, 256>>>(Xin, Wv, bv, Xfeat, N, H, Kin);

        score_kernel<<<ceil_div(N, 8), 256>>>(Xfeat, av, score, N, H);

        launch_fill(emax, -1e30f, M);
        launch_fill(eden, 0.f, M);
        launch_fill(Ye, 0.f, (long)M * H);

        edge_max_kernel<<<nnzBlocks, 256>>>(V, E, score, emax, NNZ);
        edge_exp_kernel<<<nnzBlocks, 256>>>(V, E, score, emax, ex, eden, NNZ);
        scatter_v2e_w<<<warpBlocks, 256>>>(Xfeat, V, E, ex, eden, Ye, NNZ, H);

        {
            long n = (long)M * H;
            int blocks = (int)((n + 255) / 256); if (blocks > 4096) blocks = 4096;
            elu_inplace<<<blocks, 256>>>(Ye, n);
        }

        dim3 gM(ceil_div(H, 128), ceil_div(M, 128));
        sgemm128<false><<<gM, 256>>>(Ye, Wt, bt, Ye2, M, H, H);
        sgemm128<true ><<<gM, 256>>>(S, Wt + (size_t)H * H, nullptr, Ye2, M, H, STAR);

        launch_fill(Xacc, 0.f, (long)N * H);
        scatter_rows<<<warpBlocks, 256>>>(Ye2, E, V, Xacc, NNZ, H);

        {
            long n = (long)N * H;
            int blocks = (int)((n + 255) / 256); if (blocks > 4096) blocks = 4096;
            node_finish<<<blocks, 256>>>(Xacc, Xinit, cntV, hout, N, H);
        }
    };

    layer(X,    IN, Wx0, bx0, Wv0, bv0, a0, Wt0, bt0, hbuf);
    layer(hbuf, H,  Wx1, bx1, Wv1, bv1, a1, Wt1, bt1, hbuf);

    // ---- hyperconv ----
    {
        dim3 gF(ceil_div(OUT, 128), ceil_div(N, 128));
        sgemm128<false><<<gF, 256>>>(hbuf, Wf, bf, Xfeat, N, OUT, H);

        launch_fill(Ye, 0.f, (long)M * OUT);
        scatter_rows<<<warpBlocks, 256>>>(Xfeat, V, E, Ye, NNZ, OUT);

        {
            long n = (long)M * OUT;
            int blocks = (int)((n + 255) / 256); if (blocks > 4096) blocks = 4096;
            hyper_edge_finish<<<blocks, 256>>>(Ye, cntE, sumDv, M, OUT);
        }

        launch_fill(Xacc, 0.f, (long)N * OUT);
        scatter_rows<<<warpBlocks, 256>>>(Ye, E, V, Xacc, NNZ, OUT);

        {
            long n = (long)N * OUT;
            int blocks = (int)((n + 255) / 256); if (blocks > 4096) blocks = 4096;
            hyper_node_finish<<<blocks, 256>>>(Xacc, cntV, (float*)d_out, N, OUT);
        }
    }
}

// round 2
// speedup vs baseline: 1.8729x; 1.8729x over previous
#include <cuda_runtime.h>
#include <math.h>
#include <stdint.h>

// ---------------------------------------------------------------------------
// Problem max sizes (from reference setup_inputs)
// ---------------------------------------------------------------------------
#define NMAX   50000
#define MMAX   20000
#define NNZMAX 400000
#define HMAX   256

// ---------------------------------------------------------------------------
// Scratch (device globals: allocation-free rule)
// ---------------------------------------------------------------------------
__device__ float g_Xinit[NMAX * HMAX];
__device__ float g_Xfeat[NMAX * HMAX];
__device__ float g_hbuf [NMAX * HMAX];
__device__ float g_Ye   [MMAX * HMAX];
__device__ float g_Ye2  [MMAX * HMAX];
__device__ float g_score[NMAX];

// CSR structures (rebuilt every launch; V,E are launch inputs)
__device__ int g_e_rowptr[MMAX + 1];
__device__ int g_v_rowptr[NMAX + 1];
__device__ int g_e_cursor[MMAX];
__device__ int g_v_cursor[NMAX];
__device__ int g_cntE[MMAX];
__device__ int g_cntV[NMAX];
__device__ int g_eV[NNZMAX];   // for each edge, its member node ids
__device__ int g_vE[NNZMAX];   // for each node, its incident edge ids

// ---------------------------------------------------------------------------
// Small helpers
// ---------------------------------------------------------------------------
__device__ __forceinline__ float eluf(float x)  { return x > 0.f ? x : expm1f(x); }
__device__ __forceinline__ float leakyf(float x){ return x > 0.f ? x : 0.2f * x; }

__global__ void fill_int(int* __restrict__ p, int v, int n) {
    int i = blockIdx.x * blockDim.x + threadIdx.x;
    int stride = gridDim.x * blockDim.x;
    for (; i < n; i += stride) p[i] = v;
}

// ---------------------------------------------------------------------------
// CSR construction
// ---------------------------------------------------------------------------
__global__ void count_kernel(const int* __restrict__ V, const int* __restrict__ E,
                             int* __restrict__ cntV, int* __restrict__ cntE, int nnz)
{
    int i = blockIdx.x * blockDim.x + threadIdx.x;
    if (i >= nnz) return;
    atomicAdd(&cntE[E[i]], 1);
    atomicAdd(&cntV[V[i]], 1);
}

// Single-block exclusive scan: cnt[len] -> rowptr[len+1]; also seeds cursor.
__global__ __launch_bounds__(1024)
void scan_kernel(const int* __restrict__ cnt, int* __restrict__ rowptr,
                 int* __restrict__ cursor, int len)
{
    __shared__ int buf[1024];
    __shared__ int s_carry;
    const int tid = threadIdx.x;
    if (tid == 0) s_carry = 0;
    __syncthreads();

    for (int base = 0; base < len; base += 1024) {
        int x = (base + tid < len) ? cnt[base + tid] : 0;
        buf[tid] = x;
        __syncthreads();
#pragma unroll
        for (int off = 1; off < 1024; off <<= 1) {
            int v = (tid >= off) ? buf[tid - off] : 0;
            __syncthreads();
            buf[tid] += v;
            __syncthreads();
        }
        int carry = s_carry;
        int excl = buf[tid] - x + carry;
        if (base + tid < len) { rowptr[base + tid] = excl; cursor[base + tid] = excl; }
        __syncthreads();
        if (tid == 1023) s_carry = carry + buf[1023];
        __syncthreads();
    }
    if (tid == 0) rowptr[len] = s_carry;
}

__global__ void fill_lists_kernel(const int* __restrict__ V, const int* __restrict__ E,
                                  int* __restrict__ e_cursor, int* __restrict__ v_cursor,
                                  int* __restrict__ eV, int* __restrict__ vE, int nnz)
{
    int i = blockIdx.x * blockDim.x + threadIdx.x;
    if (i >= nnz) return;
    int v = V[i], e = E[i];
    int pe = atomicAdd(&e_cursor[e], 1);
    eV[pe] = v;
    int pv = atomicAdd(&v_cursor[v], 1);
    vE[pv] = e;
}

// ---------------------------------------------------------------------------
// SGEMM: C[M,N] = A[M,K] @ B[K,N] (+ bias[N]) (+= C if ACCUM)
// Requires N % 128 == 0, K % 16 == 0. M arbitrary.
// ---------------------------------------------------------------------------
template <bool ACCUM>
__global__ __launch_bounds__(256)
void sgemm128(const float* __restrict__ A, const float* __restrict__ B,
              const float* __restrict__ bias, float* __restrict__ C,
              int M, int N, int K)
{
    constexpr int BM = 128, BN = 128, BK = 16;
    __shared__ float As[BK][BM + 4];
    __shared__ float Bs[BK][BN + 4];

    const int tid  = threadIdx.x;
    const int row0 = blockIdx.y * BM;
    const int col0 = blockIdx.x * BN;
    const int tx   = tid & 15;
    const int ty   = tid >> 4;

    float acc[8][8];
#pragma unroll
    for (int i = 0; i < 8; i++)
#pragma unroll
        for (int j = 0; j < 8; j++) acc[i][j] = 0.f;

    for (int k0 = 0; k0 < K; k0 += BK) {
#pragma unroll
        for (int t = 0; t < 2; t++) {
            int l = tid + t * 256;
            int r = l >> 2;
            int c = (l & 3) << 2;
            float4 v = make_float4(0.f, 0.f, 0.f, 0.f);
            int gr = row0 + r;
            if (gr < M) v = *reinterpret_cast<const float4*>(A + (size_t)gr * K + (k0 + c));
            As[c + 0][r] = v.x; As[c + 1][r] = v.y;
            As[c + 2][r] = v.z; As[c + 3][r] = v.w;
        }
#pragma unroll
        for (int t = 0; t < 2; t++) {
            int l = tid + t * 256;
            int r = l >> 5;
            int c = (l & 31) << 2;
            float4 v = *reinterpret_cast<const float4*>(B + (size_t)(k0 + r) * N + (col0 + c));
            Bs[r][c + 0] = v.x; Bs[r][c + 1] = v.y;
            Bs[r][c + 2] = v.z; Bs[r][c + 3] = v.w;
        }
        __syncthreads();

#pragma unroll
        for (int k = 0; k < BK; k++) {
            float ra[8], rb[8];
            float4 a0 = *reinterpret_cast<const float4*>(&As[k][ty * 8]);
            float4 a1 = *reinterpret_cast<const float4*>(&As[k][ty * 8 + 4]);
            float4 b0 = *reinterpret_cast<const float4*>(&Bs[k][tx * 8]);
            float4 b1 = *reinterpret_cast<const float4*>(&Bs[k][tx * 8 + 4]);
            ra[0] = a0.x; ra[1] = a0.y; ra[2] = a0.z; ra[3] = a0.w;
            ra[4] = a1.x; ra[5] = a1.y; ra[6] = a1.z; ra[7] = a1.w;
            rb[0] = b0.x; rb[1] = b0.y; rb[2] = b0.z; rb[3] = b0.w;
            rb[4] = b1.x; rb[5] = b1.y; rb[6] = b1.z; rb[7] = b1.w;
#pragma unroll
            for (int i = 0; i < 8; i++)
#pragma unroll
                for (int j = 0; j < 8; j++)
                    acc[i][j] = fmaf(ra[i], rb[j], acc[i][j]);
        }
        __syncthreads();
    }

#pragma unroll
    for (int i = 0; i < 8; i++) {
        int gr = row0 + ty * 8 + i;
        if (gr >= M) continue;
        float* crow = C + (size_t)gr * N + col0 + tx * 8;
#pragma unroll
        for (int j = 0; j < 8; j++) {
            float v = acc[i][j];
            if (bias) v += bias[col0 + tx * 8 + j];
            if (ACCUM) v += crow[j];
            crow[j] = v;
        }
    }
}

// ---------------------------------------------------------------------------
// score[n] = dot(Xfeat[n,:], a)   (one warp per node)
// ---------------------------------------------------------------------------
__global__ void score_kernel(const float* __restrict__ Xfeat, const float* __restrict__ a,
                             float* __restrict__ score, int N, int H)
{
    int warp = (blockIdx.x * blockDim.x + threadIdx.x) >> 5;
    int lane = threadIdx.x & 31;
    if (warp >= N) return;
    const float4* row = reinterpret_cast<const float4*>(Xfeat + (size_t)warp * H);
    const float4* av  = reinterpret_cast<const float4*>(a);
    float s = 0.f;
    for (int c4 = lane; c4 < H / 4; c4 += 32) {
        float4 x = row[c4];
        float4 w = av[c4];
        s += x.x * w.x + x.y * w.y + x.z * w.z + x.w * w.w;
    }
#pragma unroll
    for (int o = 16; o > 0; o >>= 1) s += __shfl_xor_sync(0xffffffffu, s, o);
    if (lane == 0) score[warp] = s;
}

// ---------------------------------------------------------------------------
// Fused v2e: per-edge segment softmax over member scores + weighted feature
// gather + elu.  One warp per edge.  CH4 = H/128 float4-chunks per lane.
//   Ye[e,:] = elu( sum_m softmax_m(leaky(score[v_m])) * Xfeat[v_m,:] )
// ---------------------------------------------------------------------------
template <int CH4>
__global__ __launch_bounds__(256)
void v2e_softmax_kernel(const float* __restrict__ Xfeat, const float* __restrict__ score,
                        const int* __restrict__ e_rowptr, const int* __restrict__ eV,
                        float* __restrict__ Ye, int M, int H)
{
    int warp = (blockIdx.x * blockDim.x + threadIdx.x) >> 5;
    int lane = threadIdx.x & 31;
    if (warp >= M) return;
    const int beg = e_rowptr[warp];
    const int end = e_rowptr[warp + 1];

    // phase 1: segment max of leaky(score)
    float m = -1e30f;
    for (int j = beg + lane; j < end; j += 32)
        m = fmaxf(m, leakyf(__ldg(&score[eV[j]])));
#pragma unroll
    for (int o = 16; o > 0; o >>= 1) m = fmaxf(m, __shfl_xor_sync(0xffffffffu, m, o));

    // phase 2: denom
    float den = 0.f;
    for (int j = beg + lane; j < end; j += 32)
        den += expf(leakyf(__ldg(&score[eV[j]])) - m);
#pragma unroll
    for (int o = 16; o > 0; o >>= 1) den += __shfl_xor_sync(0xffffffffu, den, o);
    float invden = (end > beg) ? 1.f / den : 0.f;

    // phase 3: weighted feature accumulation
    float4 acc[CH4];
#pragma unroll
    for (int c = 0; c < CH4; c++) acc[c] = make_float4(0.f, 0.f, 0.f, 0.f);

    for (int j = beg; j < end; j++) {
        int v = eV[j];                                   // broadcast load
        float w = expf(leakyf(__ldg(&score[v])) - m) * invden;
        const float4* row = reinterpret_cast<const float4*>(Xfeat + (size_t)v * H);
#pragma unroll
        for (int c = 0; c < CH4; c++) {
            float4 x = __ldg(&row[lane + 32 * c]);
            acc[c].x = fmaf(x.x, w, acc[c].x);
            acc[c].y = fmaf(x.y, w, acc[c].y);
            acc[c].z = fmaf(x.z, w, acc[c].z);
            acc[c].w = fmaf(x.w, w, acc[c].w);
        }
    }

    float4* drow = reinterpret_cast<float4*>(Ye + (size_t)warp * H);
#pragma unroll
    for (int c = 0; c < CH4; c++) {
        float4 o;
        o.x = eluf(acc[c].x); o.y = eluf(acc[c].y);
        o.z = eluf(acc[c].z); o.w = eluf(acc[c].w);
        drow[lane + 32 * c] = o;
    }
}

// ---------------------------------------------------------------------------
// Fused e2v: per-node mean over incident edge rows + elu + residual add.
//   h[n,:] = elu( mean_e Ye2[e,:] ) + Xinit[n,:]
// ---------------------------------------------------------------------------
template <int CH4>
__global__ __launch_bounds__(256)
void e2v_mean_kernel(const float* __restrict__ Ye2,
                     const int* __restrict__ v_rowptr, const int* __restrict__ vE,
                     const float* __restrict__ Xinit, float* __restrict__ hout,
                     int N, int H)
{
    int warp = (blockIdx.x * blockDim.x + threadIdx.x) >> 5;
    int lane = threadIdx.x & 31;
    if (warp >= N) return;
    const int beg = v_rowptr[warp];
    const int end = v_rowptr[warp + 1];

    float4 acc[CH4];
#pragma unroll
    for (int c = 0; c < CH4; c++) acc[c] = make_float4(0.f, 0.f, 0.f, 0.f);

    for (int j = beg; j < end; j++) {
        int e = vE[j];
        const float4* row = reinterpret_cast<const float4*>(Ye2 + (size_t)e * H);
#pragma unroll
        for (int c = 0; c < CH4; c++) {
            float4 x = __ldg(&row[lane + 32 * c]);
            acc[c].x += x.x; acc[c].y += x.y; acc[c].z += x.z; acc[c].w += x.w;
        }
    }
    float inv = (end > beg) ? 1.f / (float)(end - beg) : 0.f;

    const float4* xi = reinterpret_cast<const float4*>(Xinit + (size_t)warp * H);
    float4* drow = reinterpret_cast<float4*>(hout + (size_t)warp * H);
#pragma unroll
    for (int c = 0; c < CH4; c++) {
        float4 r = __ldg(&xi[lane + 32 * c]);
        float4 o;
        o.x = eluf(acc[c].x * inv) + r.x;
        o.y = eluf(acc[c].y * inv) + r.y;
        o.z = eluf(acc[c].z * inv) + r.z;
        o.w = eluf(acc[c].w * inv) + r.w;
        drow[lane + 32 * c] = o;
    }
}

// ---------------------------------------------------------------------------
// Hyperconv edge: Ye[e,:] = De^-1/2 * mean_m Xn[v_m,:]
//   De = (sum_m Dv[v_m]) / (cnt_e + 1); De_inv = De>0 ? De^-1/2 : 1
// ---------------------------------------------------------------------------
template <int CH4>
__global__ __launch_bounds__(256)
void hyper_edge_kernel(const float* __restrict__ Xn,
                       const int* __restrict__ e_rowptr, const int* __restrict__ eV,
                       const int* __restrict__ v_rowptr,
                       float* __restrict__ Ye, int M, int O)
{
    int warp = (blockIdx.x * blockDim.x + threadIdx.x) >> 5;
    int lane = threadIdx.x & 31;
    if (warp >= M) return;
    const int beg = e_rowptr[warp];
    const int end = e_rowptr[warp + 1];
    const int cnt = end - beg;

    // sum of member node degrees (lane-strided)
    float sumDv = 0.f;
    for (int j = beg + lane; j < end; j += 32) {
        int v = eV[j];
        sumDv += (float)(__ldg(&v_rowptr[v + 1]) - __ldg(&v_rowptr[v]));
    }
#pragma unroll
    for (int o = 16; o > 0; o >>= 1) sumDv += __shfl_xor_sync(0xffffffffu, sumDv, o);

    float4 acc[CH4];
#pragma unroll
    for (int c = 0; c < CH4; c++) acc[c] = make_float4(0.f, 0.f, 0.f, 0.f);

    for (int j = beg; j < end; j++) {
        int v = eV[j];
        const float4* row = reinterpret_cast<const float4*>(Xn + (size_t)v * O);
#pragma unroll
        for (int c = 0; c < CH4; c++) {
            float4 x = __ldg(&row[lane + 32 * c]);
            acc[c].x += x.x; acc[c].y += x.y; acc[c].z += x.z; acc[c].w += x.w;
        }
    }

    float invc = (cnt > 0) ? 1.f / (float)cnt : 0.f;
    float De = sumDv / ((float)cnt + 1.f);
    float dinv = (De > 0.f) ? rsqrtf(De) : 1.f;
    float s = invc * dinv;

    float4* drow = reinterpret_cast<float4*>(Ye + (size_t)warp * O);
#pragma unroll
    for (int c = 0; c < CH4; c++) {
        float4 o;
        o.x = acc[c].x * s; o.y = acc[c].y * s;
        o.z = acc[c].z * s; o.w = acc[c].w * s;
        drow[lane + 32 * c] = o;
    }
}

// ---------------------------------------------------------------------------
// Hyperconv node: out[n,:] = Dv^-1/2 * sum_e Ye[e,:]
// ---------------------------------------------------------------------------
template <int CH4>
__global__ __launch_bounds__(256)
void hyper_node_kernel(const float* __restrict__ Ye,
                       const int* __restrict__ v_rowptr, const int* __restrict__ vE,
                       float* __restrict__ out, int N, int O)
{
    int warp = (blockIdx.x * blockDim.x + threadIdx.x) >> 5;
    int lane = threadIdx.x & 31;
    if (warp >= N) return;
    const int beg = v_rowptr[warp];
    const int end = v_rowptr[warp + 1];
    const int deg = end - beg;

    float4 acc[CH4];
#pragma unroll
    for (int c = 0; c < CH4; c++) acc[c] = make_float4(0.f, 0.f, 0.f, 0.f);

    for (int j = beg; j < end; j++) {
        int e = vE[j];
        const float4* row = reinterpret_cast<const float4*>(Ye + (size_t)e * O);
#pragma unroll
        for (int c = 0; c < CH4; c++) {
            float4 x = __ldg(&row[lane + 32 * c]);
            acc[c].x += x.x; acc[c].y += x.y; acc[c].z += x.z; acc[c].w += x.w;
        }
    }
    float dinv = (deg > 0) ? rsqrtf((float)deg) : 0.f;

    float4* drow = reinterpret_cast<float4*>(out + (size_t)warp * O);
#pragma unroll
    for (int c = 0; c < CH4; c++) {
        float4 o;
        o.x = acc[c].x * dinv; o.y = acc[c].y * dinv;
        o.z = acc[c].z * dinv; o.w = acc[c].w * dinv;
        drow[lane + 32 * c] = o;
    }
}

// ---------------------------------------------------------------------------
// Host
// ---------------------------------------------------------------------------
static inline int ceil_div(int a, int b) { return (a + b - 1) / b; }

extern "C" void kernel_launch(void* const* d_in, const int* in_sizes, int n_in,
                              void* d_out, int out_size)
{
    const float* X   = (const float*)d_in[0];
    const int*   V   = (const int*)  d_in[1];
    const int*   E   = (const int*)  d_in[2];
    const float* S   = (const float*)d_in[3];
    const float* Wx0 = (const float*)d_in[4];
    const float* bx0 = (const float*)d_in[5];
    const float* Wv0 = (const float*)d_in[6];
    const float* bv0 = (const float*)d_in[7];
    const float* a0  = (const float*)d_in[8];
    const float* Wt0 = (const float*)d_in[9];
    const float* bt0 = (const float*)d_in[10];
    const float* Wx1 = (const float*)d_in[11];
    const float* bx1 = (const float*)d_in[12];
    const float* Wv1 = (const float*)d_in[13];
    const float* bv1 = (const float*)d_in[14];
    const float* a1  = (const float*)d_in[15];
    const float* Wt1 = (const float*)d_in[16];
    const float* bt1 = (const float*)d_in[17];
    const float* Wf  = (const float*)d_in[18];
    const float* bf  = (const float*)d_in[19];

    const int H    = in_sizes[5];              // 256
    const int IN   = in_sizes[4] / H;          // 128
    const int N    = in_sizes[0] / IN;         // 50000
    const int NNZ  = in_sizes[1];              // 400000
    const int HS   = in_sizes[9] / H;          // 320
    const int STAR = HS - H;                   // 64
    const int M    = in_sizes[3] / STAR;       // 20000
    const int OUT  = in_sizes[19];             // 128

    void* p;
    cudaGetSymbolAddress(&p, g_Xinit);    float* Xinit    = (float*)p;
    cudaGetSymbolAddress(&p, g_Xfeat);    float* Xfeat    = (float*)p;
    cudaGetSymbolAddress(&p, g_hbuf);     float* hbuf     = (float*)p;
    cudaGetSymbolAddress(&p, g_Ye);       float* Ye       = (float*)p;
    cudaGetSymbolAddress(&p, g_Ye2);      float* Ye2      = (float*)p;
    cudaGetSymbolAddress(&p, g_score);    float* score    = (float*)p;
    cudaGetSymbolAddress(&p, g_e_rowptr); int*   e_rowptr = (int*)p;
    cudaGetSymbolAddress(&p, g_v_rowptr); int*   v_rowptr = (int*)p;
    cudaGetSymbolAddress(&p, g_e_cursor); int*   e_cursor = (int*)p;
    cudaGetSymbolAddress(&p, g_v_cursor); int*   v_cursor = (int*)p;
    cudaGetSymbolAddress(&p, g_cntE);     int*   cntE     = (int*)p;
    cudaGetSymbolAddress(&p, g_cntV);     int*   cntV     = (int*)p;
    cudaGetSymbolAddress(&p, g_eV);       int*   eV       = (int*)p;
    cudaGetSymbolAddress(&p, g_vE);       int*   vE       = (int*)p;

    const int nnzBlocks = ceil_div(NNZ, 256);

    // ---- CSR build (V,E static within a launch) ----
    fill_int<<<ceil_div(M, 256), 256>>>(cntE, 0, M);
    fill_int<<<ceil_div(N, 256), 256>>>(cntV, 0, N);
    count_kernel<<<nnzBlocks, 256>>>(V, E, cntV, cntE, NNZ);
    scan_kernel<<<1, 1024>>>(cntE, e_rowptr, e_cursor, M);
    scan_kernel<<<1, 1024>>>(cntV, v_rowptr, v_cursor, N);
    fill_lists_kernel<<<nnzBlocks, 256>>>(V, E, e_cursor, v_cursor, eV, vE, NNZ);

    const int edgeWarpBlocks = ceil_div(M, 8);
    const int nodeWarpBlocks = ceil_div(N, 8);

    // ---- one DPHGNN layer ----
    auto layer = [&](const float* Xin, int Kin,
                     const float* Wx, const float* bx,
                     const float* Wv, const float* bv, const float* av,
                     const float* Wt, const float* bt, float* hout)
    {
        dim3 gN(ceil_div(H, 128), ceil_div(N, 128));
        sgemm128<false><<<gN, 256>>>(Xin, Wx, bx, Xinit, N, H, Kin);
        sgemm128<false><<<gN, 256>>>(Xin, Wv, bv, Xfeat, N, H, Kin);

        score_kernel<<<ceil_div(N, 8), 256>>>(Xfeat, av, score, N, H);

        // fused segment softmax + weighted gather + elu  (H=256 -> CH4=2)
        v2e_softmax_kernel<2><<<edgeWarpBlocks, 256>>>(Xfeat, score, e_rowptr, eV, Ye, M, H);

        dim3 gM(ceil_div(H, 128), ceil_div(M, 128));
        sgemm128<false><<<gM, 256>>>(Ye, Wt, bt, Ye2, M, H, H);
        sgemm128<true ><<<gM, 256>>>(S, Wt + (size_t)H * H, nullptr, Ye2, M, H, STAR);

        // fused mean + elu + residual
        e2v_mean_kernel<2><<<nodeWarpBlocks, 256>>>(Ye2, v_rowptr, vE, Xinit, hout, N, H);
    };

    layer(X,    IN, Wx0, bx0, Wv0, bv0, a0, Wt0, bt0, hbuf);
    layer(hbuf, H,  Wx1, bx1, Wv1, bv1, a1, Wt1, bt1, hbuf);

    // ---- hyperconv ----
    {
        dim3 gF(ceil_div(OUT, 128), ceil_div(N, 128));
        sgemm128<false><<<gF, 256>>>(hbuf, Wf, bf, Xfeat, N, OUT, H);

        // OUT=128 -> CH4=1
        hyper_edge_kernel<1><<<edgeWarpBlocks, 256>>>(Xfeat, e_rowptr, eV, v_rowptr, Ye, M, OUT);
        hyper_node_kernel<1><<<nodeWarpBlocks, 256>>>(Ye, v_rowptr, vE, (float*)d_out, N, OUT);
    }
}

// round 3
// speedup vs baseline: 2.7268x; 1.4559x over previous
#include <cuda_runtime.h>
#include <cuda_bf16.h>
#include <mma.h>
#include <math.h>
#include <stdint.h>

using namespace nvcuda;

// ---------------------------------------------------------------------------
// Problem max sizes
// ---------------------------------------------------------------------------
#define NMAX   50000
#define MMAX   20000
#define NNZMAX 400000
#define HMAX   256
#define WTOTAL 393216   // total weight elements (all 7 matrices)

// ---------------------------------------------------------------------------
// Scratch (device globals)
// ---------------------------------------------------------------------------
__device__ float g_Xinit[NMAX * HMAX];
__device__ float g_Xfeat[NMAX * HMAX];
__device__ float g_Ye2  [MMAX * HMAX];
__device__ float g_score[NMAX];

__device__ __nv_bfloat16 g_Ah [NMAX * HMAX];  // X (layer0 A) / h2 (layer1 e2v out)
__device__ __nv_bfloat16 g_Al [NMAX * HMAX];
__device__ __nv_bfloat16 g_Bh [NMAX * HMAX];  // h1 (layer0 e2v out)
__device__ __nv_bfloat16 g_Bl [NMAX * HMAX];
__device__ __nv_bfloat16 g_Yeh[MMAX * HMAX];
__device__ __nv_bfloat16 g_Yel[MMAX * HMAX];
__device__ __nv_bfloat16 g_Sh [MMAX * 64];
__device__ __nv_bfloat16 g_Sl [MMAX * 64];
__device__ __nv_bfloat16 g_Wh [WTOTAL];
__device__ __nv_bfloat16 g_Wl [WTOTAL];

// CSR structures
__device__ int g_e_rowptr[MMAX + 1];
__device__ int g_v_rowptr[NMAX + 1];
__device__ int g_e_cursor[MMAX];
__device__ int g_v_cursor[NMAX];
__device__ int g_cntE[MMAX];
__device__ int g_cntV[NMAX];
__device__ int g_eV[NNZMAX];
__device__ int g_vE[NNZMAX];

// ---------------------------------------------------------------------------
// Helpers
// ---------------------------------------------------------------------------
__device__ __forceinline__ float eluf(float x)  { return x > 0.f ? x : expm1f(x); }
__device__ __forceinline__ float leakyf(float x){ return x > 0.f ? x : 0.2f * x; }

// split one float4 into hi/lo bf16 quadruples and store (8B each)
__device__ __forceinline__ void split_store4(float4 v, __nv_bfloat16* ph, __nv_bfloat16* pl) {
    __nv_bfloat162 h0, h1, l0, l1;
    h0.x = __float2bfloat16_rn(v.x); h0.y = __float2bfloat16_rn(v.y);
    h1.x = __float2bfloat16_rn(v.z); h1.y = __float2bfloat16_rn(v.w);
    l0.x = __float2bfloat16_rn(v.x - __bfloat162float(h0.x));
    l0.y = __float2bfloat16_rn(v.y - __bfloat162float(h0.y));
    l1.x = __float2bfloat16_rn(v.z - __bfloat162float(h1.x));
    l1.y = __float2bfloat16_rn(v.w - __bfloat162float(h1.y));
    uint2 uh, ul;
    uh.x = *reinterpret_cast<unsigned*>(&h0); uh.y = *reinterpret_cast<unsigned*>(&h1);
    ul.x = *reinterpret_cast<unsigned*>(&l0); ul.y = *reinterpret_cast<unsigned*>(&l1);
    *reinterpret_cast<uint2*>(ph) = uh;
    *reinterpret_cast<uint2*>(pl) = ul;
}

__global__ void split_kernel(const float* __restrict__ x, __nv_bfloat16* __restrict__ hi,
                             __nv_bfloat16* __restrict__ lo, long n4)
{
    long i = (long)blockIdx.x * blockDim.x + threadIdx.x;
    long stride = (long)gridDim.x * blockDim.x;
    for (; i < n4; i += stride) {
        float4 v = reinterpret_cast<const float4*>(x)[i];
        split_store4(v, hi + 4 * i, lo + 4 * i);
    }
}

__global__ void fill_int(int* __restrict__ p, int v, int n) {
    int i = blockIdx.x * blockDim.x + threadIdx.x;
    int stride = gridDim.x * blockDim.x;
    for (; i < n; i += stride) p[i] = v;
}

// ---------------------------------------------------------------------------
// CSR construction
// ---------------------------------------------------------------------------
__global__ void count_kernel(const int* __restrict__ V, const int* __restrict__ E,
                             int* __restrict__ cntV, int* __restrict__ cntE, int nnz)
{
    int i = blockIdx.x * blockDim.x + threadIdx.x;
    if (i >= nnz) return;
    atomicAdd(&cntE[E[i]], 1);
    atomicAdd(&cntV[V[i]], 1);
}

// Single-block exclusive scan, 4 elems/thread per chunk, shfl-based.
__global__ __launch_bounds__(1024)
void scan_kernel(const int* __restrict__ cnt, int* __restrict__ rowptr,
                 int* __restrict__ cursor, int len)
{
    __shared__ int wsum[32];
    __shared__ int s_carry;
    const int tid = threadIdx.x, lane = tid & 31, wid = tid >> 5;
    if (tid == 0) s_carry = 0;
    __syncthreads();

    for (int base = 0; base < len; base += 4096) {
        int i0 = base + tid * 4;
        int v0 = (i0 + 0 < len) ? cnt[i0 + 0] : 0;
        int v1 = (i0 + 1 < len) ? cnt[i0 + 1] : 0;
        int v2 = (i0 + 2 < len) ? cnt[i0 + 2] : 0;
        int v3 = (i0 + 3 < len) ? cnt[i0 + 3] : 0;
        int t1 = v0 + v1, t2 = t1 + v2, t3 = t2 + v3;

        int inc = t3;
#pragma unroll
        for (int o = 1; o < 32; o <<= 1) {
            int u = __shfl_up_sync(0xffffffffu, inc, o);
            if (lane >= o) inc += u;
        }
        if (lane == 31) wsum[wid] = inc;
        __syncthreads();
        if (wid == 0) {
            int w = wsum[lane];
            int wi = w;
#pragma unroll
            for (int o = 1; o < 32; o <<= 1) {
                int u = __shfl_up_sync(0xffffffffu, wi, o);
                if (lane >= o) wi += u;
            }
            wsum[lane] = wi - w;   // exclusive
        }
        __syncthreads();
        int excl = s_carry + wsum[wid] + (inc - t3);
        if (i0 + 0 < len) { rowptr[i0 + 0] = excl;      cursor[i0 + 0] = excl; }
        if (i0 + 1 < len) { rowptr[i0 + 1] = excl + v0; cursor[i0 + 1] = excl + v0; }
        if (i0 + 2 < len) { rowptr[i0 + 2] = excl + t1; cursor[i0 + 2] = excl + t1; }
        if (i0 + 3 < len) { rowptr[i0 + 3] = excl + t2; cursor[i0 + 3] = excl + t2; }
        __syncthreads();
        if (tid == 1023) s_carry = s_carry + wsum[31] + inc;
        __syncthreads();
    }
    if (threadIdx.x == 0) rowptr[len] = s_carry;
}

__global__ void fill_lists_kernel(const int* __restrict__ V, const int* __restrict__ E,
                                  int* __restrict__ e_cursor, int* __restrict__ v_cursor,
                                  int* __restrict__ eV, int* __restrict__ vE, int nnz)
{
    int i = blockIdx.x * blockDim.x + threadIdx.x;
    if (i >= nnz) return;
    int v = V[i], e = E[i];
    int pe = atomicAdd(&e_cursor[e], 1);
    eV[pe] = v;
    int pv = atomicAdd(&v_cursor[v], 1);
    vE[pv] = e;
}

// ---------------------------------------------------------------------------
// bf16x3 tensor-core GEMM:  C[M,N] = [A1 | A2] @ B + bias, fp32 out.
// A given as hi/lo bf16 pairs, row-major, K1 (+K2) columns; B hi/lo [K,N] row-major.
// BM=128, BN=128, BK=32; 256 threads (8 warps, 4x2), warp tile 32x64.
// Requires N % 128 == 0, K1 % 32 == 0, K2 % 32 == 0.
// ---------------------------------------------------------------------------
#define GBM 128
#define GBN 128
#define GBK 32

__global__ __launch_bounds__(256)
void gemm_bf16x3(const __nv_bfloat16* __restrict__ A1h, const __nv_bfloat16* __restrict__ A1l, int K1,
                 const __nv_bfloat16* __restrict__ A2h, const __nv_bfloat16* __restrict__ A2l, int K2,
                 const __nv_bfloat16* __restrict__ Bh,  const __nv_bfloat16* __restrict__ Bl,
                 const float* __restrict__ bias, float* __restrict__ C,
                 int M, int N)
{
    const int K = K1 + K2;
    __shared__ union {
        struct {
            __nv_bfloat16 Ah[GBM][GBK + 8];
            __nv_bfloat16 Al[GBM][GBK + 8];
            __nv_bfloat16 Bh[GBK][GBN + 8];
            __nv_bfloat16 Bl[GBK][GBN + 8];
        } t;
        float stage[8][320];
    } sm;

    const int tid  = threadIdx.x;
    const int wid  = tid >> 5, lane = tid & 31;
    const int wm   = wid >> 1, wn = wid & 1;
    const int row0 = blockIdx.y * GBM;
    const int col0 = blockIdx.x * GBN;

    wmma::fragment<wmma::accumulator, 16, 16, 16, float> acc[2][4];
#pragma unroll
    for (int mt = 0; mt < 2; mt++)
#pragma unroll
        for (int nt = 0; nt < 4; nt++) wmma::fill_fragment(acc[mt][nt], 0.f);

    for (int k0 = 0; k0 < K; k0 += GBK) {
        const __nv_bfloat16 *Ahs, *Als; int lda, kk;
        if (k0 < K1) { Ahs = A1h; Als = A1l; lda = K1; kk = k0; }
        else         { Ahs = A2h; Als = A2l; lda = K2; kk = k0 - K1; }

        // A tile: 128 rows x 32 cols bf16 (2 x uint4 per thread)
#pragma unroll
        for (int t = 0; t < 2; t++) {
            int l = tid + t * 256;
            int r = l >> 2, q = l & 3;
            int gr = row0 + r;
            uint4 vh = make_uint4(0, 0, 0, 0), vl = make_uint4(0, 0, 0, 0);
            if (gr < M) {
                size_t off = (size_t)gr * lda + kk + q * 8;
                vh = *reinterpret_cast<const uint4*>(Ahs + off);
                vl = *reinterpret_cast<const uint4*>(Als + off);
            }
            *reinterpret_cast<uint4*>(&sm.t.Ah[r][q * 8]) = vh;
            *reinterpret_cast<uint4*>(&sm.t.Al[r][q * 8]) = vl;
        }
        // B tile: 32 rows x 128 cols
#pragma unroll
        for (int t = 0; t < 2; t++) {
            int l = tid + t * 256;
            int r = l >> 4, q = l & 15;
            size_t off = (size_t)(k0 + r) * N + col0 + q * 8;
            *reinterpret_cast<uint4*>(&sm.t.Bh[r][q * 8]) = *reinterpret_cast<const uint4*>(Bh + off);
            *reinterpret_cast<uint4*>(&sm.t.Bl[r][q * 8]) = *reinterpret_cast<const uint4*>(Bl + off);
        }
        __syncthreads();

#pragma unroll
        for (int ks = 0; ks < 2; ks++) {
            wmma::fragment<wmma::matrix_a, 16, 16, 16, __nv_bfloat16, wmma::row_major> ah[2], al[2];
#pragma unroll
            for (int mt = 0; mt < 2; mt++) {
                wmma::load_matrix_sync(ah[mt], &sm.t.Ah[wm * 32 + mt * 16][ks * 16], GBK + 8);
                wmma::load_matrix_sync(al[mt], &sm.t.Al[wm * 32 + mt * 16][ks * 16], GBK + 8);
            }
#pragma unroll
            for (int nt = 0; nt < 4; nt++) {
                wmma::fragment<wmma::matrix_b, 16, 16, 16, __nv_bfloat16, wmma::row_major> bh, bl;
                wmma::load_matrix_sync(bh, &sm.t.Bh[ks * 16][wn * 64 + nt * 16], GBN + 8);
                wmma::load_matrix_sync(bl, &sm.t.Bl[ks * 16][wn * 64 + nt * 16], GBN + 8);
#pragma unroll
                for (int mt = 0; mt < 2; mt++) {
                    wmma::mma_sync(acc[mt][nt], ah[mt], bh, acc[mt][nt]);
                    wmma::mma_sync(acc[mt][nt], al[mt], bh, acc[mt][nt]);
                    wmma::mma_sync(acc[mt][nt], ah[mt], bl, acc[mt][nt]);
                }
            }
        }
        __syncthreads();
    }

    // epilogue: stage each 16x16 tile in smem, add bias, coalesced-ish store
    float* stg = sm.stage[wid];
#pragma unroll
    for (int mt = 0; mt < 2; mt++) {
#pragma unroll
        for (int nt = 0; nt < 4; nt++) {
            wmma::store_matrix_sync(stg, acc[mt][nt], 20, wmma::mem_row_major);
            __syncwarp();
            int r = lane >> 1, c = (lane & 1) * 8;
            int gr = row0 + wm * 32 + mt * 16 + r;
            int gc = col0 + wn * 64 + nt * 16 + c;
            if (gr < M) {
                float4 o0, o1;
                o0.x = stg[r * 20 + c + 0] + bias[gc + 0];
                o0.y = stg[r * 20 + c + 1] + bias[gc + 1];
                o0.z = stg[r * 20 + c + 2] + bias[gc + 2];
                o0.w = stg[r * 20 + c + 3] + bias[gc + 3];
                o1.x = stg[r * 20 + c + 4] + bias[gc + 4];
                o1.y = stg[r * 20 + c + 5] + bias[gc + 5];
                o1.z = stg[r * 20 + c + 6] + bias[gc + 6];
                o1.w = stg[r * 20 + c + 7] + bias[gc + 7];
                *reinterpret_cast<float4*>(C + (size_t)gr * N + gc)     = o0;
                *reinterpret_cast<float4*>(C + (size_t)gr * N + gc + 4) = o1;
            }
            __syncwarp();
        }
    }
}

// ---------------------------------------------------------------------------
// score[n] = dot(Xfeat[n,:], a)
// ---------------------------------------------------------------------------
__global__ void score_kernel(const float* __restrict__ Xfeat, const float* __restrict__ a,
                             float* __restrict__ score, int N, int H)
{
    int warp = (blockIdx.x * blockDim.x + threadIdx.x) >> 5;
    int lane = threadIdx.x & 31;
    if (warp >= N) return;
    const float4* row = reinterpret_cast<const float4*>(Xfeat + (size_t)warp * H);
    const float4* av  = reinterpret_cast<const float4*>(a);
    float s = 0.f;
    for (int c4 = lane; c4 < H / 4; c4 += 32) {
        float4 x = row[c4];
        float4 w = av[c4];
        s += x.x * w.x + x.y * w.y + x.z * w.z + x.w * w.w;
    }
#pragma unroll
    for (int o = 16; o > 0; o >>= 1) s += __shfl_xor_sync(0xffffffffu, s, o);
    if (lane == 0) score[warp] = s;
}

// ---------------------------------------------------------------------------
// Fused v2e: segment softmax + weighted gather + elu -> bf16 hi/lo outputs
// ---------------------------------------------------------------------------
template <int CH4>
__global__ __launch_bounds__(256)
void v2e_softmax_kernel(const float* __restrict__ Xfeat, const float* __restrict__ score,
                        const int* __restrict__ e_rowptr, const int* __restrict__ eV,
                        __nv_bfloat16* __restrict__ Yeh, __nv_bfloat16* __restrict__ Yel,
                        int M, int H)
{
    int warp = (blockIdx.x * blockDim.x + threadIdx.x) >> 5;
    int lane = threadIdx.x & 31;
    if (warp >= M) return;
    const int beg = e_rowptr[warp];
    const int end = e_rowptr[warp + 1];

    float m = -1e30f;
    for (int j = beg + lane; j < end; j += 32)
        m = fmaxf(m, leakyf(__ldg(&score[eV[j]])));
#pragma unroll
    for (int o = 16; o > 0; o >>= 1) m = fmaxf(m, __shfl_xor_sync(0xffffffffu, m, o));

    float den = 0.f;
    for (int j = beg + lane; j < end; j += 32)
        den += expf(leakyf(__ldg(&score[eV[j]])) - m);
#pragma unroll
    for (int o = 16; o > 0; o >>= 1) den += __shfl_xor_sync(0xffffffffu, den, o);
    float invden = (end > beg) ? 1.f / den : 0.f;

    float4 acc[CH4];
#pragma unroll
    for (int c = 0; c < CH4; c++) acc[c] = make_float4(0.f, 0.f, 0.f, 0.f);

    for (int j = beg; j < end; j++) {
        int v = eV[j];
        float w = expf(leakyf(__ldg(&score[v])) - m) * invden;
        const float4* row = reinterpret_cast<const float4*>(Xfeat + (size_t)v * H);
#pragma unroll
        for (int c = 0; c < CH4; c++) {
            float4 x = __ldg(&row[lane + 32 * c]);
            acc[c].x = fmaf(x.x, w, acc[c].x);
            acc[c].y = fmaf(x.y, w, acc[c].y);
            acc[c].z = fmaf(x.z, w, acc[c].z);
            acc[c].w = fmaf(x.w, w, acc[c].w);
        }
    }

#pragma unroll
    for (int c = 0; c < CH4; c++) {
        float4 o;
        o.x = eluf(acc[c].x); o.y = eluf(acc[c].y);
        o.z = eluf(acc[c].z); o.w = eluf(acc[c].w);
        size_t off = (size_t)warp * H + (lane + 32 * c) * 4;
        split_store4(o, Yeh + off, Yel + off);
    }
}

// ---------------------------------------------------------------------------
// Fused e2v: mean + elu + residual -> bf16 hi/lo outputs
// ---------------------------------------------------------------------------
template <int CH4>
__global__ __launch_bounds__(256)
void e2v_mean_kernel(const float* __restrict__ Ye2,
                     const int* __restrict__ v_rowptr, const int* __restrict__ vE,
                     const float* __restrict__ Xinit,
                     __nv_bfloat16* __restrict__ hh, __nv_bfloat16* __restrict__ hl,
                     int N, int H)
{
    int warp = (blockIdx.x * blockDim.x + threadIdx.x) >> 5;
    int lane = threadIdx.x & 31;
    if (warp >= N) return;
    const int beg = v_rowptr[warp];
    const int end = v_rowptr[warp + 1];

    float4 acc[CH4];
#pragma unroll
    for (int c = 0; c < CH4; c++) acc[c] = make_float4(0.f, 0.f, 0.f, 0.f);

    for (int j = beg; j < end; j++) {
        int e = vE[j];
        const float4* row = reinterpret_cast<const float4*>(Ye2 + (size_t)e * H);
#pragma unroll
        for (int c = 0; c < CH4; c++) {
            float4 x = __ldg(&row[lane + 32 * c]);
            acc[c].x += x.x; acc[c].y += x.y; acc[c].z += x.z; acc[c].w += x.w;
        }
    }
    float inv = (end > beg) ? 1.f / (float)(end - beg) : 0.f;

    const float4* xi = reinterpret_cast<const float4*>(Xinit + (size_t)warp * H);
#pragma unroll
    for (int c = 0; c < CH4; c++) {
        float4 r = __ldg(&xi[lane + 32 * c]);
        float4 o;
        o.x = eluf(acc[c].x * inv) + r.x;
        o.y = eluf(acc[c].y * inv) + r.y;
        o.z = eluf(acc[c].z * inv) + r.z;
        o.w = eluf(acc[c].w * inv) + r.w;
        size_t off = (size_t)warp * H + (lane + 32 * c) * 4;
        split_store4(o, hh + off, hl + off);
    }
}

// ---------------------------------------------------------------------------
// Hyperconv edge + node (fp32)
// ---------------------------------------------------------------------------
template <int CH4>
__global__ __launch_bounds__(256)
void hyper_edge_kernel(const float* __restrict__ Xn,
                       const int* __restrict__ e_rowptr, const int* __restrict__ eV,
                       const int* __restrict__ v_rowptr,
                       float* __restrict__ Ye, int M, int O)
{
    int warp = (blockIdx.x * blockDim.x + threadIdx.x) >> 5;
    int lane = threadIdx.x & 31;
    if (warp >= M) return;
    const int beg = e_rowptr[warp];
    const int end = e_rowptr[warp + 1];
    const int cnt = end - beg;

    float sumDv = 0.f;
    for (int j = beg + lane; j < end; j += 32) {
        int v = eV[j];
        sumDv += (float)(__ldg(&v_rowptr[v + 1]) - __ldg(&v_rowptr[v]));
    }
#pragma unroll
    for (int o = 16; o > 0; o >>= 1) sumDv += __shfl_xor_sync(0xffffffffu, sumDv, o);

    float4 acc[CH4];
#pragma unroll
    for (int c = 0; c < CH4; c++) acc[c] = make_float4(0.f, 0.f, 0.f, 0.f);

    for (int j = beg; j < end; j++) {
        int v = eV[j];
        const float4* row = reinterpret_cast<const float4*>(Xn + (size_t)v * O);
#pragma unroll
        for (int c = 0; c < CH4; c++) {
            float4 x = __ldg(&row[lane + 32 * c]);
            acc[c].x += x.x; acc[c].y += x.y; acc[c].z += x.z; acc[c].w += x.w;
        }
    }

    float invc = (cnt > 0) ? 1.f / (float)cnt : 0.f;
    float De = sumDv / ((float)cnt + 1.f);
    float dinv = (De > 0.f) ? rsqrtf(De) : 1.f;
    float s = invc * dinv;

    float4* drow = reinterpret_cast<float4*>(Ye + (size_t)warp * O);
#pragma unroll
    for (int c = 0; c < CH4; c++) {
        float4 o;
        o.x = acc[c].x * s; o.y = acc[c].y * s;
        o.z = acc[c].z * s; o.w = acc[c].w * s;
        drow[lane + 32 * c] = o;
    }
}

template <int CH4>
__global__ __launch_bounds__(256)
void hyper_node_kernel(const float* __restrict__ Ye,
                       const int* __restrict__ v_rowptr, const int* __restrict__ vE,
                       float* __restrict__ out, int N, int O)
{
    int warp = (blockIdx.x * blockDim.x + threadIdx.x) >> 5;
    int lane = threadIdx.x & 31;
    if (warp >= N) return;
    const int beg = v_rowptr[warp];
    const int end = v_rowptr[warp + 1];
    const int deg = end - beg;

    float4 acc[CH4];
#pragma unroll
    for (int c = 0; c < CH4; c++) acc[c] = make_float4(0.f, 0.f, 0.f, 0.f);

    for (int j = beg; j < end; j++) {
        int e = vE[j];
        const float4* row = reinterpret_cast<const float4*>(Ye + (size_t)e * O);
#pragma unroll
        for (int c = 0; c < CH4; c++) {
            float4 x = __ldg(&row[lane + 32 * c]);
            acc[c].x += x.x; acc[c].y += x.y; acc[c].z += x.z; acc[c].w += x.w;
        }
    }
    float dinv = (deg > 0) ? rsqrtf((float)deg) : 0.f;

    float4* drow = reinterpret_cast<float4*>(out + (size_t)warp * O);
#pragma unroll
    for (int c = 0; c < CH4; c++) {
        float4 o;
        o.x = acc[c].x * dinv; o.y = acc[c].y * dinv;
        o.z = acc[c].z * dinv; o.w = acc[c].w * dinv;
        drow[lane + 32 * c] = o;
    }
}

// ---------------------------------------------------------------------------
// Host
// ---------------------------------------------------------------------------
static inline int ceil_div(int a, int b) { return (a + b - 1) / b; }

extern "C" void kernel_launch(void* const* d_in, const int* in_sizes, int n_in,
                              void* d_out, int out_size)
{
    const float* X   = (const float*)d_in[0];
    const int*   V   = (const int*)  d_in[1];
    const int*   E   = (const int*)  d_in[2];
    const float* S   = (const float*)d_in[3];
    const float* Wx0 = (const float*)d_in[4];
    const float* bx0 = (const float*)d_in[5];
    const float* Wv0 = (const float*)d_in[6];
    const float* bv0 = (const float*)d_in[7];
    const float* a0  = (const float*)d_in[8];
    const float* Wt0 = (const float*)d_in[9];
    const float* bt0 = (const float*)d_in[10];
    const float* Wx1 = (const float*)d_in[11];
    const float* bx1 = (const float*)d_in[12];
    const float* Wv1 = (const float*)d_in[13];
    const float* bv1 = (const float*)d_in[14];
    const float* a1  = (const float*)d_in[15];
    const float* Wt1 = (const float*)d_in[16];
    const float* bt1 = (const float*)d_in[17];
    const float* Wf  = (const float*)d_in[18];
    const float* bf  = (const float*)d_in[19];

    const int H    = in_sizes[5];              // 256
    const int IN   = in_sizes[4] / H;          // 128
    const int N    = in_sizes[0] / IN;         // 50000
    const int NNZ  = in_sizes[1];              // 400000
    const int HS   = in_sizes[9] / H;          // 320
    const int STAR = HS - H;                   // 64
    const int M    = in_sizes[3] / STAR;       // 20000
    const int OUT  = in_sizes[19];             // 128

    void* p;
    cudaGetSymbolAddress(&p, g_Xinit);    float* Xinit = (float*)p;
    cudaGetSymbolAddress(&p, g_Xfeat);    float* Xfeat = (float*)p;
    cudaGetSymbolAddress(&p, g_Ye2);      float* Ye2   = (float*)p;
    cudaGetSymbolAddress(&p, g_score);    float* score = (float*)p;
    cudaGetSymbolAddress(&p, g_Ah);  __nv_bfloat16* Ah  = (__nv_bfloat16*)p;
    cudaGetSymbolAddress(&p, g_Al);  __nv_bfloat16* Al  = (__nv_bfloat16*)p;
    cudaGetSymbolAddress(&p, g_Bh);  __nv_bfloat16* Bhh = (__nv_bfloat16*)p;
    cudaGetSymbolAddress(&p, g_Bl);  __nv_bfloat16* Bll = (__nv_bfloat16*)p;
    cudaGetSymbolAddress(&p, g_Yeh); __nv_bfloat16* Yeh = (__nv_bfloat16*)p;
    cudaGetSymbolAddress(&p, g_Yel); __nv_bfloat16* Yel = (__nv_bfloat16*)p;
    cudaGetSymbolAddress(&p, g_Sh);  __nv_bfloat16* Sh  = (__nv_bfloat16*)p;
    cudaGetSymbolAddress(&p, g_Sl);  __nv_bfloat16* Sl  = (__nv_bfloat16*)p;
    cudaGetSymbolAddress(&p, g_Wh);  __nv_bfloat16* Wh  = (__nv_bfloat16*)p;
    cudaGetSymbolAddress(&p, g_Wl);  __nv_bfloat16* Wl  = (__nv_bfloat16*)p;
    cudaGetSymbolAddress(&p, g_e_rowptr); int* e_rowptr = (int*)p;
    cudaGetSymbolAddress(&p, g_v_rowptr); int* v_rowptr = (int*)p;
    cudaGetSymbolAddress(&p, g_e_cursor); int* e_cursor = (int*)p;
    cudaGetSymbolAddress(&p, g_v_cursor); int* v_cursor = (int*)p;
    cudaGetSymbolAddress(&p, g_cntE);     int* cntE     = (int*)p;
    cudaGetSymbolAddress(&p, g_cntV);     int* cntV     = (int*)p;
    cudaGetSymbolAddress(&p, g_eV);       int* eV       = (int*)p;
    cudaGetSymbolAddress(&p, g_vE);       int* vE       = (int*)p;

    // weight offsets inside the packed hi/lo buffers
    const size_t o_wx0 = 0;
    const size_t o_wv0 = o_wx0 + (size_t)IN * H;         // 32768
    const size_t o_wt0 = o_wv0 + (size_t)IN * H;         // 65536
    const size_t o_wx1 = o_wt0 + (size_t)HS * H;         // 147456
    const size_t o_wv1 = o_wx1 + (size_t)H * H;          // 212992
    const size_t o_wt1 = o_wv1 + (size_t)H * H;          // 278528
    const size_t o_wf  = o_wt1 + (size_t)HS * H;         // 360448

    auto split = [&](const float* src, __nv_bfloat16* dh, __nv_bfloat16* dl, long nelem) {
        long n4 = nelem / 4;
        int blocks = (int)((n4 + 255) / 256); if (blocks > 2048) blocks = 2048;
        split_kernel<<<blocks, 256>>>(src, dh, dl, n4);
    };

    // ---- splits ----
    split(X,   Ah, Al, (long)N * IN);
    split(S,   Sh, Sl, (long)M * STAR);
    split(Wx0, Wh + o_wx0, Wl + o_wx0, (long)IN * H);
    split(Wv0, Wh + o_wv0, Wl + o_wv0, (long)IN * H);
    split(Wt0, Wh + o_wt0, Wl + o_wt0, (long)HS * H);
    split(Wx1, Wh + o_wx1, Wl + o_wx1, (long)H * H);
    split(Wv1, Wh + o_wv1, Wl + o_wv1, (long)H * H);
    split(Wt1, Wh + o_wt1, Wl + o_wt1, (long)HS * H);
    split(Wf,  Wh + o_wf,  Wl + o_wf,  (long)H * OUT);

    // ---- CSR build ----
    const int nnzBlocks = ceil_div(NNZ, 256);
    fill_int<<<ceil_div(M, 256), 256>>>(cntE, 0, M);
    fill_int<<<ceil_div(N, 256), 256>>>(cntV, 0, N);
    count_kernel<<<nnzBlocks, 256>>>(V, E, cntV, cntE, NNZ);
    scan_kernel<<<1, 1024>>>(cntE, e_rowptr, e_cursor, M);
    scan_kernel<<<1, 1024>>>(cntV, v_rowptr, v_cursor, N);
    fill_lists_kernel<<<nnzBlocks, 256>>>(V, E, e_cursor, v_cursor, eV, vE, NNZ);

    const int edgeWarpBlocks = ceil_div(M, 8);
    const int nodeWarpBlocks = ceil_div(N, 8);

    auto gemm = [&](const __nv_bfloat16* a1h, const __nv_bfloat16* a1l, int K1,
                    const __nv_bfloat16* a2h, const __nv_bfloat16* a2l, int K2,
                    size_t woff, const float* bias, float* C, int Mrows, int Ncols) {
        dim3 grid(Ncols / GBN, ceil_div(Mrows, GBM));
        gemm_bf16x3<<<grid, 256>>>(a1h, a1l, K1, a2h, a2l, K2,
                                   Wh + woff, Wl + woff, bias, C, Mrows, Ncols);
    };

    // ---- layer 0 ----
    gemm(Ah, Al, IN, nullptr, nullptr, 0, o_wx0, bx0, Xinit, N, H);
    gemm(Ah, Al, IN, nullptr, nullptr, 0, o_wv0, bv0, Xfeat, N, H);
    score_kernel<<<ceil_div(N, 8), 256>>>(Xfeat, a0, score, N, H);
    v2e_softmax_kernel<2><<<edgeWarpBlocks, 256>>>(Xfeat, score, e_rowptr, eV, Yeh, Yel, M, H);
    gemm(Yeh, Yel, H, Sh, Sl, STAR, o_wt0, bt0, Ye2, M, H);
    e2v_mean_kernel<2><<<nodeWarpBlocks, 256>>>(Ye2, v_rowptr, vE, Xinit, Bhh, Bll, N, H);

    // ---- layer 1 ----
    gemm(Bhh, Bll, H, nullptr, nullptr, 0, o_wx1, bx1, Xinit, N, H);
    gemm(Bhh, Bll, H, nullptr, nullptr, 0, o_wv1, bv1, Xfeat, N, H);
    score_kernel<<<ceil_div(N, 8), 256>>>(Xfeat, a1, score, N, H);
    v2e_softmax_kernel<2><<<edgeWarpBlocks, 256>>>(Xfeat, score, e_rowptr, eV, Yeh, Yel, M, H);
    gemm(Yeh, Yel, H, Sh, Sl, STAR, o_wt1, bt1, Ye2, M, H);
    e2v_mean_kernel<2><<<nodeWarpBlocks, 256>>>(Ye2, v_rowptr, vE, Xinit, Ah, Al, N, H);

    // ---- hyperconv ----
    gemm(Ah, Al, H, nullptr, nullptr, 0, o_wf, bf, Xfeat, N, OUT);
    hyper_edge_kernel<1><<<edgeWarpBlocks, 256>>>(Xfeat, e_rowptr, eV, v_rowptr, Ye2, M, OUT);
    hyper_node_kernel<1><<<nodeWarpBlocks, 256>>>(Ye2, v_rowptr, vE, (float*)d_out, N, OUT);
}

// round 5
// speedup vs baseline: 2.8621x; 1.0496x over previous
#include <cuda_runtime.h>
#include <cuda_bf16.h>
#include <mma.h>
#include <math.h>
#include <stdint.h>

using namespace nvcuda;

// ---------------------------------------------------------------------------
// Problem max sizes
// ---------------------------------------------------------------------------
#define NMAX   50000
#define MMAX   20000
#define NNZMAX 400000
#define HMAX   256
#define WTOTAL 393216

// ---------------------------------------------------------------------------
// Scratch (device globals)
// ---------------------------------------------------------------------------
__device__ float g_Xinit[NMAX * HMAX];
__device__ float g_Xfeat[NMAX * HMAX];
__device__ float g_Ye2  [MMAX * HMAX];
__device__ float g_score[NMAX];

__device__ __nv_bfloat16 g_Ah [NMAX * HMAX];
__device__ __nv_bfloat16 g_Al [NMAX * HMAX];
__device__ __nv_bfloat16 g_Bh [NMAX * HMAX];
__device__ __nv_bfloat16 g_Bl [NMAX * HMAX];
__device__ __nv_bfloat16 g_Yeh[MMAX * HMAX];
__device__ __nv_bfloat16 g_Yel[MMAX * HMAX];
__device__ __nv_bfloat16 g_Sh [MMAX * 64];
__device__ __nv_bfloat16 g_Sl [MMAX * 64];
__device__ __nv_bfloat16 g_Wh [WTOTAL];   // [K,N] row-major, packed
__device__ __nv_bfloat16 g_Wl [WTOTAL];

// CSR structures
__device__ int g_e_rowptr[MMAX + 1];
__device__ int g_v_rowptr[NMAX + 1];
__device__ int g_e_cursor[MMAX];
__device__ int g_v_cursor[NMAX];
__device__ int g_cntE[MMAX];
__device__ int g_cntV[NMAX];
__device__ int g_eV[NNZMAX];
__device__ int g_vE[NNZMAX];

// ---------------------------------------------------------------------------
// Helpers
// ---------------------------------------------------------------------------
__device__ __forceinline__ float eluf(float x)  { return x > 0.f ? x : expm1f(x); }
__device__ __forceinline__ float leakyf(float x){ return x > 0.f ? x : 0.2f * x; }

__device__ __forceinline__ uint32_t smem_to_u32(const void* p) {
    uint32_t a;
    asm("{ .reg .u64 t; cvta.to.shared.u64 t, %1; cvt.u32.u64 %0, t; }" : "=r"(a) : "l"(p));
    return a;
}
__device__ __forceinline__ void cp_async16(uint32_t dst, const void* src, int sz) {
    asm volatile("cp.async.cg.shared.global [%0], [%1], 16, %2;"
                 :: "r"(dst), "l"(src), "r"(sz) : "memory");
}
#define CP_COMMIT() asm volatile("cp.async.commit_group;" ::: "memory")
#define CP_WAIT(n)  asm volatile("cp.async.wait_group %0;" :: "n"(n) : "memory")

__device__ __forceinline__ void split_store4(float4 v, __nv_bfloat16* ph, __nv_bfloat16* pl) {
    __nv_bfloat162 h0, h1, l0, l1;
    h0.x = __float2bfloat16_rn(v.x); h0.y = __float2bfloat16_rn(v.y);
    h1.x = __float2bfloat16_rn(v.z); h1.y = __float2bfloat16_rn(v.w);
    l0.x = __float2bfloat16_rn(v.x - __bfloat162float(h0.x));
    l0.y = __float2bfloat16_rn(v.y - __bfloat162float(h0.y));
    l1.x = __float2bfloat16_rn(v.z - __bfloat162float(h1.x));
    l1.y = __float2bfloat16_rn(v.w - __bfloat162float(h1.y));
    uint2 uh, ul;
    uh.x = *reinterpret_cast<unsigned*>(&h0); uh.y = *reinterpret_cast<unsigned*>(&h1);
    ul.x = *reinterpret_cast<unsigned*>(&l0); ul.y = *reinterpret_cast<unsigned*>(&l1);
    *reinterpret_cast<uint2*>(ph) = uh;
    *reinterpret_cast<uint2*>(pl) = ul;
}

__global__ void split_kernel(const float* __restrict__ x, __nv_bfloat16* __restrict__ hi,
                             __nv_bfloat16* __restrict__ lo, long n4)
{
    long i = (long)blockIdx.x * blockDim.x + threadIdx.x;
    long stride = (long)gridDim.x * blockDim.x;
    for (; i < n4; i += stride) {
        float4 v = reinterpret_cast<const float4*>(x)[i];
        split_store4(v, hi + 4 * i, lo + 4 * i);
    }
}

__global__ void fill_int(int* __restrict__ p, int v, int n) {
    int i = blockIdx.x * blockDim.x + threadIdx.x;
    int stride = gridDim.x * blockDim.x;
    for (; i < n; i += stride) p[i] = v;
}

// ---------------------------------------------------------------------------
// CSR construction
// ---------------------------------------------------------------------------
__global__ void count_kernel(const int* __restrict__ V, const int* __restrict__ E,
                             int* __restrict__ cntV, int* __restrict__ cntE, int nnz)
{
    int i = blockIdx.x * blockDim.x + threadIdx.x;
    if (i >= nnz) return;
    atomicAdd(&cntE[E[i]], 1);
    atomicAdd(&cntV[V[i]], 1);
}

__global__ __launch_bounds__(1024)
void scan_kernel(const int* __restrict__ cnt, int* __restrict__ rowptr,
                 int* __restrict__ cursor, int len)
{
    __shared__ int wsum[32];
    __shared__ int s_carry;
    const int tid = threadIdx.x, lane = tid & 31, wid = tid >> 5;
    if (tid == 0) s_carry = 0;
    __syncthreads();

    for (int base = 0; base < len; base += 4096) {
        int i0 = base + tid * 4;
        int v0 = (i0 + 0 < len) ? cnt[i0 + 0] : 0;
        int v1 = (i0 + 1 < len) ? cnt[i0 + 1] : 0;
        int v2 = (i0 + 2 < len) ? cnt[i0 + 2] : 0;
        int v3 = (i0 + 3 < len) ? cnt[i0 + 3] : 0;
        int t1 = v0 + v1, t2 = t1 + v2, t3 = t2 + v3;

        int inc = t3;
#pragma unroll
        for (int o = 1; o < 32; o <<= 1) {
            int u = __shfl_up_sync(0xffffffffu, inc, o);
            if (lane >= o) inc += u;
        }
        if (lane == 31) wsum[wid] = inc;
        __syncthreads();
        if (wid == 0) {
            int w = wsum[lane];
            int wi = w;
#pragma unroll
            for (int o = 1; o < 32; o <<= 1) {
                int u = __shfl_up_sync(0xffffffffu, wi, o);
                if (lane >= o) wi += u;
            }
            wsum[lane] = wi - w;
        }
        __syncthreads();
        int excl = s_carry + wsum[wid] + (inc - t3);
        if (i0 + 0 < len) { rowptr[i0 + 0] = excl;      cursor[i0 + 0] = excl; }
        if (i0 + 1 < len) { rowptr[i0 + 1] = excl + v0; cursor[i0 + 1] = excl + v0; }
        if (i0 + 2 < len) { rowptr[i0 + 2] = excl + t1; cursor[i0 + 2] = excl + t1; }
        if (i0 + 3 < len) { rowptr[i0 + 3] = excl + t2; cursor[i0 + 3] = excl + t2; }
        __syncthreads();
        if (tid == 1023) s_carry = s_carry + wsum[31] + inc;
        __syncthreads();
    }
    if (threadIdx.x == 0) rowptr[len] = s_carry;
}

__global__ void fill_lists_kernel(const int* __restrict__ V, const int* __restrict__ E,
                                  int* __restrict__ e_cursor, int* __restrict__ v_cursor,
                                  int* __restrict__ eV, int* __restrict__ vE, int nnz)
{
    int i = blockIdx.x * blockDim.x + threadIdx.x;
    if (i >= nnz) return;
    int v = V[i], e = E[i];
    int pe = atomicAdd(&e_cursor[e], 1);
    eV[pe] = v;
    int pv = atomicAdd(&v_cursor[v], 1);
    vE[pv] = e;
}

// ---------------------------------------------------------------------------
// bf16x3 tensor-core GEMM with cp.async double buffering.
// C[M,N] = [A1 | A2] @ B + bias, fp32 out.
// A hi/lo row-major [M,K1]/[M,K2]; B hi/lo [K,N] row-major.
// BM=128, BN=128, BK=32; 256 threads (8 warps, 4x2), warp tile 32x64.
// Requires N % 128 == 0, K1 % 32 == 0, K2 % 32 == 0.
// ---------------------------------------------------------------------------
struct GemmStage {
    __nv_bfloat16 Ah[128][40];
    __nv_bfloat16 Al[128][40];
    __nv_bfloat16 Bh[32][136];
    __nv_bfloat16 Bl[32][136];
};
static constexpr int GEMM_SMEM = 2 * sizeof(GemmStage);   // 75776

__global__ __launch_bounds__(256)
void gemm_bf16x3(const __nv_bfloat16* __restrict__ A1h, const __nv_bfloat16* __restrict__ A1l, int K1,
                 const __nv_bfloat16* __restrict__ A2h, const __nv_bfloat16* __restrict__ A2l, int K2,
                 const __nv_bfloat16* __restrict__ Bhg, const __nv_bfloat16* __restrict__ Blg,
                 const float* __restrict__ bias, float* __restrict__ C,
                 int M, int N)
{
    extern __shared__ char smem_raw[];
    GemmStage* st = reinterpret_cast<GemmStage*>(smem_raw);

    const int tid  = threadIdx.x;
    const int wid  = tid >> 5, lane = tid & 31;
    const int wm   = wid >> 1, wn = wid & 1;
    const int row0 = blockIdx.y * 128;
    const int col0 = blockIdx.x * 128;
    const int K = K1 + K2, nch = K >> 5;

    wmma::fragment<wmma::accumulator, 16, 16, 16, float> acc[2][4];
#pragma unroll
    for (int mt = 0; mt < 2; mt++)
#pragma unroll
        for (int nt = 0; nt < 4; nt++) wmma::fill_fragment(acc[mt][nt], 0.f);

    auto prefetch = [&](int c, int s) {
        const int k0 = c * 32;
        const __nv_bfloat16 *ah, *al; int lda, col;
        if (k0 < K1) { ah = A1h; al = A1l; lda = K1; col = k0; }
        else         { ah = A2h; al = A2l; lda = K2; col = k0 - K1; }
        // A: 128 rows x 32 cols bf16 -> 512 x 16B (hi + lo)
#pragma unroll
        for (int t = 0; t < 2; t++) {
            int u = tid + t * 256, r = u >> 2, q = u & 3;
            int gr = row0 + r;
            int sz = (gr < M) ? 16 : 0;
            size_t off = (size_t)(gr < M ? gr : 0) * lda + col + q * 8;
            cp_async16(smem_to_u32(&st[s].Ah[r][q * 8]), ah + off, sz);
            cp_async16(smem_to_u32(&st[s].Al[r][q * 8]), al + off, sz);
        }
        // B: 32 rows x 128 cols
#pragma unroll
        for (int t = 0; t < 2; t++) {
            int u = tid + t * 256, r = u >> 4, q = u & 15;
            size_t off = (size_t)(k0 + r) * N + col0 + q * 8;
            cp_async16(smem_to_u32(&st[s].Bh[r][q * 8]), Bhg + off, 16);
            cp_async16(smem_to_u32(&st[s].Bl[r][q * 8]), Blg + off, 16);
        }
    };

    prefetch(0, 0);
    CP_COMMIT();

    for (int c = 0; c < nch; c++) {
        const int s = c & 1;
        if (c + 1 < nch) {
            prefetch(c + 1, s ^ 1);
            CP_COMMIT();
            CP_WAIT(1);
        } else {
            CP_WAIT(0);
        }
        __syncthreads();

#pragma unroll
        for (int ks = 0; ks < 2; ks++) {
            wmma::fragment<wmma::matrix_a, 16, 16, 16, __nv_bfloat16, wmma::row_major> ah2[2], al2[2];
#pragma unroll
            for (int mt = 0; mt < 2; mt++) {
                wmma::load_matrix_sync(ah2[mt], &st[s].Ah[wm * 32 + mt * 16][ks * 16], 40);
                wmma::load_matrix_sync(al2[mt], &st[s].Al[wm * 32 + mt * 16][ks * 16], 40);
            }
#pragma unroll
            for (int nt = 0; nt < 4; nt++) {
                wmma::fragment<wmma::matrix_b, 16, 16, 16, __nv_bfloat16, wmma::row_major> bh, bl;
                wmma::load_matrix_sync(bh, &st[s].Bh[ks * 16][wn * 64 + nt * 16], 136);
                wmma::load_matrix_sync(bl, &st[s].Bl[ks * 16][wn * 64 + nt * 16], 136);
#pragma unroll
                for (int mt = 0; mt < 2; mt++) {
                    wmma::mma_sync(acc[mt][nt], ah2[mt], bh, acc[mt][nt]);
                    wmma::mma_sync(acc[mt][nt], al2[mt], bh, acc[mt][nt]);
                    wmma::mma_sync(acc[mt][nt], ah2[mt], bl, acc[mt][nt]);
                }
            }
        }
        __syncthreads();
    }

    // epilogue: stage each 16x16 tile in smem (reuse pipeline smem), add bias
    float* stg = reinterpret_cast<float*>(smem_raw) + wid * 320;
#pragma unroll
    for (int mt = 0; mt < 2; mt++) {
#pragma unroll
        for (int nt = 0; nt < 4; nt++) {
            wmma::store_matrix_sync(stg, acc[mt][nt], 20, wmma::mem_row_major);
            __syncwarp();
            int r = lane >> 1, cofs = (lane & 1) * 8;
            int gr = row0 + wm * 32 + mt * 16 + r;
            int gc = col0 + wn * 64 + nt * 16 + cofs;
            if (gr < M) {
                float4 o0, o1;
                o0.x = stg[r * 20 + cofs + 0] + bias[gc + 0];
                o0.y = stg[r * 20 + cofs + 1] + bias[gc + 1];
                o0.z = stg[r * 20 + cofs + 2] + bias[gc + 2];
                o0.w = stg[r * 20 + cofs + 3] + bias[gc + 3];
                o1.x = stg[r * 20 + cofs + 4] + bias[gc + 4];
                o1.y = stg[r * 20 + cofs + 5] + bias[gc + 5];
                o1.z = stg[r * 20 + cofs + 6] + bias[gc + 6];
                o1.w = stg[r * 20 + cofs + 7] + bias[gc + 7];
                *reinterpret_cast<float4*>(C + (size_t)gr * N + gc)     = o0;
                *reinterpret_cast<float4*>(C + (size_t)gr * N + gc + 4) = o1;
            }
            __syncwarp();
        }
    }
}

// ---------------------------------------------------------------------------
// score[n] = dot(Xfeat[n,:], a)
// ---------------------------------------------------------------------------
__global__ void score_kernel(const float* __restrict__ Xfeat, const float* __restrict__ a,
                             float* __restrict__ score, int N, int H)
{
    int warp = (blockIdx.x * blockDim.x + threadIdx.x) >> 5;
    int lane = threadIdx.x & 31;
    if (warp >= N) return;
    const float4* row = reinterpret_cast<const float4*>(Xfeat + (size_t)warp * H);
    const float4* av  = reinterpret_cast<const float4*>(a);
    float s = 0.f;
    for (int c4 = lane; c4 < H / 4; c4 += 32) {
        float4 x = row[c4];
        float4 w = av[c4];
        s += x.x * w.x + x.y * w.y + x.z * w.z + x.w * w.w;
    }
#pragma unroll
    for (int o = 16; o > 0; o >>= 1) s += __shfl_xor_sync(0xffffffffu, s, o);
    if (lane == 0) score[warp] = s;
}

// ---------------------------------------------------------------------------
// Fused v2e: segment softmax + weighted gather + elu -> bf16 hi/lo
// ---------------------------------------------------------------------------
template <int CH4>
__global__ __launch_bounds__(256)
void v2e_softmax_kernel(const float* __restrict__ Xfeat, const float* __restrict__ score,
                        const int* __restrict__ e_rowptr, const int* __restrict__ eV,
                        __nv_bfloat16* __restrict__ Yeh, __nv_bfloat16* __restrict__ Yel,
                        int M, int H)
{
    int warp = (blockIdx.x * blockDim.x + threadIdx.x) >> 5;
    int lane = threadIdx.x & 31;
    if (warp >= M) return;
    const int beg = e_rowptr[warp];
    const int end = e_rowptr[warp + 1];

    float m = -1e30f;
    for (int j = beg + lane; j < end; j += 32)
        m = fmaxf(m, leakyf(__ldg(&score[eV[j]])));
#pragma unroll
    for (int o = 16; o > 0; o >>= 1) m = fmaxf(m, __shfl_xor_sync(0xffffffffu, m, o));

    float den = 0.f;
    for (int j = beg + lane; j < end; j += 32)
        den += expf(leakyf(__ldg(&score[eV[j]])) - m);
#pragma unroll
    for (int o = 16; o > 0; o >>= 1) den += __shfl_xor_sync(0xffffffffu, den, o);
    float invden = (end > beg) ? 1.f / den : 0.f;

    float4 acc[CH4];
#pragma unroll
    for (int c = 0; c < CH4; c++) acc[c] = make_float4(0.f, 0.f, 0.f, 0.f);

    for (int j = beg; j < end; j++) {
        int v = eV[j];
        float w = expf(leakyf(__ldg(&score[v])) - m) * invden;
        const float4* row = reinterpret_cast<const float4*>(Xfeat + (size_t)v * H);
#pragma unroll
        for (int c = 0; c < CH4; c++) {
            float4 x = __ldg(&row[lane + 32 * c]);
            acc[c].x = fmaf(x.x, w, acc[c].x);
            acc[c].y = fmaf(x.y, w, acc[c].y);
            acc[c].z = fmaf(x.z, w, acc[c].z);
            acc[c].w = fmaf(x.w, w, acc[c].w);
        }
    }

#pragma unroll
    for (int c = 0; c < CH4; c++) {
        float4 o;
        o.x = eluf(acc[c].x); o.y = eluf(acc[c].y);
        o.z = eluf(acc[c].z); o.w = eluf(acc[c].w);
        size_t off = (size_t)warp * H + (lane + 32 * c) * 4;
        split_store4(o, Yeh + off, Yel + off);
    }
}

// ---------------------------------------------------------------------------
// Fused e2v: mean + elu + residual -> bf16 hi/lo
// ---------------------------------------------------------------------------
template <int CH4>
__global__ __launch_bounds__(256)
void e2v_mean_kernel(const float* __restrict__ Ye2,
                     const int* __restrict__ v_rowptr, const int* __restrict__ vE,
                     const float* __restrict__ Xinit,
                     __nv_bfloat16* __restrict__ hh, __nv_bfloat16* __restrict__ hl,
                     int N, int H)
{
    int warp = (blockIdx.x * blockDim.x + threadIdx.x) >> 5;
    int lane = threadIdx.x & 31;
    if (warp >= N) return;
    const int beg = v_rowptr[warp];
    const int end = v_rowptr[warp + 1];

    float4 acc[CH4];
#pragma unroll
    for (int c = 0; c < CH4; c++) acc[c] = make_float4(0.f, 0.f, 0.f, 0.f);

    for (int j = beg; j < end; j++) {
        int e = vE[j];
        const float4* row = reinterpret_cast<const float4*>(Ye2 + (size_t)e * H);
#pragma unroll
        for (int c = 0; c < CH4; c++) {
            float4 x = __ldg(&row[lane + 32 * c]);
            acc[c].x += x.x; acc[c].y += x.y; acc[c].z += x.z; acc[c].w += x.w;
        }
    }
    float inv = (end > beg) ? 1.f / (float)(end - beg) : 0.f;

    const float4* xi = reinterpret_cast<const float4*>(Xinit + (size_t)warp * H);
#pragma unroll
    for (int c = 0; c < CH4; c++) {
        float4 r = __ldg(&xi[lane + 32 * c]);
        float4 o;
        o.x = eluf(acc[c].x * inv) + r.x;
        o.y = eluf(acc[c].y * inv) + r.y;
        o.z = eluf(acc[c].z * inv) + r.z;
        o.w = eluf(acc[c].w * inv) + r.w;
        size_t off = (size_t)warp * H + (lane + 32 * c) * 4;
        split_store4(o, hh + off, hl + off);
    }
}

// ---------------------------------------------------------------------------
// Hyperconv edge + node (fp32)
// ---------------------------------------------------------------------------
template <int CH4>
__global__ __launch_bounds__(256)
void hyper_edge_kernel(const float* __restrict__ Xn,
                       const int* __restrict__ e_rowptr, const int* __restrict__ eV,
                       const int* __restrict__ v_rowptr,
                       float* __restrict__ Ye, int M, int O)
{
    int warp = (blockIdx.x * blockDim.x + threadIdx.x) >> 5;
    int lane = threadIdx.x & 31;
    if (warp >= M) return;
    const int beg = e_rowptr[warp];
    const int end = e_rowptr[warp + 1];
    const int cnt = end - beg;

    float sumDv = 0.f;
    for (int j = beg + lane; j < end; j += 32) {
        int v = eV[j];
        sumDv += (float)(__ldg(&v_rowptr[v + 1]) - __ldg(&v_rowptr[v]));
    }
#pragma unroll
    for (int o = 16; o > 0; o >>= 1) sumDv += __shfl_xor_sync(0xffffffffu, sumDv, o);

    float4 acc[CH4];
#pragma unroll
    for (int c = 0; c < CH4; c++) acc[c] = make_float4(0.f, 0.f, 0.f, 0.f);

    for (int j = beg; j < end; j++) {
        int v = eV[j];
        const float4* row = reinterpret_cast<const float4*>(Xn + (size_t)v * O);
#pragma unroll
        for (int c = 0; c < CH4; c++) {
            float4 x = __ldg(&row[lane + 32 * c]);
            acc[c].x += x.x; acc[c].y += x.y; acc[c].z += x.z; acc[c].w += x.w;
        }
    }

    float invc = (cnt > 0) ? 1.f / (float)cnt : 0.f;
    float De = sumDv / ((float)cnt + 1.f);
    float dinv = (De > 0.f) ? rsqrtf(De) : 1.f;
    float s = invc * dinv;

    float4* drow = reinterpret_cast<float4*>(Ye + (size_t)warp * O);
#pragma unroll
    for (int c = 0; c < CH4; c++) {
        float4 o;
        o.x = acc[c].x * s; o.y = acc[c].y * s;
        o.z = acc[c].z * s; o.w = acc[c].w * s;
        drow[lane + 32 * c] = o;
    }
}

template <int CH4>
__global__ __launch_bounds__(256)
void hyper_node_kernel(const float* __restrict__ Ye,
                       const int* __restrict__ v_rowptr, const int* __restrict__ vE,
                       float* __restrict__ out, int N, int O)
{
    int warp = (blockIdx.x * blockDim.x + threadIdx.x) >> 5;
    int lane = threadIdx.x & 31;
    if (warp >= N) return;
    const int beg = v_rowptr[warp];
    const int end = v_rowptr[warp + 1];
    const int deg = end - beg;

    float4 acc[CH4];
#pragma unroll
    for (int c = 0; c < CH4; c++) acc[c] = make_float4(0.f, 0.f, 0.f, 0.f);

    for (int j = beg; j < end; j++) {
        int e = vE[j];
        const float4* row = reinterpret_cast<const float4*>(Ye + (size_t)e * O);
#pragma unroll
        for (int c = 0; c < CH4; c++) {
            float4 x = __ldg(&row[lane + 32 * c]);
            acc[c].x += x.x; acc[c].y += x.y; acc[c].z += x.z; acc[c].w += x.w;
        }
    }
    float dinv = (deg > 0) ? rsqrtf((float)deg) : 0.f;

    float4* drow = reinterpret_cast<float4*>(out + (size_t)warp * O);
#pragma unroll
    for (int c = 0; c < CH4; c++) {
        float4 o;
        o.x = acc[c].x * dinv; o.y = acc[c].y * dinv;
        o.z = acc[c].z * dinv; o.w = acc[c].w * dinv;
        drow[lane + 32 * c] = o;
    }
}

// ---------------------------------------------------------------------------
// Host
// ---------------------------------------------------------------------------
static inline int ceil_div(int a, int b) { return (a + b - 1) / b; }

extern "C" void kernel_launch(void* const* d_in, const int* in_sizes, int n_in,
                              void* d_out, int out_size)
{
    const float* X   = (const float*)d_in[0];
    const int*   V   = (const int*)  d_in[1];
    const int*   E   = (const int*)  d_in[2];
    const float* S   = (const float*)d_in[3];
    const float* Wx0 = (const float*)d_in[4];
    const float* bx0 = (const float*)d_in[5];
    const float* Wv0 = (const float*)d_in[6];
    const float* bv0 = (const float*)d_in[7];
    const float* a0  = (const float*)d_in[8];
    const float* Wt0 = (const float*)d_in[9];
    const float* bt0 = (const float*)d_in[10];
    const float* Wx1 = (const float*)d_in[11];
    const float* bx1 = (const float*)d_in[12];
    const float* Wv1 = (const float*)d_in[13];
    const float* bv1 = (const float*)d_in[14];
    const float* a1  = (const float*)d_in[15];
    const float* Wt1 = (const float*)d_in[16];
    const float* bt1 = (const float*)d_in[17];
    const float* Wf  = (const float*)d_in[18];
    const float* bf  = (const float*)d_in[19];

    const int H    = in_sizes[5];              // 256
    const int IN   = in_sizes[4] / H;          // 128
    const int N    = in_sizes[0] / IN;         // 50000
    const int NNZ  = in_sizes[1];              // 400000
    const int HS   = in_sizes[9] / H;          // 320
    const int STAR = HS - H;                   // 64
    const int M    = in_sizes[3] / STAR;       // 20000
    const int OUT  = in_sizes[19];             // 128

    void* p;
    cudaGetSymbolAddress(&p, g_Xinit);    float* Xinit = (float*)p;
    cudaGetSymbolAddress(&p, g_Xfeat);    float* Xfeat = (float*)p;
    cudaGetSymbolAddress(&p, g_Ye2);      float* Ye2   = (float*)p;
    cudaGetSymbolAddress(&p, g_score);    float* score = (float*)p;
    cudaGetSymbolAddress(&p, g_Ah);  __nv_bfloat16* Ah  = (__nv_bfloat16*)p;
    cudaGetSymbolAddress(&p, g_Al);  __nv_bfloat16* Al  = (__nv_bfloat16*)p;
    cudaGetSymbolAddress(&p, g_Bh);  __nv_bfloat16* Bhh = (__nv_bfloat16*)p;
    cudaGetSymbolAddress(&p, g_Bl);  __nv_bfloat16* Bll = (__nv_bfloat16*)p;
    cudaGetSymbolAddress(&p, g_Yeh); __nv_bfloat16* Yeh = (__nv_bfloat16*)p;
    cudaGetSymbolAddress(&p, g_Yel); __nv_bfloat16* Yel = (__nv_bfloat16*)p;
    cudaGetSymbolAddress(&p, g_Sh);  __nv_bfloat16* Sh  = (__nv_bfloat16*)p;
    cudaGetSymbolAddress(&p, g_Sl);  __nv_bfloat16* Sl  = (__nv_bfloat16*)p;
    cudaGetSymbolAddress(&p, g_Wh);  __nv_bfloat16* Wh  = (__nv_bfloat16*)p;
    cudaGetSymbolAddress(&p, g_Wl);  __nv_bfloat16* Wl  = (__nv_bfloat16*)p;
    cudaGetSymbolAddress(&p, g_e_rowptr); int* e_rowptr = (int*)p;
    cudaGetSymbolAddress(&p, g_v_rowptr); int* v_rowptr = (int*)p;
    cudaGetSymbolAddress(&p, g_e_cursor); int* e_cursor = (int*)p;
    cudaGetSymbolAddress(&p, g_v_cursor); int* v_cursor = (int*)p;
    cudaGetSymbolAddress(&p, g_cntE);     int* cntE     = (int*)p;
    cudaGetSymbolAddress(&p, g_cntV);     int* cntV     = (int*)p;
    cudaGetSymbolAddress(&p, g_eV);       int* eV       = (int*)p;
    cudaGetSymbolAddress(&p, g_vE);       int* vE       = (int*)p;

    static bool attr_set = false;
    if (!attr_set) {
        cudaFuncSetAttribute(gemm_bf16x3, cudaFuncAttributeMaxDynamicSharedMemorySize, GEMM_SMEM);
        attr_set = true;
    }

    // weight offsets ([K,N] row-major, packed)
    const size_t o_wx0 = 0;
    const size_t o_wv0 = o_wx0 + (size_t)IN * H;
    const size_t o_wt0 = o_wv0 + (size_t)IN * H;
    const size_t o_wx1 = o_wt0 + (size_t)HS * H;
    const size_t o_wv1 = o_wx1 + (size_t)H * H;
    const size_t o_wt1 = o_wv1 + (size_t)H * H;
    const size_t o_wf  = o_wt1 + (size_t)HS * H;

    auto split = [&](const float* src, __nv_bfloat16* dh, __nv_bfloat16* dl, long nelem) {
        long n4 = nelem / 4;
        int blocks = (int)((n4 + 255) / 256); if (blocks > 2048) blocks = 2048;
        split_kernel<<<blocks, 256>>>(src, dh, dl, n4);
    };

    // ---- splits ----
    split(X,   Ah, Al, (long)N * IN);
    split(S,   Sh, Sl, (long)M * STAR);
    split(Wx0, Wh + o_wx0, Wl + o_wx0, (long)IN * H);
    split(Wv0, Wh + o_wv0, Wl + o_wv0, (long)IN * H);
    split(Wt0, Wh + o_wt0, Wl + o_wt0, (long)HS * H);
    split(Wx1, Wh + o_wx1, Wl + o_wx1, (long)H * H);
    split(Wv1, Wh + o_wv1, Wl + o_wv1, (long)H * H);
    split(Wt1, Wh + o_wt1, Wl + o_wt1, (long)HS * H);
    split(Wf,  Wh + o_wf,  Wl + o_wf,  (long)H * OUT);

    // ---- CSR build ----
    const int nnzBlocks = ceil_div(NNZ, 256);
    fill_int<<<ceil_div(M, 256), 256>>>(cntE, 0, M);
    fill_int<<<ceil_div(N, 256), 256>>>(cntV, 0, N);
    count_kernel<<<nnzBlocks, 256>>>(V, E, cntV, cntE, NNZ);
    scan_kernel<<<1, 1024>>>(cntE, e_rowptr, e_cursor, M);
    scan_kernel<<<1, 1024>>>(cntV, v_rowptr, v_cursor, N);
    fill_lists_kernel<<<nnzBlocks, 256>>>(V, E, e_cursor, v_cursor, eV, vE, NNZ);

    const int edgeWarpBlocks = ceil_div(M, 8);
    const int nodeWarpBlocks = ceil_div(N, 8);

    auto gemm = [&](const __nv_bfloat16* a1h, const __nv_bfloat16* a1l, int K1,
                    const __nv_bfloat16* a2h, const __nv_bfloat16* a2l, int K2,
                    size_t woff, const float* bias, float* C, int Mrows, int Ncols) {
        dim3 grid(Ncols / 128, ceil_div(Mrows, 128));
        gemm_bf16x3<<<grid, 256, GEMM_SMEM>>>(a1h, a1l, K1, a2h, a2l, K2,
                                              Wh + woff, Wl + woff, bias, C, Mrows, Ncols);
    };

    // ---- layer 0 ----
    gemm(Ah, Al, IN, nullptr, nullptr, 0, o_wx0, bx0, Xinit, N, H);
    gemm(Ah, Al, IN, nullptr, nullptr, 0, o_wv0, bv0, Xfeat, N, H);
    score_kernel<<<ceil_div(N, 8), 256>>>(Xfeat, a0, score, N, H);
    v2e_softmax_kernel<2><<<edgeWarpBlocks, 256>>>(Xfeat, score, e_rowptr, eV, Yeh, Yel, M, H);
    gemm(Yeh, Yel, H, Sh, Sl, STAR, o_wt0, bt0, Ye2, M, H);
    e2v_mean_kernel<2><<<nodeWarpBlocks, 256>>>(Ye2, v_rowptr, vE, Xinit, Bhh, Bll, N, H);

    // ---- layer 1 ----
    gemm(Bhh, Bll, H, nullptr, nullptr, 0, o_wx1, bx1, Xinit, N, H);
    gemm(Bhh, Bll, H, nullptr, nullptr, 0, o_wv1, bv1, Xfeat, N, H);
    score_kernel<<<ceil_div(N, 8), 256>>>(Xfeat, a1, score, N, H);
    v2e_softmax_kernel<2><<<edgeWarpBlocks, 256>>>(Xfeat, score, e_rowptr, eV, Yeh, Yel, M, H);
    gemm(Yeh, Yel, H, Sh, Sl, STAR, o_wt1, bt1, Ye2, M, H);
    e2v_mean_kernel<2><<<nodeWarpBlocks, 256>>>(Ye2, v_rowptr, vE, Xinit, Ah, Al, N, H);

    // ---- hyperconv ----
    gemm(Ah, Al, H, nullptr, nullptr, 0, o_wf, bf, Xfeat, N, OUT);
    hyper_edge_kernel<1><<<edgeWarpBlocks, 256>>>(Xfeat, e_rowptr, eV, v_rowptr, Ye2, M, OUT);
    hyper_node_kernel<1><<<nodeWarpBlocks, 256>>>(Ye2, v_rowptr, vE, (float*)d_out, N, OUT);
}

// round 6
// speedup vs baseline: 3.0900x; 1.0796x over previous
#include <cuda_runtime.h>
#include <cuda_bf16.h>
#include <mma.h>
#include <math.h>
#include <stdint.h>

using namespace nvcuda;

// ---------------------------------------------------------------------------
// Problem max sizes
// ---------------------------------------------------------------------------
#define NMAX   50000
#define MMAX   20000
#define NNZMAX 400000
#define HMAX   256
#define WTOTAL 393216

// ---------------------------------------------------------------------------
// Scratch (device globals)
// ---------------------------------------------------------------------------
__device__ float g_Xinit[NMAX * HMAX];
__device__ float g_Xfeat[NMAX * HMAX];
__device__ float g_Ye2  [MMAX * HMAX];
__device__ float g_score[NMAX];

__device__ __nv_bfloat16 g_Ah [NMAX * HMAX];
__device__ __nv_bfloat16 g_Al [NMAX * HMAX];
__device__ __nv_bfloat16 g_Bh [NMAX * HMAX];
__device__ __nv_bfloat16 g_Bl [NMAX * HMAX];
__device__ __nv_bfloat16 g_Yeh[MMAX * HMAX];
__device__ __nv_bfloat16 g_Yel[MMAX * HMAX];
__device__ __nv_bfloat16 g_Sh [MMAX * 64];
__device__ __nv_bfloat16 g_Sl [MMAX * 64];
__device__ __nv_bfloat16 g_Wh [WTOTAL];   // [K,N] row-major, packed
__device__ __nv_bfloat16 g_Wl [WTOTAL];

// CSR structures
__device__ int g_e_rowptr[MMAX + 1];
__device__ int g_v_rowptr[NMAX + 1];
__device__ int g_e_cursor[MMAX];
__device__ int g_v_cursor[NMAX];
__device__ int g_cntE[MMAX];
__device__ int g_cntV[NMAX];
__device__ int g_eV[NNZMAX];
__device__ int g_vE[NNZMAX];

// ---------------------------------------------------------------------------
// Helpers
// ---------------------------------------------------------------------------
__device__ __forceinline__ float eluf(float x)  { return x > 0.f ? x : expm1f(x); }
__device__ __forceinline__ float leakyf(float x){ return x > 0.f ? x : 0.2f * x; }

__device__ __forceinline__ uint32_t smem_to_u32(const void* p) {
    uint32_t a;
    asm("{ .reg .u64 t; cvta.to.shared.u64 t, %1; cvt.u32.u64 %0, t; }" : "=r"(a) : "l"(p));
    return a;
}
__device__ __forceinline__ void cp_async16(uint32_t dst, const void* src, int sz) {
    asm volatile("cp.async.cg.shared.global [%0], [%1], 16, %2;"
                 :: "r"(dst), "l"(src), "r"(sz) : "memory");
}
#define CP_COMMIT() asm volatile("cp.async.commit_group;" ::: "memory")
#define CP_WAIT(n)  asm volatile("cp.async.wait_group %0;" :: "n"(n) : "memory")

__device__ __forceinline__ void split_store4(float4 v, __nv_bfloat16* ph, __nv_bfloat16* pl) {
    __nv_bfloat162 h0, h1, l0, l1;
    h0.x = __float2bfloat16_rn(v.x); h0.y = __float2bfloat16_rn(v.y);
    h1.x = __float2bfloat16_rn(v.z); h1.y = __float2bfloat16_rn(v.w);
    l0.x = __float2bfloat16_rn(v.x - __bfloat162float(h0.x));
    l0.y = __float2bfloat16_rn(v.y - __bfloat162float(h0.y));
    l1.x = __float2bfloat16_rn(v.z - __bfloat162float(h1.x));
    l1.y = __float2bfloat16_rn(v.w - __bfloat162float(h1.y));
    uint2 uh, ul;
    uh.x = *reinterpret_cast<unsigned*>(&h0); uh.y = *reinterpret_cast<unsigned*>(&h1);
    ul.x = *reinterpret_cast<unsigned*>(&l0); ul.y = *reinterpret_cast<unsigned*>(&l1);
    *reinterpret_cast<uint2*>(ph) = uh;
    *reinterpret_cast<uint2*>(pl) = ul;
}

__global__ void split_kernel(const float* __restrict__ x, __nv_bfloat16* __restrict__ hi,
                             __nv_bfloat16* __restrict__ lo, long n4)
{
    long i = (long)blockIdx.x * blockDim.x + threadIdx.x;
    long stride = (long)gridDim.x * blockDim.x;
    for (; i < n4; i += stride) {
        float4 v = reinterpret_cast<const float4*>(x)[i];
        split_store4(v, hi + 4 * i, lo + 4 * i);
    }
}

__global__ void fill_int(int* __restrict__ p, int v, int n) {
    int i = blockIdx.x * blockDim.x + threadIdx.x;
    int stride = gridDim.x * blockDim.x;
    for (; i < n; i += stride) p[i] = v;
}

// ---------------------------------------------------------------------------
// CSR construction
// ---------------------------------------------------------------------------
__global__ void count_kernel(const int* __restrict__ V, const int* __restrict__ E,
                             int* __restrict__ cntV, int* __restrict__ cntE, int nnz)
{
    int i = blockIdx.x * blockDim.x + threadIdx.x;
    if (i >= nnz) return;
    atomicAdd(&cntE[E[i]], 1);
    atomicAdd(&cntV[V[i]], 1);
}

__global__ __launch_bounds__(1024)
void scan_kernel(const int* __restrict__ cnt, int* __restrict__ rowptr,
                 int* __restrict__ cursor, int len)
{
    __shared__ int wsum[32];
    __shared__ int s_carry;
    const int tid = threadIdx.x, lane = tid & 31, wid = tid >> 5;
    if (tid == 0) s_carry = 0;
    __syncthreads();

    for (int base = 0; base < len; base += 4096) {
        int i0 = base + tid * 4;
        int v0 = (i0 + 0 < len) ? cnt[i0 + 0] : 0;
        int v1 = (i0 + 1 < len) ? cnt[i0 + 1] : 0;
        int v2 = (i0 + 2 < len) ? cnt[i0 + 2] : 0;
        int v3 = (i0 + 3 < len) ? cnt[i0 + 3] : 0;
        int t1 = v0 + v1, t2 = t1 + v2, t3 = t2 + v3;

        int inc = t3;
#pragma unroll
        for (int o = 1; o < 32; o <<= 1) {
            int u = __shfl_up_sync(0xffffffffu, inc, o);
            if (lane >= o) inc += u;
        }
        if (lane == 31) wsum[wid] = inc;
        __syncthreads();
        if (wid == 0) {
            int w = wsum[lane];
            int wi = w;
#pragma unroll
            for (int o = 1; o < 32; o <<= 1) {
                int u = __shfl_up_sync(0xffffffffu, wi, o);
                if (lane >= o) wi += u;
            }
            wsum[lane] = wi - w;
        }
        __syncthreads();
        int excl = s_carry + wsum[wid] + (inc - t3);
        if (i0 + 0 < len) { rowptr[i0 + 0] = excl;      cursor[i0 + 0] = excl; }
        if (i0 + 1 < len) { rowptr[i0 + 1] = excl + v0; cursor[i0 + 1] = excl + v0; }
        if (i0 + 2 < len) { rowptr[i0 + 2] = excl + t1; cursor[i0 + 2] = excl + t1; }
        if (i0 + 3 < len) { rowptr[i0 + 3] = excl + t2; cursor[i0 + 3] = excl + t2; }
        __syncthreads();
        if (tid == 1023) s_carry = s_carry + wsum[31] + inc;
        __syncthreads();
    }
    if (threadIdx.x == 0) rowptr[len] = s_carry;
}

__global__ void fill_lists_kernel(const int* __restrict__ V, const int* __restrict__ E,
                                  int* __restrict__ e_cursor, int* __restrict__ v_cursor,
                                  int* __restrict__ eV, int* __restrict__ vE, int nnz)
{
    int i = blockIdx.x * blockDim.x + threadIdx.x;
    if (i >= nnz) return;
    int v = V[i], e = E[i];
    int pe = atomicAdd(&e_cursor[e], 1);
    eV[pe] = v;
    int pv = atomicAdd(&v_cursor[v], 1);
    vE[pv] = e;
}

// ---------------------------------------------------------------------------
// bf16x3 tensor-core GEMM with cp.async double buffering.
// C[M,N] = [A1 | A2] @ B + bias, fp32 out.
// ---------------------------------------------------------------------------
struct GemmStage {
    __nv_bfloat16 Ah[128][40];
    __nv_bfloat16 Al[128][40];
    __nv_bfloat16 Bh[32][136];
    __nv_bfloat16 Bl[32][136];
};
static constexpr int GEMM_SMEM = 2 * sizeof(GemmStage);   // 75776

__global__ __launch_bounds__(256)
void gemm_bf16x3(const __nv_bfloat16* __restrict__ A1h, const __nv_bfloat16* __restrict__ A1l, int K1,
                 const __nv_bfloat16* __restrict__ A2h, const __nv_bfloat16* __restrict__ A2l, int K2,
                 const __nv_bfloat16* __restrict__ Bhg, const __nv_bfloat16* __restrict__ Blg,
                 const float* __restrict__ bias, float* __restrict__ C,
                 int M, int N)
{
    extern __shared__ char smem_raw[];
    GemmStage* st = reinterpret_cast<GemmStage*>(smem_raw);

    const int tid  = threadIdx.x;
    const int wid  = tid >> 5, lane = tid & 31;
    const int wm   = wid >> 1, wn = wid & 1;
    const int row0 = blockIdx.y * 128;
    const int col0 = blockIdx.x * 128;
    const int K = K1 + K2, nch = K >> 5;

    wmma::fragment<wmma::accumulator, 16, 16, 16, float> acc[2][4];
#pragma unroll
    for (int mt = 0; mt < 2; mt++)
#pragma unroll
        for (int nt = 0; nt < 4; nt++) wmma::fill_fragment(acc[mt][nt], 0.f);

    auto prefetch = [&](int c, int s) {
        const int k0 = c * 32;
        const __nv_bfloat16 *ah, *al; int lda, col;
        if (k0 < K1) { ah = A1h; al = A1l; lda = K1; col = k0; }
        else         { ah = A2h; al = A2l; lda = K2; col = k0 - K1; }
#pragma unroll
        for (int t = 0; t < 2; t++) {
            int u = tid + t * 256, r = u >> 2, q = u & 3;
            int gr = row0 + r;
            int sz = (gr < M) ? 16 : 0;
            size_t off = (size_t)(gr < M ? gr : 0) * lda + col + q * 8;
            cp_async16(smem_to_u32(&st[s].Ah[r][q * 8]), ah + off, sz);
            cp_async16(smem_to_u32(&st[s].Al[r][q * 8]), al + off, sz);
        }
#pragma unroll
        for (int t = 0; t < 2; t++) {
            int u = tid + t * 256, r = u >> 4, q = u & 15;
            size_t off = (size_t)(k0 + r) * N + col0 + q * 8;
            cp_async16(smem_to_u32(&st[s].Bh[r][q * 8]), Bhg + off, 16);
            cp_async16(smem_to_u32(&st[s].Bl[r][q * 8]), Blg + off, 16);
        }
    };

    prefetch(0, 0);
    CP_COMMIT();

    for (int c = 0; c < nch; c++) {
        const int s = c & 1;
        if (c + 1 < nch) {
            prefetch(c + 1, s ^ 1);
            CP_COMMIT();
            CP_WAIT(1);
        } else {
            CP_WAIT(0);
        }
        __syncthreads();

#pragma unroll
        for (int ks = 0; ks < 2; ks++) {
            wmma::fragment<wmma::matrix_a, 16, 16, 16, __nv_bfloat16, wmma::row_major> ah2[2], al2[2];
#pragma unroll
            for (int mt = 0; mt < 2; mt++) {
                wmma::load_matrix_sync(ah2[mt], &st[s].Ah[wm * 32 + mt * 16][ks * 16], 40);
                wmma::load_matrix_sync(al2[mt], &st[s].Al[wm * 32 + mt * 16][ks * 16], 40);
            }
#pragma unroll
            for (int nt = 0; nt < 4; nt++) {
                wmma::fragment<wmma::matrix_b, 16, 16, 16, __nv_bfloat16, wmma::row_major> bh, bl;
                wmma::load_matrix_sync(bh, &st[s].Bh[ks * 16][wn * 64 + nt * 16], 136);
                wmma::load_matrix_sync(bl, &st[s].Bl[ks * 16][wn * 64 + nt * 16], 136);
#pragma unroll
                for (int mt = 0; mt < 2; mt++) {
                    wmma::mma_sync(acc[mt][nt], ah2[mt], bh, acc[mt][nt]);
                    wmma::mma_sync(acc[mt][nt], al2[mt], bh, acc[mt][nt]);
                    wmma::mma_sync(acc[mt][nt], ah2[mt], bl, acc[mt][nt]);
                }
            }
        }
        __syncthreads();
    }

    // epilogue
    float* stg = reinterpret_cast<float*>(smem_raw) + wid * 320;
#pragma unroll
    for (int mt = 0; mt < 2; mt++) {
#pragma unroll
        for (int nt = 0; nt < 4; nt++) {
            wmma::store_matrix_sync(stg, acc[mt][nt], 20, wmma::mem_row_major);
            __syncwarp();
            int r = lane >> 1, cofs = (lane & 1) * 8;
            int gr = row0 + wm * 32 + mt * 16 + r;
            int gc = col0 + wn * 64 + nt * 16 + cofs;
            if (gr < M) {
                float4 o0, o1;
                o0.x = stg[r * 20 + cofs + 0] + bias[gc + 0];
                o0.y = stg[r * 20 + cofs + 1] + bias[gc + 1];
                o0.z = stg[r * 20 + cofs + 2] + bias[gc + 2];
                o0.w = stg[r * 20 + cofs + 3] + bias[gc + 3];
                o1.x = stg[r * 20 + cofs + 4] + bias[gc + 4];
                o1.y = stg[r * 20 + cofs + 5] + bias[gc + 5];
                o1.z = stg[r * 20 + cofs + 6] + bias[gc + 6];
                o1.w = stg[r * 20 + cofs + 7] + bias[gc + 7];
                *reinterpret_cast<float4*>(C + (size_t)gr * N + gc)     = o0;
                *reinterpret_cast<float4*>(C + (size_t)gr * N + gc + 4) = o1;
            }
            __syncwarp();
        }
    }
}

// ---------------------------------------------------------------------------
// score[n] = dot(Xfeat[n,:], a)
// ---------------------------------------------------------------------------
__global__ void score_kernel(const float* __restrict__ Xfeat, const float* __restrict__ a,
                             float* __restrict__ score, int N, int H)
{
    int warp = (blockIdx.x * blockDim.x + threadIdx.x) >> 5;
    int lane = threadIdx.x & 31;
    if (warp >= N) return;
    const float4* row = reinterpret_cast<const float4*>(Xfeat + (size_t)warp * H);
    const float4* av  = reinterpret_cast<const float4*>(a);
    float s = 0.f;
    for (int c4 = lane; c4 < H / 4; c4 += 32) {
        float4 x = row[c4];
        float4 w = av[c4];
        s += x.x * w.x + x.y * w.y + x.z * w.z + x.w * w.w;
    }
#pragma unroll
    for (int o = 16; o > 0; o >>= 1) s += __shfl_xor_sync(0xffffffffu, s, o);
    if (lane == 0) score[warp] = s;
}

// ---------------------------------------------------------------------------
// Fused v2e: segment softmax + weighted gather + elu -> bf16 hi/lo
// ---------------------------------------------------------------------------
template <int CH4>
__global__ __launch_bounds__(256)
void v2e_softmax_kernel(const float* __restrict__ Xfeat, const float* __restrict__ score,
                        const int* __restrict__ e_rowptr, const int* __restrict__ eV,
                        __nv_bfloat16* __restrict__ Yeh, __nv_bfloat16* __restrict__ Yel,
                        int M, int H)
{
    int warp = (blockIdx.x * blockDim.x + threadIdx.x) >> 5;
    int lane = threadIdx.x & 31;
    if (warp >= M) return;
    const int beg = e_rowptr[warp];
    const int end = e_rowptr[warp + 1];

    float m = -1e30f;
    for (int j = beg + lane; j < end; j += 32)
        m = fmaxf(m, leakyf(__ldg(&score[eV[j]])));
#pragma unroll
    for (int o = 16; o > 0; o >>= 1) m = fmaxf(m, __shfl_xor_sync(0xffffffffu, m, o));

    float den = 0.f;
    for (int j = beg + lane; j < end; j += 32)
        den += expf(leakyf(__ldg(&score[eV[j]])) - m);
#pragma unroll
    for (int o = 16; o > 0; o >>= 1) den += __shfl_xor_sync(0xffffffffu, den, o);
    float invden = (end > beg) ? 1.f / den : 0.f;

    float4 acc[CH4];
#pragma unroll
    for (int c = 0; c < CH4; c++) acc[c] = make_float4(0.f, 0.f, 0.f, 0.f);

    for (int j = beg; j < end; j++) {
        int v = eV[j];
        float w = expf(leakyf(__ldg(&score[v])) - m) * invden;
        const float4* row = reinterpret_cast<const float4*>(Xfeat + (size_t)v * H);
#pragma unroll
        for (int c = 0; c < CH4; c++) {
            float4 x = __ldg(&row[lane + 32 * c]);
            acc[c].x = fmaf(x.x, w, acc[c].x);
            acc[c].y = fmaf(x.y, w, acc[c].y);
            acc[c].z = fmaf(x.z, w, acc[c].z);
            acc[c].w = fmaf(x.w, w, acc[c].w);
        }
    }

#pragma unroll
    for (int c = 0; c < CH4; c++) {
        float4 o;
        o.x = eluf(acc[c].x); o.y = eluf(acc[c].y);
        o.z = eluf(acc[c].z); o.w = eluf(acc[c].w);
        size_t off = (size_t)warp * H + (lane + 32 * c) * 4;
        split_store4(o, Yeh + off, Yel + off);
    }
}

// ---------------------------------------------------------------------------
// Fused e2v: mean + elu + residual -> bf16 hi/lo
// ---------------------------------------------------------------------------
template <int CH4>
__global__ __launch_bounds__(256)
void e2v_mean_kernel(const float* __restrict__ Ye2,
                     const int* __restrict__ v_rowptr, const int* __restrict__ vE,
                     const float* __restrict__ Xinit,
                     __nv_bfloat16* __restrict__ hh, __nv_bfloat16* __restrict__ hl,
                     int N, int H)
{
    int warp = (blockIdx.x * blockDim.x + threadIdx.x) >> 5;
    int lane = threadIdx.x & 31;
    if (warp >= N) return;
    const int beg = v_rowptr[warp];
    const int end = v_rowptr[warp + 1];

    float4 acc[CH4];
#pragma unroll
    for (int c = 0; c < CH4; c++) acc[c] = make_float4(0.f, 0.f, 0.f, 0.f);

    for (int j = beg; j < end; j++) {
        int e = vE[j];
        const float4* row = reinterpret_cast<const float4*>(Ye2 + (size_t)e * H);
#pragma unroll
        for (int c = 0; c < CH4; c++) {
            float4 x = __ldg(&row[lane + 32 * c]);
            acc[c].x += x.x; acc[c].y += x.y; acc[c].z += x.z; acc[c].w += x.w;
        }
    }
    float inv = (end > beg) ? 1.f / (float)(end - beg) : 0.f;

    const float4* xi = reinterpret_cast<const float4*>(Xinit + (size_t)warp * H);
#pragma unroll
    for (int c = 0; c < CH4; c++) {
        float4 r = __ldg(&xi[lane + 32 * c]);
        float4 o;
        o.x = eluf(acc[c].x * inv) + r.x;
        o.y = eluf(acc[c].y * inv) + r.y;
        o.z = eluf(acc[c].z * inv) + r.z;
        o.w = eluf(acc[c].w * inv) + r.w;
        size_t off = (size_t)warp * H + (lane + 32 * c) * 4;
        split_store4(o, hh + off, hl + off);
    }
}

// ---------------------------------------------------------------------------
// Hyperconv edge + node (fp32)
// ---------------------------------------------------------------------------
template <int CH4>
__global__ __launch_bounds__(256)
void hyper_edge_kernel(const float* __restrict__ Xn,
                       const int* __restrict__ e_rowptr, const int* __restrict__ eV,
                       const int* __restrict__ v_rowptr,
                       float* __restrict__ Ye, int M, int O)
{
    int warp = (blockIdx.x * blockDim.x + threadIdx.x) >> 5;
    int lane = threadIdx.x & 31;
    if (warp >= M) return;
    const int beg = e_rowptr[warp];
    const int end = e_rowptr[warp + 1];
    const int cnt = end - beg;

    float sumDv = 0.f;
    for (int j = beg + lane; j < end; j += 32) {
        int v = eV[j];
        sumDv += (float)(__ldg(&v_rowptr[v + 1]) - __ldg(&v_rowptr[v]));
    }
#pragma unroll
    for (int o = 16; o > 0; o >>= 1) sumDv += __shfl_xor_sync(0xffffffffu, sumDv, o);

    float4 acc[CH4];
#pragma unroll
    for (int c = 0; c < CH4; c++) acc[c] = make_float4(0.f, 0.f, 0.f, 0.f);

    for (int j = beg; j < end; j++) {
        int v = eV[j];
        const float4* row = reinterpret_cast<const float4*>(Xn + (size_t)v * O);
#pragma unroll
        for (int c = 0; c < CH4; c++) {
            float4 x = __ldg(&row[lane + 32 * c]);
            acc[c].x += x.x; acc[c].y += x.y; acc[c].z += x.z; acc[c].w += x.w;
        }
    }

    float invc = (cnt > 0) ? 1.f / (float)cnt : 0.f;
    float De = sumDv / ((float)cnt + 1.f);
    float dinv = (De > 0.f) ? rsqrtf(De) : 1.f;
    float s = invc * dinv;

    float4* drow = reinterpret_cast<float4*>(Ye + (size_t)warp * O);
#pragma unroll
    for (int c = 0; c < CH4; c++) {
        float4 o;
        o.x = acc[c].x * s; o.y = acc[c].y * s;
        o.z = acc[c].z * s; o.w = acc[c].w * s;
        drow[lane + 32 * c] = o;
    }
}

template <int CH4>
__global__ __launch_bounds__(256)
void hyper_node_kernel(const float* __restrict__ Ye,
                       const int* __restrict__ v_rowptr, const int* __restrict__ vE,
                       float* __restrict__ out, int N, int O)
{
    int warp = (blockIdx.x * blockDim.x + threadIdx.x) >> 5;
    int lane = threadIdx.x & 31;
    if (warp >= N) return;
    const int beg = v_rowptr[warp];
    const int end = v_rowptr[warp + 1];
    const int deg = end - beg;

    float4 acc[CH4];
#pragma unroll
    for (int c = 0; c < CH4; c++) acc[c] = make_float4(0.f, 0.f, 0.f, 0.f);

    for (int j = beg; j < end; j++) {
        int e = vE[j];
        const float4* row = reinterpret_cast<const float4*>(Ye + (size_t)e * O);
#pragma unroll
        for (int c = 0; c < CH4; c++) {
            float4 x = __ldg(&row[lane + 32 * c]);
            acc[c].x += x.x; acc[c].y += x.y; acc[c].z += x.z; acc[c].w += x.w;
        }
    }
    float dinv = (deg > 0) ? rsqrtf((float)deg) : 0.f;

    float4* drow = reinterpret_cast<float4*>(out + (size_t)warp * O);
#pragma unroll
    for (int c = 0; c < CH4; c++) {
        float4 o;
        o.x = acc[c].x * dinv; o.y = acc[c].y * dinv;
        o.z = acc[c].z * dinv; o.w = acc[c].w * dinv;
        drow[lane + 32 * c] = o;
    }
}

// ---------------------------------------------------------------------------
// Host
// ---------------------------------------------------------------------------
static inline int ceil_div(int a, int b) { return (a + b - 1) / b; }

extern "C" void kernel_launch(void* const* d_in, const int* in_sizes, int n_in,
                              void* d_out, int out_size)
{
    const float* X   = (const float*)d_in[0];
    const int*   V   = (const int*)  d_in[1];
    const int*   E   = (const int*)  d_in[2];
    const float* S   = (const float*)d_in[3];
    const float* Wx0 = (const float*)d_in[4];
    const float* bx0 = (const float*)d_in[5];
    const float* Wv0 = (const float*)d_in[6];
    const float* bv0 = (const float*)d_in[7];
    const float* a0  = (const float*)d_in[8];
    const float* Wt0 = (const float*)d_in[9];
    const float* bt0 = (const float*)d_in[10];
    const float* Wx1 = (const float*)d_in[11];
    const float* bx1 = (const float*)d_in[12];
    const float* Wv1 = (const float*)d_in[13];
    const float* bv1 = (const float*)d_in[14];
    const float* a1  = (const float*)d_in[15];
    const float* Wt1 = (const float*)d_in[16];
    const float* bt1 = (const float*)d_in[17];
    const float* Wf  = (const float*)d_in[18];
    const float* bf  = (const float*)d_in[19];

    const int H    = in_sizes[5];              // 256
    const int IN   = in_sizes[4] / H;          // 128
    const int N    = in_sizes[0] / IN;         // 50000
    const int NNZ  = in_sizes[1];              // 400000
    const int HS   = in_sizes[9] / H;          // 320
    const int STAR = HS - H;                   // 64
    const int M    = in_sizes[3] / STAR;       // 20000
    const int OUT  = in_sizes[19];             // 128

    void* p;
    cudaGetSymbolAddress(&p, g_Xinit);    float* Xinit = (float*)p;
    cudaGetSymbolAddress(&p, g_Xfeat);    float* Xfeat = (float*)p;
    cudaGetSymbolAddress(&p, g_Ye2);      float* Ye2   = (float*)p;
    cudaGetSymbolAddress(&p, g_score);    float* score = (float*)p;
    cudaGetSymbolAddress(&p, g_Ah);  __nv_bfloat16* Ah  = (__nv_bfloat16*)p;
    cudaGetSymbolAddress(&p, g_Al);  __nv_bfloat16* Al  = (__nv_bfloat16*)p;
    cudaGetSymbolAddress(&p, g_Bh);  __nv_bfloat16* Bhh = (__nv_bfloat16*)p;
    cudaGetSymbolAddress(&p, g_Bl);  __nv_bfloat16* Bll = (__nv_bfloat16*)p;
    cudaGetSymbolAddress(&p, g_Yeh); __nv_bfloat16* Yeh = (__nv_bfloat16*)p;
    cudaGetSymbolAddress(&p, g_Yel); __nv_bfloat16* Yel = (__nv_bfloat16*)p;
    cudaGetSymbolAddress(&p, g_Sh);  __nv_bfloat16* Sh  = (__nv_bfloat16*)p;
    cudaGetSymbolAddress(&p, g_Sl);  __nv_bfloat16* Sl  = (__nv_bfloat16*)p;
    cudaGetSymbolAddress(&p, g_Wh);  __nv_bfloat16* Wh  = (__nv_bfloat16*)p;
    cudaGetSymbolAddress(&p, g_Wl);  __nv_bfloat16* Wl  = (__nv_bfloat16*)p;
    cudaGetSymbolAddress(&p, g_e_rowptr); int* e_rowptr = (int*)p;
    cudaGetSymbolAddress(&p, g_v_rowptr); int* v_rowptr = (int*)p;
    cudaGetSymbolAddress(&p, g_e_cursor); int* e_cursor = (int*)p;
    cudaGetSymbolAddress(&p, g_v_cursor); int* v_cursor = (int*)p;
    cudaGetSymbolAddress(&p, g_cntE);     int* cntE     = (int*)p;
    cudaGetSymbolAddress(&p, g_cntV);     int* cntV     = (int*)p;
    cudaGetSymbolAddress(&p, g_eV);       int* eV       = (int*)p;
    cudaGetSymbolAddress(&p, g_vE);       int* vE       = (int*)p;

    // one-time init (first call = correctness run, NOT under graph capture)
    static bool inited = false;
    static cudaStream_t s1 = 0, s2 = 0;
    static cudaEvent_t evFork, eW01, eWall, eCsr, eG1a, eX0, eG1b, eX1;
    if (!inited) {
        cudaFuncSetAttribute(gemm_bf16x3, cudaFuncAttributeMaxDynamicSharedMemorySize, GEMM_SMEM);
        if (cudaStreamCreateWithFlags(&s1, cudaStreamNonBlocking) != cudaSuccess) s1 = 0;
        if (cudaStreamCreateWithFlags(&s2, cudaStreamNonBlocking) != cudaSuccess) s2 = 0;
        cudaEventCreateWithFlags(&evFork, cudaEventDisableTiming);
        cudaEventCreateWithFlags(&eW01,  cudaEventDisableTiming);
        cudaEventCreateWithFlags(&eWall, cudaEventDisableTiming);
        cudaEventCreateWithFlags(&eCsr,  cudaEventDisableTiming);
        cudaEventCreateWithFlags(&eG1a,  cudaEventDisableTiming);
        cudaEventCreateWithFlags(&eX0,   cudaEventDisableTiming);
        cudaEventCreateWithFlags(&eG1b,  cudaEventDisableTiming);
        cudaEventCreateWithFlags(&eX1,   cudaEventDisableTiming);
        inited = true;
    }

    // weight offsets ([K,N] row-major, packed)
    const size_t o_wx0 = 0;
    const size_t o_wv0 = o_wx0 + (size_t)IN * H;
    const size_t o_wt0 = o_wv0 + (size_t)IN * H;
    const size_t o_wx1 = o_wt0 + (size_t)HS * H;
    const size_t o_wv1 = o_wx1 + (size_t)H * H;
    const size_t o_wt1 = o_wv1 + (size_t)H * H;
    const size_t o_wf  = o_wt1 + (size_t)HS * H;

    auto split = [&](const float* src, __nv_bfloat16* dh, __nv_bfloat16* dl, long nelem,
                     cudaStream_t st) {
        long n4 = nelem / 4;
        int blocks = (int)((n4 + 255) / 256); if (blocks > 2048) blocks = 2048;
        split_kernel<<<blocks, 256, 0, st>>>(src, dh, dl, n4);
    };

    auto gemm = [&](const __nv_bfloat16* a1h, const __nv_bfloat16* a1l, int K1,
                    const __nv_bfloat16* a2h, const __nv_bfloat16* a2l, int K2,
                    size_t woff, const float* bias, float* C, int Mrows, int Ncols,
                    cudaStream_t st) {
        dim3 grid(Ncols / 128, ceil_div(Mrows, 128));
        gemm_bf16x3<<<grid, 256, GEMM_SMEM, st>>>(a1h, a1l, K1, a2h, a2l, K2,
                                                  Wh + woff, Wl + woff, bias, C, Mrows, Ncols);
    };

    const int nnzBlocks     = ceil_div(NNZ, 256);
    const int edgeWarpBlocks = ceil_div(M, 8);
    const int nodeWarpBlocks = ceil_div(N, 8);

    // ---- fork ----
    cudaEventRecord(evFork, 0);
    cudaStreamWaitEvent(s1, evFork, 0);
    cudaStreamWaitEvent(s2, evFork, 0);

    // ---- s2: weight + S splits ----
    split(Wv0, Wh + o_wv0, Wl + o_wv0, (long)IN * H, s2);
    split(Wx0, Wh + o_wx0, Wl + o_wx0, (long)IN * H, s2);
    cudaEventRecord(eW01, s2);
    split(Wt0, Wh + o_wt0, Wl + o_wt0, (long)HS * H, s2);
    split(Wx1, Wh + o_wx1, Wl + o_wx1, (long)H * H,  s2);
    split(Wv1, Wh + o_wv1, Wl + o_wv1, (long)H * H,  s2);
    split(Wt1, Wh + o_wt1, Wl + o_wt1, (long)HS * H, s2);
    split(Wf,  Wh + o_wf,  Wl + o_wf,  (long)H * OUT, s2);
    split(S,   Sh, Sl, (long)M * STAR, s2);
    cudaEventRecord(eWall, s2);

    // ---- s1: CSR build ----
    fill_int<<<ceil_div(M, 256), 256, 0, s1>>>(cntE, 0, M);
    fill_int<<<ceil_div(N, 256), 256, 0, s1>>>(cntV, 0, N);
    count_kernel<<<nnzBlocks, 256, 0, s1>>>(V, E, cntV, cntE, NNZ);
    scan_kernel<<<1, 1024, 0, s1>>>(cntE, e_rowptr, e_cursor, M);
    scan_kernel<<<1, 1024, 0, s1>>>(cntV, v_rowptr, v_cursor, N);
    fill_lists_kernel<<<nnzBlocks, 256, 0, s1>>>(V, E, e_cursor, v_cursor, eV, vE, NNZ);
    cudaEventRecord(eCsr, s1);

    // ---- s0: split X, then layer 0 ----
    split(X, Ah, Al, (long)N * IN, 0);
    cudaStreamWaitEvent(0, eW01, 0);
    gemm(Ah, Al, IN, nullptr, nullptr, 0, o_wv0, bv0, Xfeat, N, H, 0);
    cudaEventRecord(eG1a, 0);

    // s1: Xinit GEMM overlapped with score/v2e/Wt-GEMM
    cudaStreamWaitEvent(s1, eG1a, 0);
    gemm(Ah, Al, IN, nullptr, nullptr, 0, o_wx0, bx0, Xinit, N, H, s1);
    cudaEventRecord(eX0, s1);

    score_kernel<<<ceil_div(N, 8), 256>>>(Xfeat, a0, score, N, H);
    cudaStreamWaitEvent(0, eCsr, 0);
    cudaStreamWaitEvent(0, eWall, 0);
    v2e_softmax_kernel<2><<<edgeWarpBlocks, 256>>>(Xfeat, score, e_rowptr, eV, Yeh, Yel, M, H);
    gemm(Yeh, Yel, H, Sh, Sl, STAR, o_wt0, bt0, Ye2, M, H, 0);
    cudaStreamWaitEvent(0, eX0, 0);
    e2v_mean_kernel<2><<<nodeWarpBlocks, 256>>>(Ye2, v_rowptr, vE, Xinit, Bhh, Bll, N, H);

    // ---- layer 1 ----
    gemm(Bhh, Bll, H, nullptr, nullptr, 0, o_wv1, bv1, Xfeat, N, H, 0);
    cudaEventRecord(eG1b, 0);

    cudaStreamWaitEvent(s1, eG1b, 0);
    gemm(Bhh, Bll, H, nullptr, nullptr, 0, o_wx1, bx1, Xinit, N, H, s1);
    cudaEventRecord(eX1, s1);

    score_kernel<<<ceil_div(N, 8), 256>>>(Xfeat, a1, score, N, H);
    v2e_softmax_kernel<2><<<edgeWarpBlocks, 256>>>(Xfeat, score, e_rowptr, eV, Yeh, Yel, M, H);
    gemm(Yeh, Yel, H, Sh, Sl, STAR, o_wt1, bt1, Ye2, M, H, 0);
    cudaStreamWaitEvent(0, eX1, 0);
    e2v_mean_kernel<2><<<nodeWarpBlocks, 256>>>(Ye2, v_rowptr, vE, Xinit, Ah, Al, N, H);

    // ---- hyperconv (s0) ----
    gemm(Ah, Al, H, nullptr, nullptr, 0, o_wf, bf, Xfeat, N, OUT, 0);
    hyper_edge_kernel<1><<<edgeWarpBlocks, 256>>>(Xfeat, e_rowptr, eV, v_rowptr, Ye2, M, OUT);
    hyper_node_kernel<1><<<nodeWarpBlocks, 256>>>(Ye2, v_rowptr, vE, (float*)d_out, N, OUT);
}

// round 7
// speedup vs baseline: 4.4627x; 1.4442x over previous
#include <cuda_runtime.h>
#include <cuda_fp16.h>
#include <mma.h>
#include <math.h>
#include <stdint.h>

using namespace nvcuda;

// ---------------------------------------------------------------------------
// Problem max sizes
// ---------------------------------------------------------------------------
#define NMAX   50000
#define MMAX   20000
#define NNZMAX 400000
#define HMAX   256
#define WTOTAL 393216

// ---------------------------------------------------------------------------
// Scratch (device globals)
// ---------------------------------------------------------------------------
__device__ float g_Xinit[NMAX * HMAX];
__device__ float g_Xfeat[NMAX * HMAX];
__device__ float g_Ye2  [MMAX * HMAX];
__device__ float g_score[NMAX];

__device__ __half g_A [NMAX * HMAX];   // activations (X / h2)
__device__ __half g_B [NMAX * HMAX];   // h1
__device__ __half g_Ye[MMAX * HMAX];   // edge features (v2e out)
__device__ __half g_S [MMAX * 64];
__device__ __half g_Wh[WTOTAL];        // weight hi, [K,N] row-major packed
__device__ __half g_Wl[WTOTAL];        // weight lo

// CSR structures
__device__ int g_e_rowptr[MMAX + 1];
__device__ int g_v_rowptr[NMAX + 1];
__device__ int g_e_cursor[MMAX];
__device__ int g_v_cursor[NMAX];
__device__ int g_cntE[MMAX];
__device__ int g_cntV[NMAX];
__device__ int g_eV[NNZMAX];
__device__ int g_vE[NNZMAX];

// ---------------------------------------------------------------------------
// Helpers
// ---------------------------------------------------------------------------
__device__ __forceinline__ float eluf(float x)  { return x > 0.f ? x : expm1f(x); }
__device__ __forceinline__ float leakyf(float x){ return x > 0.f ? x : 0.2f * x; }

__device__ __forceinline__ uint32_t smem_to_u32(const void* p) {
    uint32_t a;
    asm("{ .reg .u64 t; cvta.to.shared.u64 t, %1; cvt.u32.u64 %0, t; }" : "=r"(a) : "l"(p));
    return a;
}
__device__ __forceinline__ void cp_async16(uint32_t dst, const void* src, int sz) {
    asm volatile("cp.async.cg.shared.global [%0], [%1], 16, %2;"
                 :: "r"(dst), "l"(src), "r"(sz) : "memory");
}
#define CP_COMMIT() asm volatile("cp.async.commit_group;" ::: "memory")
#define CP_WAIT(n)  asm volatile("cp.async.wait_group %0;" :: "n"(n) : "memory")

// store float4 as 4 fp16 (8 bytes)
__device__ __forceinline__ void half_store4(float4 v, __half* p) {
    __half2 h0 = __floats2half2_rn(v.x, v.y);
    __half2 h1 = __floats2half2_rn(v.z, v.w);
    uint2 u;
    u.x = *reinterpret_cast<unsigned*>(&h0);
    u.y = *reinterpret_cast<unsigned*>(&h1);
    *reinterpret_cast<uint2*>(p) = u;
}

// activations: fp32 -> single fp16
__global__ void tohalf_kernel(const float* __restrict__ x, __half* __restrict__ out, long n4)
{
    long i = (long)blockIdx.x * blockDim.x + threadIdx.x;
    long stride = (long)gridDim.x * blockDim.x;
    for (; i < n4; i += stride) {
        float4 v = reinterpret_cast<const float4*>(x)[i];
        half_store4(v, out + 4 * i);
    }
}

// weights: fp32 -> fp16 hi + fp16 lo
__global__ void splitw_kernel(const float* __restrict__ w, __half* __restrict__ hi,
                              __half* __restrict__ lo, long n4)
{
    long i = (long)blockIdx.x * blockDim.x + threadIdx.x;
    long stride = (long)gridDim.x * blockDim.x;
    for (; i < n4; i += stride) {
        float4 v = reinterpret_cast<const float4*>(w)[i];
        __half h0 = __float2half_rn(v.x), h1 = __float2half_rn(v.y);
        __half h2 = __float2half_rn(v.z), h3 = __float2half_rn(v.w);
        __half l0 = __float2half_rn(v.x - __half2float(h0));
        __half l1 = __float2half_rn(v.y - __half2float(h1));
        __half l2 = __float2half_rn(v.z - __half2float(h2));
        __half l3 = __float2half_rn(v.w - __half2float(h3));
        __half2 ph0 = __halves2half2(h0, h1), ph1 = __halves2half2(h2, h3);
        __half2 pl0 = __halves2half2(l0, l1), pl1 = __halves2half2(l2, l3);
        uint2 uh, ul;
        uh.x = *reinterpret_cast<unsigned*>(&ph0); uh.y = *reinterpret_cast<unsigned*>(&ph1);
        ul.x = *reinterpret_cast<unsigned*>(&pl0); ul.y = *reinterpret_cast<unsigned*>(&pl1);
        *reinterpret_cast<uint2*>(hi + 4 * i) = uh;
        *reinterpret_cast<uint2*>(lo + 4 * i) = ul;
    }
}

__global__ void fill_int(int* __restrict__ p, int v, int n) {
    int i = blockIdx.x * blockDim.x + threadIdx.x;
    int stride = gridDim.x * blockDim.x;
    for (; i < n; i += stride) p[i] = v;
}

// ---------------------------------------------------------------------------
// CSR construction
// ---------------------------------------------------------------------------
__global__ void count_kernel(const int* __restrict__ V, const int* __restrict__ E,
                             int* __restrict__ cntV, int* __restrict__ cntE, int nnz)
{
    int i = blockIdx.x * blockDim.x + threadIdx.x;
    if (i >= nnz) return;
    atomicAdd(&cntE[E[i]], 1);
    atomicAdd(&cntV[V[i]], 1);
}

__global__ __launch_bounds__(1024)
void scan_kernel(const int* __restrict__ cnt, int* __restrict__ rowptr,
                 int* __restrict__ cursor, int len)
{
    __shared__ int wsum[32];
    __shared__ int s_carry;
    const int tid = threadIdx.x, lane = tid & 31, wid = tid >> 5;
    if (tid == 0) s_carry = 0;
    __syncthreads();

    for (int base = 0; base < len; base += 4096) {
        int i0 = base + tid * 4;
        int v0 = (i0 + 0 < len) ? cnt[i0 + 0] : 0;
        int v1 = (i0 + 1 < len) ? cnt[i0 + 1] : 0;
        int v2 = (i0 + 2 < len) ? cnt[i0 + 2] : 0;
        int v3 = (i0 + 3 < len) ? cnt[i0 + 3] : 0;
        int t1 = v0 + v1, t2 = t1 + v2, t3 = t2 + v3;

        int inc = t3;
#pragma unroll
        for (int o = 1; o < 32; o <<= 1) {
            int u = __shfl_up_sync(0xffffffffu, inc, o);
            if (lane >= o) inc += u;
        }
        if (lane == 31) wsum[wid] = inc;
        __syncthreads();
        if (wid == 0) {
            int w = wsum[lane];
            int wi = w;
#pragma unroll
            for (int o = 1; o < 32; o <<= 1) {
                int u = __shfl_up_sync(0xffffffffu, wi, o);
                if (lane >= o) wi += u;
            }
            wsum[lane] = wi - w;
        }
        __syncthreads();
        int excl = s_carry + wsum[wid] + (inc - t3);
        if (i0 + 0 < len) { rowptr[i0 + 0] = excl;      cursor[i0 + 0] = excl; }
        if (i0 + 1 < len) { rowptr[i0 + 1] = excl + v0; cursor[i0 + 1] = excl + v0; }
        if (i0 + 2 < len) { rowptr[i0 + 2] = excl + t1; cursor[i0 + 2] = excl + t1; }
        if (i0 + 3 < len) { rowptr[i0 + 3] = excl + t2; cursor[i0 + 3] = excl + t2; }
        __syncthreads();
        if (tid == 1023) s_carry = s_carry + wsum[31] + inc;
        __syncthreads();
    }
    if (threadIdx.x == 0) rowptr[len] = s_carry;
}

__global__ void fill_lists_kernel(const int* __restrict__ V, const int* __restrict__ E,
                                  int* __restrict__ e_cursor, int* __restrict__ v_cursor,
                                  int* __restrict__ eV, int* __restrict__ vE, int nnz)
{
    int i = blockIdx.x * blockDim.x + threadIdx.x;
    if (i >= nnz) return;
    int v = V[i], e = E[i];
    int pe = atomicAdd(&e_cursor[e], 1);
    eV[pe] = v;
    int pv = atomicAdd(&v_cursor[v], 1);
    vE[pv] = e;
}

// ---------------------------------------------------------------------------
// fp16x2 tensor-core GEMM with cp.async double buffering.
// C[M,N] = [A1 | A2] @ (Wh + Wl) + bias, fp32 out.
// A single fp16 row-major; W hi/lo [K,N] row-major fp16.
// BM=128, BN=128, BK=32; 256 threads (8 warps, 4x2), warp tile 32x64.
// ---------------------------------------------------------------------------
struct GemmStage {
    __half A [128][40];
    __half Bh[32][136];
    __half Bl[32][136];
};
static constexpr int GEMM_SMEM = 2 * sizeof(GemmStage);   // 55296

__global__ __launch_bounds__(256, 2)
void gemm_fp16x2(const __half* __restrict__ A1, int K1,
                 const __half* __restrict__ A2, int K2,
                 const __half* __restrict__ Bhg, const __half* __restrict__ Blg,
                 const float* __restrict__ bias, float* __restrict__ C,
                 int M, int N)
{
    extern __shared__ char smem_raw[];
    GemmStage* st = reinterpret_cast<GemmStage*>(smem_raw);

    const int tid  = threadIdx.x;
    const int wid  = tid >> 5, lane = tid & 31;
    const int wm   = wid >> 1, wn = wid & 1;
    const int row0 = blockIdx.y * 128;
    const int col0 = blockIdx.x * 128;
    const int K = K1 + K2, nch = K >> 5;

    wmma::fragment<wmma::accumulator, 16, 16, 16, float> acc[2][4];
#pragma unroll
    for (int mt = 0; mt < 2; mt++)
#pragma unroll
        for (int nt = 0; nt < 4; nt++) wmma::fill_fragment(acc[mt][nt], 0.f);

    auto prefetch = [&](int c, int s) {
        const int k0 = c * 32;
        const __half* a; int lda, col;
        if (k0 < K1) { a = A1; lda = K1; col = k0; }
        else         { a = A2; lda = K2; col = k0 - K1; }
        // A: 128 rows x 32 halves = 8 KB -> 512 x 16B over 2 iters
#pragma unroll
        for (int t = 0; t < 2; t++) {
            int u = tid + t * 256, r = u >> 2, q = u & 3;
            int gr = row0 + r;
            int sz = (gr < M) ? 16 : 0;
            size_t off = (size_t)(gr < M ? gr : 0) * lda + col + q * 8;
            cp_async16(smem_to_u32(&st[s].A[r][q * 8]), a + off, sz);
        }
        // B hi + lo: 32 rows x 128 halves each
#pragma unroll
        for (int t = 0; t < 2; t++) {
            int u = tid + t * 256, r = u >> 4, q = u & 15;
            size_t off = (size_t)(k0 + r) * N + col0 + q * 8;
            cp_async16(smem_to_u32(&st[s].Bh[r][q * 8]), Bhg + off, 16);
            cp_async16(smem_to_u32(&st[s].Bl[r][q * 8]), Blg + off, 16);
        }
    };

    prefetch(0, 0);
    CP_COMMIT();

    for (int c = 0; c < nch; c++) {
        const int s = c & 1;
        if (c + 1 < nch) {
            prefetch(c + 1, s ^ 1);
            CP_COMMIT();
            CP_WAIT(1);
        } else {
            CP_WAIT(0);
        }
        __syncthreads();

#pragma unroll
        for (int ks = 0; ks < 2; ks++) {
            wmma::fragment<wmma::matrix_a, 16, 16, 16, __half, wmma::row_major> af[2];
#pragma unroll
            for (int mt = 0; mt < 2; mt++)
                wmma::load_matrix_sync(af[mt], &st[s].A[wm * 32 + mt * 16][ks * 16], 40);
#pragma unroll
            for (int nt = 0; nt < 4; nt++) {
                wmma::fragment<wmma::matrix_b, 16, 16, 16, __half, wmma::row_major> bh, bl;
                wmma::load_matrix_sync(bh, &st[s].Bh[ks * 16][wn * 64 + nt * 16], 136);
                wmma::load_matrix_sync(bl, &st[s].Bl[ks * 16][wn * 64 + nt * 16], 136);
#pragma unroll
                for (int mt = 0; mt < 2; mt++) {
                    wmma::mma_sync(acc[mt][nt], af[mt], bh, acc[mt][nt]);
                    wmma::mma_sync(acc[mt][nt], af[mt], bl, acc[mt][nt]);
                }
            }
        }
        __syncthreads();
    }

    // epilogue: stage each 16x16 tile in smem, add bias
    float* stg = reinterpret_cast<float*>(smem_raw) + wid * 320;
#pragma unroll
    for (int mt = 0; mt < 2; mt++) {
#pragma unroll
        for (int nt = 0; nt < 4; nt++) {
            wmma::store_matrix_sync(stg, acc[mt][nt], 20, wmma::mem_row_major);
            __syncwarp();
            int r = lane >> 1, cofs = (lane & 1) * 8;
            int gr = row0 + wm * 32 + mt * 16 + r;
            int gc = col0 + wn * 64 + nt * 16 + cofs;
            if (gr < M) {
                float4 o0, o1;
                o0.x = stg[r * 20 + cofs + 0] + bias[gc + 0];
                o0.y = stg[r * 20 + cofs + 1] + bias[gc + 1];
                o0.z = stg[r * 20 + cofs + 2] + bias[gc + 2];
                o0.w = stg[r * 20 + cofs + 3] + bias[gc + 3];
                o1.x = stg[r * 20 + cofs + 4] + bias[gc + 4];
                o1.y = stg[r * 20 + cofs + 5] + bias[gc + 5];
                o1.z = stg[r * 20 + cofs + 6] + bias[gc + 6];
                o1.w = stg[r * 20 + cofs + 7] + bias[gc + 7];
                *reinterpret_cast<float4*>(C + (size_t)gr * N + gc)     = o0;
                *reinterpret_cast<float4*>(C + (size_t)gr * N + gc + 4) = o1;
            }
            __syncwarp();
        }
    }
}

// ---------------------------------------------------------------------------
// score[n] = dot(Xfeat[n,:], a)
// ---------------------------------------------------------------------------
__global__ void score_kernel(const float* __restrict__ Xfeat, const float* __restrict__ a,
                             float* __restrict__ score, int N, int H)
{
    int warp = (blockIdx.x * blockDim.x + threadIdx.x) >> 5;
    int lane = threadIdx.x & 31;
    if (warp >= N) return;
    const float4* row = reinterpret_cast<const float4*>(Xfeat + (size_t)warp * H);
    const float4* av  = reinterpret_cast<const float4*>(a);
    float s = 0.f;
    for (int c4 = lane; c4 < H / 4; c4 += 32) {
        float4 x = row[c4];
        float4 w = av[c4];
        s += x.x * w.x + x.y * w.y + x.z * w.z + x.w * w.w;
    }
#pragma unroll
    for (int o = 16; o > 0; o >>= 1) s += __shfl_xor_sync(0xffffffffu, s, o);
    if (lane == 0) score[warp] = s;
}

// ---------------------------------------------------------------------------
// Fused v2e: segment softmax + weighted gather + elu -> fp16 out
// ---------------------------------------------------------------------------
template <int CH4>
__global__ __launch_bounds__(256)
void v2e_softmax_kernel(const float* __restrict__ Xfeat, const float* __restrict__ score,
                        const int* __restrict__ e_rowptr, const int* __restrict__ eV,
                        __half* __restrict__ Ye, int M, int H)
{
    int warp = (blockIdx.x * blockDim.x + threadIdx.x) >> 5;
    int lane = threadIdx.x & 31;
    if (warp >= M) return;
    const int beg = e_rowptr[warp];
    const int end = e_rowptr[warp + 1];

    float m = -1e30f;
    for (int j = beg + lane; j < end; j += 32)
        m = fmaxf(m, leakyf(__ldg(&score[eV[j]])));
#pragma unroll
    for (int o = 16; o > 0; o >>= 1) m = fmaxf(m, __shfl_xor_sync(0xffffffffu, m, o));

    float den = 0.f;
    for (int j = beg + lane; j < end; j += 32)
        den += expf(leakyf(__ldg(&score[eV[j]])) - m);
#pragma unroll
    for (int o = 16; o > 0; o >>= 1) den += __shfl_xor_sync(0xffffffffu, den, o);
    float invden = (end > beg) ? 1.f / den : 0.f;

    float4 acc[CH4];
#pragma unroll
    for (int c = 0; c < CH4; c++) acc[c] = make_float4(0.f, 0.f, 0.f, 0.f);

    for (int j = beg; j < end; j++) {
        int v = eV[j];
        float w = expf(leakyf(__ldg(&score[v])) - m) * invden;
        const float4* row = reinterpret_cast<const float4*>(Xfeat + (size_t)v * H);
#pragma unroll
        for (int c = 0; c < CH4; c++) {
            float4 x = __ldg(&row[lane + 32 * c]);
            acc[c].x = fmaf(x.x, w, acc[c].x);
            acc[c].y = fmaf(x.y, w, acc[c].y);
            acc[c].z = fmaf(x.z, w, acc[c].z);
            acc[c].w = fmaf(x.w, w, acc[c].w);
        }
    }

#pragma unroll
    for (int c = 0; c < CH4; c++) {
        float4 o;
        o.x = eluf(acc[c].x); o.y = eluf(acc[c].y);
        o.z = eluf(acc[c].z); o.w = eluf(acc[c].w);
        half_store4(o, Ye + (size_t)warp * H + (lane + 32 * c) * 4);
    }
}

// ---------------------------------------------------------------------------
// Fused e2v: mean + elu + residual -> fp16 out
// ---------------------------------------------------------------------------
template <int CH4>
__global__ __launch_bounds__(256)
void e2v_mean_kernel(const float* __restrict__ Ye2,
                     const int* __restrict__ v_rowptr, const int* __restrict__ vE,
                     const float* __restrict__ Xinit,
                     __half* __restrict__ hout, int N, int H)
{
    int warp = (blockIdx.x * blockDim.x + threadIdx.x) >> 5;
    int lane = threadIdx.x & 31;
    if (warp >= N) return;
    const int beg = v_rowptr[warp];
    const int end = v_rowptr[warp + 1];

    float4 acc[CH4];
#pragma unroll
    for (int c = 0; c < CH4; c++) acc[c] = make_float4(0.f, 0.f, 0.f, 0.f);

    for (int j = beg; j < end; j++) {
        int e = vE[j];
        const float4* row = reinterpret_cast<const float4*>(Ye2 + (size_t)e * H);
#pragma unroll
        for (int c = 0; c < CH4; c++) {
            float4 x = __ldg(&row[lane + 32 * c]);
            acc[c].x += x.x; acc[c].y += x.y; acc[c].z += x.z; acc[c].w += x.w;
        }
    }
    float inv = (end > beg) ? 1.f / (float)(end - beg) : 0.f;

    const float4* xi = reinterpret_cast<const float4*>(Xinit + (size_t)warp * H);
#pragma unroll
    for (int c = 0; c < CH4; c++) {
        float4 r = __ldg(&xi[lane + 32 * c]);
        float4 o;
        o.x = eluf(acc[c].x * inv) + r.x;
        o.y = eluf(acc[c].y * inv) + r.y;
        o.z = eluf(acc[c].z * inv) + r.z;
        o.w = eluf(acc[c].w * inv) + r.w;
        half_store4(o, hout + (size_t)warp * H + (lane + 32 * c) * 4);
    }
}

// ---------------------------------------------------------------------------
// Hyperconv edge + node (fp32)
// ---------------------------------------------------------------------------
template <int CH4>
__global__ __launch_bounds__(256)
void hyper_edge_kernel(const float* __restrict__ Xn,
                       const int* __restrict__ e_rowptr, const int* __restrict__ eV,
                       const int* __restrict__ v_rowptr,
                       float* __restrict__ Ye, int M, int O)
{
    int warp = (blockIdx.x * blockDim.x + threadIdx.x) >> 5;
    int lane = threadIdx.x & 31;
    if (warp >= M) return;
    const int beg = e_rowptr[warp];
    const int end = e_rowptr[warp + 1];
    const int cnt = end - beg;

    float sumDv = 0.f;
    for (int j = beg + lane; j < end; j += 32) {
        int v = eV[j];
        sumDv += (float)(__ldg(&v_rowptr[v + 1]) - __ldg(&v_rowptr[v]));
    }
#pragma unroll
    for (int o = 16; o > 0; o >>= 1) sumDv += __shfl_xor_sync(0xffffffffu, sumDv, o);

    float4 acc[CH4];
#pragma unroll
    for (int c = 0; c < CH4; c++) acc[c] = make_float4(0.f, 0.f, 0.f, 0.f);

    for (int j = beg; j < end; j++) {
        int v = eV[j];
        const float4* row = reinterpret_cast<const float4*>(Xn + (size_t)v * O);
#pragma unroll
        for (int c = 0; c < CH4; c++) {
            float4 x = __ldg(&row[lane + 32 * c]);
            acc[c].x += x.x; acc[c].y += x.y; acc[c].z += x.z; acc[c].w += x.w;
        }
    }

    float invc = (cnt > 0) ? 1.f / (float)cnt : 0.f;
    float De = sumDv / ((float)cnt + 1.f);
    float dinv = (De > 0.f) ? rsqrtf(De) : 1.f;
    float s = invc * dinv;

    float4* drow = reinterpret_cast<float4*>(Ye + (size_t)warp * O);
#pragma unroll
    for (int c = 0; c < CH4; c++) {
        float4 o;
        o.x = acc[c].x * s; o.y = acc[c].y * s;
        o.z = acc[c].z * s; o.w = acc[c].w * s;
        drow[lane + 32 * c] = o;
    }
}

template <int CH4>
__global__ __launch_bounds__(256)
void hyper_node_kernel(const float* __restrict__ Ye,
                       const int* __restrict__ v_rowptr, const int* __restrict__ vE,
                       float* __restrict__ out, int N, int O)
{
    int warp = (blockIdx.x * blockDim.x + threadIdx.x) >> 5;
    int lane = threadIdx.x & 31;
    if (warp >= N) return;
    const int beg = v_rowptr[warp];
    const int end = v_rowptr[warp + 1];
    const int deg = end - beg;

    float4 acc[CH4];
#pragma unroll
    for (int c = 0; c < CH4; c++) acc[c] = make_float4(0.f, 0.f, 0.f, 0.f);

    for (int j = beg; j < end; j++) {
        int e = vE[j];
        const float4* row = reinterpret_cast<const float4*>(Ye + (size_t)e * O);
#pragma unroll
        for (int c = 0; c < CH4; c++) {
            float4 x = __ldg(&row[lane + 32 * c]);
            acc[c].x += x.x; acc[c].y += x.y; acc[c].z += x.z; acc[c].w += x.w;
        }
    }
    float dinv = (deg > 0) ? rsqrtf((float)deg) : 0.f;

    float4* drow = reinterpret_cast<float4*>(out + (size_t)warp * O);
#pragma unroll
    for (int c = 0; c < CH4; c++) {
        float4 o;
        o.x = acc[c].x * dinv; o.y = acc[c].y * dinv;
        o.z = acc[c].z * dinv; o.w = acc[c].w * dinv;
        drow[lane + 32 * c] = o;
    }
}

// ---------------------------------------------------------------------------
// Host
// ---------------------------------------------------------------------------
static inline int ceil_div(int a, int b) { return (a + b - 1) / b; }

extern "C" void kernel_launch(void* const* d_in, const int* in_sizes, int n_in,
                              void* d_out, int out_size)
{
    const float* X   = (const float*)d_in[0];
    const int*   V   = (const int*)  d_in[1];
    const int*   E   = (const int*)  d_in[2];
    const float* S   = (const float*)d_in[3];
    const float* Wx0 = (const float*)d_in[4];
    const float* bx0 = (const float*)d_in[5];
    const float* Wv0 = (const float*)d_in[6];
    const float* bv0 = (const float*)d_in[7];
    const float* a0  = (const float*)d_in[8];
    const float* Wt0 = (const float*)d_in[9];
    const float* bt0 = (const float*)d_in[10];
    const float* Wx1 = (const float*)d_in[11];
    const float* bx1 = (const float*)d_in[12];
    const float* Wv1 = (const float*)d_in[13];
    const float* bv1 = (const float*)d_in[14];
    const float* a1  = (const float*)d_in[15];
    const float* Wt1 = (const float*)d_in[16];
    const float* bt1 = (const float*)d_in[17];
    const float* Wf  = (const float*)d_in[18];
    const float* bf  = (const float*)d_in[19];

    const int H    = in_sizes[5];              // 256
    const int IN   = in_sizes[4] / H;          // 128
    const int N    = in_sizes[0] / IN;         // 50000
    const int NNZ  = in_sizes[1];              // 400000
    const int HS   = in_sizes[9] / H;          // 320
    const int STAR = HS - H;                   // 64
    const int M    = in_sizes[3] / STAR;       // 20000
    const int OUT  = in_sizes[19];             // 128

    void* p;
    cudaGetSymbolAddress(&p, g_Xinit); float* Xinit = (float*)p;
    cudaGetSymbolAddress(&p, g_Xfeat); float* Xfeat = (float*)p;
    cudaGetSymbolAddress(&p, g_Ye2);   float* Ye2   = (float*)p;
    cudaGetSymbolAddress(&p, g_score); float* score = (float*)p;
    cudaGetSymbolAddress(&p, g_A);  __half* Abuf = (__half*)p;
    cudaGetSymbolAddress(&p, g_B);  __half* Bbuf = (__half*)p;
    cudaGetSymbolAddress(&p, g_Ye); __half* Yeh  = (__half*)p;
    cudaGetSymbolAddress(&p, g_S);  __half* Sh   = (__half*)p;
    cudaGetSymbolAddress(&p, g_Wh); __half* Wh   = (__half*)p;
    cudaGetSymbolAddress(&p, g_Wl); __half* Wl   = (__half*)p;
    cudaGetSymbolAddress(&p, g_e_rowptr); int* e_rowptr = (int*)p;
    cudaGetSymbolAddress(&p, g_v_rowptr); int* v_rowptr = (int*)p;
    cudaGetSymbolAddress(&p, g_e_cursor); int* e_cursor = (int*)p;
    cudaGetSymbolAddress(&p, g_v_cursor); int* v_cursor = (int*)p;
    cudaGetSymbolAddress(&p, g_cntE);     int* cntE     = (int*)p;
    cudaGetSymbolAddress(&p, g_cntV);     int* cntV     = (int*)p;
    cudaGetSymbolAddress(&p, g_eV);       int* eV       = (int*)p;
    cudaGetSymbolAddress(&p, g_vE);       int* vE       = (int*)p;

    // one-time init (first call = correctness run, NOT under graph capture)
    static bool inited = false;
    static cudaStream_t s1 = 0, s2 = 0;
    static cudaEvent_t evFork, eW01, eWall, eCsr, eG1a, eX0, eG1b, eX1;
    if (!inited) {
        cudaFuncSetAttribute(gemm_fp16x2, cudaFuncAttributeMaxDynamicSharedMemorySize, GEMM_SMEM);
        if (cudaStreamCreateWithFlags(&s1, cudaStreamNonBlocking) != cudaSuccess) s1 = 0;
        if (cudaStreamCreateWithFlags(&s2, cudaStreamNonBlocking) != cudaSuccess) s2 = 0;
        cudaEventCreateWithFlags(&evFork, cudaEventDisableTiming);
        cudaEventCreateWithFlags(&eW01,  cudaEventDisableTiming);
        cudaEventCreateWithFlags(&eWall, cudaEventDisableTiming);
        cudaEventCreateWithFlags(&eCsr,  cudaEventDisableTiming);
        cudaEventCreateWithFlags(&eG1a,  cudaEventDisableTiming);
        cudaEventCreateWithFlags(&eX0,   cudaEventDisableTiming);
        cudaEventCreateWithFlags(&eG1b,  cudaEventDisableTiming);
        cudaEventCreateWithFlags(&eX1,   cudaEventDisableTiming);
        inited = true;
    }

    // weight offsets ([K,N] row-major, packed)
    const size_t o_wx0 = 0;
    const size_t o_wv0 = o_wx0 + (size_t)IN * H;
    const size_t o_wt0 = o_wv0 + (size_t)IN * H;
    const size_t o_wx1 = o_wt0 + (size_t)HS * H;
    const size_t o_wv1 = o_wx1 + (size_t)H * H;
    const size_t o_wt1 = o_wv1 + (size_t)H * H;
    const size_t o_wf  = o_wt1 + (size_t)HS * H;

    auto splitw = [&](const float* src, __half* dh, __half* dl, long nelem, cudaStream_t st) {
        long n4 = nelem / 4;
        int blocks = (int)((n4 + 255) / 256); if (blocks > 2048) blocks = 2048;
        splitw_kernel<<<blocks, 256, 0, st>>>(src, dh, dl, n4);
    };
    auto tohalf = [&](const float* src, __half* dst, long nelem, cudaStream_t st) {
        long n4 = nelem / 4;
        int blocks = (int)((n4 + 255) / 256); if (blocks > 2048) blocks = 2048;
        tohalf_kernel<<<blocks, 256, 0, st>>>(src, dst, n4);
    };

    auto gemm = [&](const __half* a1, int K1, const __half* a2, int K2,
                    size_t woff, const float* bias, float* C, int Mrows, int Ncols,
                    cudaStream_t st) {
        dim3 grid(Ncols / 128, ceil_div(Mrows, 128));
        gemm_fp16x2<<<grid, 256, GEMM_SMEM, st>>>(a1, K1, a2, K2,
                                                  Wh + woff, Wl + woff, bias, C, Mrows, Ncols);
    };

    const int nnzBlocks      = ceil_div(NNZ, 256);
    const int edgeWarpBlocks = ceil_div(M, 8);
    const int nodeWarpBlocks = ceil_div(N, 8);

    // ---- fork ----
    cudaEventRecord(evFork, 0);
    cudaStreamWaitEvent(s1, evFork, 0);
    cudaStreamWaitEvent(s2, evFork, 0);

    // ---- s2: weight splits + S conversion ----
    splitw(Wv0, Wh + o_wv0, Wl + o_wv0, (long)IN * H, s2);
    splitw(Wx0, Wh + o_wx0, Wl + o_wx0, (long)IN * H, s2);
    cudaEventRecord(eW01, s2);
    splitw(Wt0, Wh + o_wt0, Wl + o_wt0, (long)HS * H, s2);
    splitw(Wx1, Wh + o_wx1, Wl + o_wx1, (long)H * H,  s2);
    splitw(Wv1, Wh + o_wv1, Wl + o_wv1, (long)H * H,  s2);
    splitw(Wt1, Wh + o_wt1, Wl + o_wt1, (long)HS * H, s2);
    splitw(Wf,  Wh + o_wf,  Wl + o_wf,  (long)H * OUT, s2);
    tohalf(S, Sh, (long)M * STAR, s2);
    cudaEventRecord(eWall, s2);

    // ---- s1: CSR build ----
    fill_int<<<ceil_div(M, 256), 256, 0, s1>>>(cntE, 0, M);
    fill_int<<<ceil_div(N, 256), 256, 0, s1>>>(cntV, 0, N);
    count_kernel<<<nnzBlocks, 256, 0, s1>>>(V, E, cntV, cntE, NNZ);
    scan_kernel<<<1, 1024, 0, s1>>>(cntE, e_rowptr, e_cursor, M);
    scan_kernel<<<1, 1024, 0, s1>>>(cntV, v_rowptr, v_cursor, N);
    fill_lists_kernel<<<nnzBlocks, 256, 0, s1>>>(V, E, e_cursor, v_cursor, eV, vE, NNZ);
    cudaEventRecord(eCsr, s1);

    // ---- s0: convert X, then layer 0 ----
    tohalf(X, Abuf, (long)N * IN, 0);
    cudaStreamWaitEvent(0, eW01, 0);
    gemm(Abuf, IN, nullptr, 0, o_wv0, bv0, Xfeat, N, H, 0);
    cudaEventRecord(eG1a, 0);

    // s1: Xinit GEMM overlapped with score/v2e/Wt-GEMM
    cudaStreamWaitEvent(s1, eG1a, 0);
    gemm(Abuf, IN, nullptr, 0, o_wx0, bx0, Xinit, N, H, s1);
    cudaEventRecord(eX0, s1);

    score_kernel<<<ceil_div(N, 8), 256>>>(Xfeat, a0, score, N, H);
    cudaStreamWaitEvent(0, eCsr, 0);
    cudaStreamWaitEvent(0, eWall, 0);
    v2e_softmax_kernel<2><<<edgeWarpBlocks, 256>>>(Xfeat, score, e_rowptr, eV, Yeh, M, H);
    gemm(Yeh, H, Sh, STAR, o_wt0, bt0, Ye2, M, H, 0);
    cudaStreamWaitEvent(0, eX0, 0);
    e2v_mean_kernel<2><<<nodeWarpBlocks, 256>>>(Ye2, v_rowptr, vE, Xinit, Bbuf, N, H);

    // ---- layer 1 ----
    gemm(Bbuf, H, nullptr, 0, o_wv1, bv1, Xfeat, N, H, 0);
    cudaEventRecord(eG1b, 0);

    cudaStreamWaitEvent(s1, eG1b, 0);
    gemm(Bbuf, H, nullptr, 0, o_wx1, bx1, Xinit, N, H, s1);
    cudaEventRecord(eX1, s1);

    score_kernel<<<ceil_div(N, 8), 256>>>(Xfeat, a1, score, N, H);
    v2e_softmax_kernel<2><<<edgeWarpBlocks, 256>>>(Xfeat, score, e_rowptr, eV, Yeh, M, H);
    gemm(Yeh, H, Sh, STAR, o_wt1, bt1, Ye2, M, H, 0);
    cudaStreamWaitEvent(0, eX1, 0);
    e2v_mean_kernel<2><<<nodeWarpBlocks, 256>>>(Ye2, v_rowptr, vE, Xinit, Abuf, N, H);

    // ---- hyperconv (s0) ----
    gemm(Abuf, H, nullptr, 0, o_wf, bf, Xfeat, N, OUT, 0);
    hyper_edge_kernel<1><<<edgeWarpBlocks, 256>>>(Xfeat, e_rowptr, eV, v_rowptr, Ye2, M, OUT);
    hyper_node_kernel<1><<<nodeWarpBlocks, 256>>>(Ye2, v_rowptr, vE, (float*)d_out, N, OUT);
}

// round 8
// speedup vs baseline: 4.9146x; 1.1012x over previous
#include <cuda_runtime.h>
#include <cuda_fp16.h>
#include <mma.h>
#include <math.h>
#include <stdint.h>

using namespace nvcuda;

// ---------------------------------------------------------------------------
// Problem max sizes
// ---------------------------------------------------------------------------
#define NMAX   50000
#define MMAX   20000
#define NNZMAX 400000
#define HMAX   256
#define WTOTAL 393216

// ---------------------------------------------------------------------------
// Scratch (device globals)
// ---------------------------------------------------------------------------
__device__ float g_Xinit[NMAX * HMAX];
__device__ float g_score[NMAX];

__device__ __half g_Xfeat[NMAX * HMAX];  // fp16 GEMM outputs (Wv / Wf)
__device__ __half g_Ye2  [MMAX * HMAX];  // fp16 GEMM output (Wt)
__device__ __half g_A [NMAX * HMAX];     // activations (X / h2)
__device__ __half g_B [NMAX * HMAX];     // h1
__device__ __half g_Ye[MMAX * HMAX];     // v2e out / hyper_edge out
__device__ __half g_S [MMAX * 64];
__device__ __half g_Wh[WTOTAL];          // weight hi, [K,N] row-major packed
__device__ __half g_Wl[WTOTAL];          // weight lo

// CSR structures
__device__ int g_e_rowptr[MMAX + 1];
__device__ int g_v_rowptr[NMAX + 1];
__device__ int g_e_cursor[MMAX];
__device__ int g_v_cursor[NMAX];
__device__ int g_cntE[MMAX];
__device__ int g_cntV[NMAX];
__device__ int g_eV[NNZMAX];
__device__ int g_vE[NNZMAX];

// ---------------------------------------------------------------------------
// Helpers
// ---------------------------------------------------------------------------
__device__ __forceinline__ float eluf(float x)  { return x > 0.f ? x : expm1f(x); }
__device__ __forceinline__ float leakyf(float x){ return x > 0.f ? x : 0.2f * x; }

__device__ __forceinline__ uint32_t smem_to_u32(const void* p) {
    uint32_t a;
    asm("{ .reg .u64 t; cvta.to.shared.u64 t, %1; cvt.u32.u64 %0, t; }" : "=r"(a) : "l"(p));
    return a;
}
__device__ __forceinline__ void cp_async16(uint32_t dst, const void* src, int sz) {
    asm volatile("cp.async.cg.shared.global [%0], [%1], 16, %2;"
                 :: "r"(dst), "l"(src), "r"(sz) : "memory");
}
#define CP_COMMIT() asm volatile("cp.async.commit_group;" ::: "memory")
#define CP_WAIT(n)  asm volatile("cp.async.wait_group %0;" :: "n"(n) : "memory")

// activations: fp32 -> single fp16
__global__ void tohalf_kernel(const float* __restrict__ x, __half* __restrict__ out, long n4)
{
    long i = (long)blockIdx.x * blockDim.x + threadIdx.x;
    long stride = (long)gridDim.x * blockDim.x;
    for (; i < n4; i += stride) {
        float4 v = reinterpret_cast<const float4*>(x)[i];
        __half2 h0 = __floats2half2_rn(v.x, v.y);
        __half2 h1 = __floats2half2_rn(v.z, v.w);
        uint2 u;
        u.x = *reinterpret_cast<unsigned*>(&h0);
        u.y = *reinterpret_cast<unsigned*>(&h1);
        *reinterpret_cast<uint2*>(out + 4 * i) = u;
    }
}

// weights: fp32 -> fp16 hi + fp16 lo
__global__ void splitw_kernel(const float* __restrict__ w, __half* __restrict__ hi,
                              __half* __restrict__ lo, long n4)
{
    long i = (long)blockIdx.x * blockDim.x + threadIdx.x;
    long stride = (long)gridDim.x * blockDim.x;
    for (; i < n4; i += stride) {
        float4 v = reinterpret_cast<const float4*>(w)[i];
        __half h0 = __float2half_rn(v.x), h1 = __float2half_rn(v.y);
        __half h2 = __float2half_rn(v.z), h3 = __float2half_rn(v.w);
        __half l0 = __float2half_rn(v.x - __half2float(h0));
        __half l1 = __float2half_rn(v.y - __half2float(h1));
        __half l2 = __float2half_rn(v.z - __half2float(h2));
        __half l3 = __float2half_rn(v.w - __half2float(h3));
        __half2 ph0 = __halves2half2(h0, h1), ph1 = __halves2half2(h2, h3);
        __half2 pl0 = __halves2half2(l0, l1), pl1 = __halves2half2(l2, l3);
        uint2 uh, ul;
        uh.x = *reinterpret_cast<unsigned*>(&ph0); uh.y = *reinterpret_cast<unsigned*>(&ph1);
        ul.x = *reinterpret_cast<unsigned*>(&pl0); ul.y = *reinterpret_cast<unsigned*>(&pl1);
        *reinterpret_cast<uint2*>(hi + 4 * i) = uh;
        *reinterpret_cast<uint2*>(lo + 4 * i) = ul;
    }
}

__global__ void fill_int(int* __restrict__ p, int v, int n) {
    int i = blockIdx.x * blockDim.x + threadIdx.x;
    int stride = gridDim.x * blockDim.x;
    for (; i < n; i += stride) p[i] = v;
}

// ---------------------------------------------------------------------------
// CSR construction
// ---------------------------------------------------------------------------
__global__ void count_kernel(const int* __restrict__ V, const int* __restrict__ E,
                             int* __restrict__ cntV, int* __restrict__ cntE, int nnz)
{
    int i = blockIdx.x * blockDim.x + threadIdx.x;
    if (i >= nnz) return;
    atomicAdd(&cntE[E[i]], 1);
    atomicAdd(&cntV[V[i]], 1);
}

__global__ __launch_bounds__(1024)
void scan_kernel(const int* __restrict__ cnt, int* __restrict__ rowptr,
                 int* __restrict__ cursor, int len)
{
    __shared__ int wsum[32];
    __shared__ int s_carry;
    const int tid = threadIdx.x, lane = tid & 31, wid = tid >> 5;
    if (tid == 0) s_carry = 0;
    __syncthreads();

    for (int base = 0; base < len; base += 4096) {
        int i0 = base + tid * 4;
        int v0 = (i0 + 0 < len) ? cnt[i0 + 0] : 0;
        int v1 = (i0 + 1 < len) ? cnt[i0 + 1] : 0;
        int v2 = (i0 + 2 < len) ? cnt[i0 + 2] : 0;
        int v3 = (i0 + 3 < len) ? cnt[i0 + 3] : 0;
        int t1 = v0 + v1, t2 = t1 + v2, t3 = t2 + v3;

        int inc = t3;
#pragma unroll
        for (int o = 1; o < 32; o <<= 1) {
            int u = __shfl_up_sync(0xffffffffu, inc, o);
            if (lane >= o) inc += u;
        }
        if (lane == 31) wsum[wid] = inc;
        __syncthreads();
        if (wid == 0) {
            int w = wsum[lane];
            int wi = w;
#pragma unroll
            for (int o = 1; o < 32; o <<= 1) {
                int u = __shfl_up_sync(0xffffffffu, wi, o);
                if (lane >= o) wi += u;
            }
            wsum[lane] = wi - w;
        }
        __syncthreads();
        int excl = s_carry + wsum[wid] + (inc - t3);
        if (i0 + 0 < len) { rowptr[i0 + 0] = excl;      cursor[i0 + 0] = excl; }
        if (i0 + 1 < len) { rowptr[i0 + 1] = excl + v0; cursor[i0 + 1] = excl + v0; }
        if (i0 + 2 < len) { rowptr[i0 + 2] = excl + t1; cursor[i0 + 2] = excl + t1; }
        if (i0 + 3 < len) { rowptr[i0 + 3] = excl + t2; cursor[i0 + 3] = excl + t2; }
        __syncthreads();
        if (tid == 1023) s_carry = s_carry + wsum[31] + inc;
        __syncthreads();
    }
    if (threadIdx.x == 0) rowptr[len] = s_carry;
}

__global__ void fill_lists_kernel(const int* __restrict__ V, const int* __restrict__ E,
                                  int* __restrict__ e_cursor, int* __restrict__ v_cursor,
                                  int* __restrict__ eV, int* __restrict__ vE, int nnz)
{
    int i = blockIdx.x * blockDim.x + threadIdx.x;
    if (i >= nnz) return;
    int v = V[i], e = E[i];
    int pe = atomicAdd(&e_cursor[e], 1);
    eV[pe] = v;
    int pv = atomicAdd(&v_cursor[v], 1);
    vE[pv] = e;
}

// ---------------------------------------------------------------------------
// fp16x2 tensor-core GEMM with cp.async double buffering, templated output.
// C[M,N] = [A1 | A2] @ (Wh + Wl) + bias; out fp32 or fp16.
// ---------------------------------------------------------------------------
struct GemmStage {
    __half A [128][40];
    __half Bh[32][136];
    __half Bl[32][136];
};
static constexpr int GEMM_SMEM = 2 * sizeof(GemmStage);   // 55296

template <bool HALF_OUT>
__global__ __launch_bounds__(256, 2)
void gemm_fp16x2(const __half* __restrict__ A1, int K1,
                 const __half* __restrict__ A2, int K2,
                 const __half* __restrict__ Bhg, const __half* __restrict__ Blg,
                 const float* __restrict__ bias,
                 float* __restrict__ Cf, __half* __restrict__ Ch,
                 int M, int N)
{
    extern __shared__ char smem_raw[];
    GemmStage* st = reinterpret_cast<GemmStage*>(smem_raw);

    const int tid  = threadIdx.x;
    const int wid  = tid >> 5, lane = tid & 31;
    const int wm   = wid >> 1, wn = wid & 1;
    const int row0 = blockIdx.y * 128;
    const int col0 = blockIdx.x * 128;
    const int K = K1 + K2, nch = K >> 5;

    wmma::fragment<wmma::accumulator, 16, 16, 16, float> acc[2][4];
#pragma unroll
    for (int mt = 0; mt < 2; mt++)
#pragma unroll
        for (int nt = 0; nt < 4; nt++) wmma::fill_fragment(acc[mt][nt], 0.f);

    auto prefetch = [&](int c, int s) {
        const int k0 = c * 32;
        const __half* a; int lda, col;
        if (k0 < K1) { a = A1; lda = K1; col = k0; }
        else         { a = A2; lda = K2; col = k0 - K1; }
#pragma unroll
        for (int t = 0; t < 2; t++) {
            int u = tid + t * 256, r = u >> 2, q = u & 3;
            int gr = row0 + r;
            int sz = (gr < M) ? 16 : 0;
            size_t off = (size_t)(gr < M ? gr : 0) * lda + col + q * 8;
            cp_async16(smem_to_u32(&st[s].A[r][q * 8]), a + off, sz);
        }
#pragma unroll
        for (int t = 0; t < 2; t++) {
            int u = tid + t * 256, r = u >> 4, q = u & 15;
            size_t off = (size_t)(k0 + r) * N + col0 + q * 8;
            cp_async16(smem_to_u32(&st[s].Bh[r][q * 8]), Bhg + off, 16);
            cp_async16(smem_to_u32(&st[s].Bl[r][q * 8]), Blg + off, 16);
        }
    };

    prefetch(0, 0);
    CP_COMMIT();

    for (int c = 0; c < nch; c++) {
        const int s = c & 1;
        if (c + 1 < nch) {
            prefetch(c + 1, s ^ 1);
            CP_COMMIT();
            CP_WAIT(1);
        } else {
            CP_WAIT(0);
        }
        __syncthreads();

#pragma unroll
        for (int ks = 0; ks < 2; ks++) {
            wmma::fragment<wmma::matrix_a, 16, 16, 16, __half, wmma::row_major> af[2];
#pragma unroll
            for (int mt = 0; mt < 2; mt++)
                wmma::load_matrix_sync(af[mt], &st[s].A[wm * 32 + mt * 16][ks * 16], 40);
#pragma unroll
            for (int nt = 0; nt < 4; nt++) {
                wmma::fragment<wmma::matrix_b, 16, 16, 16, __half, wmma::row_major> bh, bl;
                wmma::load_matrix_sync(bh, &st[s].Bh[ks * 16][wn * 64 + nt * 16], 136);
                wmma::load_matrix_sync(bl, &st[s].Bl[ks * 16][wn * 64 + nt * 16], 136);
#pragma unroll
                for (int mt = 0; mt < 2; mt++) {
                    wmma::mma_sync(acc[mt][nt], af[mt], bh, acc[mt][nt]);
                    wmma::mma_sync(acc[mt][nt], af[mt], bl, acc[mt][nt]);
                }
            }
        }
        __syncthreads();
    }

    // epilogue: stage each 16x16 tile in smem, add bias, store fp32 or fp16
    float* stg = reinterpret_cast<float*>(smem_raw) + wid * 320;
#pragma unroll
    for (int mt = 0; mt < 2; mt++) {
#pragma unroll
        for (int nt = 0; nt < 4; nt++) {
            wmma::store_matrix_sync(stg, acc[mt][nt], 20, wmma::mem_row_major);
            __syncwarp();
            int r = lane >> 1, cofs = (lane & 1) * 8;
            int gr = row0 + wm * 32 + mt * 16 + r;
            int gc = col0 + wn * 64 + nt * 16 + cofs;
            if (gr < M) {
                float o[8];
#pragma unroll
                for (int j = 0; j < 8; j++) o[j] = stg[r * 20 + cofs + j] + bias[gc + j];
                if (HALF_OUT) {
                    uint4 u;
                    __half2 p0 = __floats2half2_rn(o[0], o[1]);
                    __half2 p1 = __floats2half2_rn(o[2], o[3]);
                    __half2 p2 = __floats2half2_rn(o[4], o[5]);
                    __half2 p3 = __floats2half2_rn(o[6], o[7]);
                    u.x = *reinterpret_cast<unsigned*>(&p0);
                    u.y = *reinterpret_cast<unsigned*>(&p1);
                    u.z = *reinterpret_cast<unsigned*>(&p2);
                    u.w = *reinterpret_cast<unsigned*>(&p3);
                    *reinterpret_cast<uint4*>(Ch + (size_t)gr * N + gc) = u;
                } else {
                    *reinterpret_cast<float4*>(Cf + (size_t)gr * N + gc)     = make_float4(o[0], o[1], o[2], o[3]);
                    *reinterpret_cast<float4*>(Cf + (size_t)gr * N + gc + 4) = make_float4(o[4], o[5], o[6], o[7]);
                }
            }
            __syncwarp();
        }
    }
}

// ---------------------------------------------------------------------------
// score[n] = dot(Xfeat[n,:], a)   (Xfeat fp16)
// ---------------------------------------------------------------------------
__global__ void score_kernel(const __half* __restrict__ Xfeat, const float* __restrict__ a,
                             float* __restrict__ score, int N, int H)
{
    int warp = (blockIdx.x * blockDim.x + threadIdx.x) >> 5;
    int lane = threadIdx.x & 31;
    if (warp >= N) return;
    const uint4* row = reinterpret_cast<const uint4*>(Xfeat + (size_t)warp * H);
    float s = 0.f;
    for (int c = lane; c < H / 8; c += 32) {
        uint4 u = __ldg(&row[c]);
        const __half2* h = reinterpret_cast<const __half2*>(&u);
        const float4* av = reinterpret_cast<const float4*>(a + c * 8);
        float4 a0 = __ldg(&av[0]), a1 = __ldg(&av[1]);
        float2 f0 = __half22float2(h[0]), f1 = __half22float2(h[1]);
        float2 f2 = __half22float2(h[2]), f3 = __half22float2(h[3]);
        s += f0.x * a0.x + f0.y * a0.y + f1.x * a0.z + f1.y * a0.w;
        s += f2.x * a1.x + f2.y * a1.y + f3.x * a1.z + f3.y * a1.w;
    }
#pragma unroll
    for (int o = 16; o > 0; o >>= 1) s += __shfl_xor_sync(0xffffffffu, s, o);
    if (lane == 0) score[warp] = s;
}

// ---------------------------------------------------------------------------
// Fused v2e: segment softmax + weighted fp16 gather + elu -> fp16 out
// H == 256: one uint4 (8 halves) per lane.
// ---------------------------------------------------------------------------
__global__ __launch_bounds__(256)
void v2e_softmax_kernel(const __half* __restrict__ Xfeat, const float* __restrict__ score,
                        const int* __restrict__ e_rowptr, const int* __restrict__ eV,
                        __half* __restrict__ Ye, int M, int H)
{
    int warp = (blockIdx.x * blockDim.x + threadIdx.x) >> 5;
    int lane = threadIdx.x & 31;
    if (warp >= M) return;
    const int beg = e_rowptr[warp];
    const int end = e_rowptr[warp + 1];

    float m = -1e30f;
    for (int j = beg + lane; j < end; j += 32)
        m = fmaxf(m, leakyf(__ldg(&score[eV[j]])));
#pragma unroll
    for (int o = 16; o > 0; o >>= 1) m = fmaxf(m, __shfl_xor_sync(0xffffffffu, m, o));

    float den = 0.f;
    for (int j = beg + lane; j < end; j += 32)
        den += expf(leakyf(__ldg(&score[eV[j]])) - m);
#pragma unroll
    for (int o = 16; o > 0; o >>= 1) den += __shfl_xor_sync(0xffffffffu, den, o);
    float invden = (end > beg) ? 1.f / den : 0.f;

    float acc[8];
#pragma unroll
    for (int k = 0; k < 8; k++) acc[k] = 0.f;

    for (int j = beg; j < end; j++) {
        int v = eV[j];
        float w = expf(leakyf(__ldg(&score[v])) - m) * invden;
        uint4 u = __ldg(reinterpret_cast<const uint4*>(Xfeat + (size_t)v * H) + lane);
        const __half2* h = reinterpret_cast<const __half2*>(&u);
#pragma unroll
        for (int k = 0; k < 4; k++) {
            float2 f = __half22float2(h[k]);
            acc[2 * k + 0] = fmaf(f.x, w, acc[2 * k + 0]);
            acc[2 * k + 1] = fmaf(f.y, w, acc[2 * k + 1]);
        }
    }

    uint4 u;
    __half2 p0 = __floats2half2_rn(eluf(acc[0]), eluf(acc[1]));
    __half2 p1 = __floats2half2_rn(eluf(acc[2]), eluf(acc[3]));
    __half2 p2 = __floats2half2_rn(eluf(acc[4]), eluf(acc[5]));
    __half2 p3 = __floats2half2_rn(eluf(acc[6]), eluf(acc[7]));
    u.x = *reinterpret_cast<unsigned*>(&p0);
    u.y = *reinterpret_cast<unsigned*>(&p1);
    u.z = *reinterpret_cast<unsigned*>(&p2);
    u.w = *reinterpret_cast<unsigned*>(&p3);
    *(reinterpret_cast<uint4*>(Ye + (size_t)warp * H) + lane) = u;
}

// ---------------------------------------------------------------------------
// Fused e2v: mean (fp16 gather) + elu + residual (fp32) -> fp16 out
// ---------------------------------------------------------------------------
__global__ __launch_bounds__(256)
void e2v_mean_kernel(const __half* __restrict__ Ye2,
                     const int* __restrict__ v_rowptr, const int* __restrict__ vE,
                     const float* __restrict__ Xinit,
                     __half* __restrict__ hout, int N, int H)
{
    int warp = (blockIdx.x * blockDim.x + threadIdx.x) >> 5;
    int lane = threadIdx.x & 31;
    if (warp >= N) return;
    const int beg = v_rowptr[warp];
    const int end = v_rowptr[warp + 1];

    float acc[8];
#pragma unroll
    for (int k = 0; k < 8; k++) acc[k] = 0.f;

    for (int j = beg; j < end; j++) {
        int e = vE[j];
        uint4 u = __ldg(reinterpret_cast<const uint4*>(Ye2 + (size_t)e * H) + lane);
        const __half2* h = reinterpret_cast<const __half2*>(&u);
#pragma unroll
        for (int k = 0; k < 4; k++) {
            float2 f = __half22float2(h[k]);
            acc[2 * k + 0] += f.x;
            acc[2 * k + 1] += f.y;
        }
    }
    float inv = (end > beg) ? 1.f / (float)(end - beg) : 0.f;

    const float4* xi = reinterpret_cast<const float4*>(Xinit + (size_t)warp * H) + lane * 2;
    float4 r0 = __ldg(&xi[0]), r1 = __ldg(&xi[1]);
    float o[8];
    o[0] = eluf(acc[0] * inv) + r0.x; o[1] = eluf(acc[1] * inv) + r0.y;
    o[2] = eluf(acc[2] * inv) + r0.z; o[3] = eluf(acc[3] * inv) + r0.w;
    o[4] = eluf(acc[4] * inv) + r1.x; o[5] = eluf(acc[5] * inv) + r1.y;
    o[6] = eluf(acc[6] * inv) + r1.z; o[7] = eluf(acc[7] * inv) + r1.w;

    uint4 u;
    __half2 p0 = __floats2half2_rn(o[0], o[1]);
    __half2 p1 = __floats2half2_rn(o[2], o[3]);
    __half2 p2 = __floats2half2_rn(o[4], o[5]);
    __half2 p3 = __floats2half2_rn(o[6], o[7]);
    u.x = *reinterpret_cast<unsigned*>(&p0);
    u.y = *reinterpret_cast<unsigned*>(&p1);
    u.z = *reinterpret_cast<unsigned*>(&p2);
    u.w = *reinterpret_cast<unsigned*>(&p3);
    *(reinterpret_cast<uint4*>(hout + (size_t)warp * H) + lane) = u;
}

// ---------------------------------------------------------------------------
// Hyperconv edge: fp16 gather, fp16 out.  O == 128: uint2 (4 halves) per lane.
// ---------------------------------------------------------------------------
__global__ __launch_bounds__(256)
void hyper_edge_kernel(const __half* __restrict__ Xn,
                       const int* __restrict__ e_rowptr, const int* __restrict__ eV,
                       const int* __restrict__ v_rowptr,
                       __half* __restrict__ Ye, int M, int O)
{
    int warp = (blockIdx.x * blockDim.x + threadIdx.x) >> 5;
    int lane = threadIdx.x & 31;
    if (warp >= M) return;
    const int beg = e_rowptr[warp];
    const int end = e_rowptr[warp + 1];
    const int cnt = end - beg;

    float sumDv = 0.f;
    for (int j = beg + lane; j < end; j += 32) {
        int v = eV[j];
        sumDv += (float)(__ldg(&v_rowptr[v + 1]) - __ldg(&v_rowptr[v]));
    }
#pragma unroll
    for (int o = 16; o > 0; o >>= 1) sumDv += __shfl_xor_sync(0xffffffffu, sumDv, o);

    float acc[4];
#pragma unroll
    for (int k = 0; k < 4; k++) acc[k] = 0.f;

    for (int j = beg; j < end; j++) {
        int v = eV[j];
        uint2 u = __ldg(reinterpret_cast<const uint2*>(Xn + (size_t)v * O) + lane);
        const __half2* h = reinterpret_cast<const __half2*>(&u);
        float2 f0 = __half22float2(h[0]), f1 = __half22float2(h[1]);
        acc[0] += f0.x; acc[1] += f0.y; acc[2] += f1.x; acc[3] += f1.y;
    }

    float invc = (cnt > 0) ? 1.f / (float)cnt : 0.f;
    float De = sumDv / ((float)cnt + 1.f);
    float dinv = (De > 0.f) ? rsqrtf(De) : 1.f;
    float s = invc * dinv;

    uint2 u;
    __half2 p0 = __floats2half2_rn(acc[0] * s, acc[1] * s);
    __half2 p1 = __floats2half2_rn(acc[2] * s, acc[3] * s);
    u.x = *reinterpret_cast<unsigned*>(&p0);
    u.y = *reinterpret_cast<unsigned*>(&p1);
    *(reinterpret_cast<uint2*>(Ye + (size_t)warp * O) + lane) = u;
}

// ---------------------------------------------------------------------------
// Hyperconv node: fp16 gather, fp32 out (final output)
// ---------------------------------------------------------------------------
__global__ __launch_bounds__(256)
void hyper_node_kernel(const __half* __restrict__ Ye,
                       const int* __restrict__ v_rowptr, const int* __restrict__ vE,
                       float* __restrict__ out, int N, int O)
{
    int warp = (blockIdx.x * blockDim.x + threadIdx.x) >> 5;
    int lane = threadIdx.x & 31;
    if (warp >= N) return;
    const int beg = v_rowptr[warp];
    const int end = v_rowptr[warp + 1];
    const int deg = end - beg;

    float acc[4];
#pragma unroll
    for (int k = 0; k < 4; k++) acc[k] = 0.f;

    for (int j = beg; j < end; j++) {
        int e = vE[j];
        uint2 u = __ldg(reinterpret_cast<const uint2*>(Ye + (size_t)e * O) + lane);
        const __half2* h = reinterpret_cast<const __half2*>(&u);
        float2 f0 = __half22float2(h[0]), f1 = __half22float2(h[1]);
        acc[0] += f0.x; acc[1] += f0.y; acc[2] += f1.x; acc[3] += f1.y;
    }
    float dinv = (deg > 0) ? rsqrtf((float)deg) : 0.f;

    float4 o;
    o.x = acc[0] * dinv; o.y = acc[1] * dinv;
    o.z = acc[2] * dinv; o.w = acc[3] * dinv;
    *(reinterpret_cast<float4*>(out + (size_t)warp * O) + lane) = o;
}

// ---------------------------------------------------------------------------
// Host
// ---------------------------------------------------------------------------
static inline int ceil_div(int a, int b) { return (a + b - 1) / b; }

extern "C" void kernel_launch(void* const* d_in, const int* in_sizes, int n_in,
                              void* d_out, int out_size)
{
    const float* X   = (const float*)d_in[0];
    const int*   V   = (const int*)  d_in[1];
    const int*   E   = (const int*)  d_in[2];
    const float* S   = (const float*)d_in[3];
    const float* Wx0 = (const float*)d_in[4];
    const float* bx0 = (const float*)d_in[5];
    const float* Wv0 = (const float*)d_in[6];
    const float* bv0 = (const float*)d_in[7];
    const float* a0  = (const float*)d_in[8];
    const float* Wt0 = (const float*)d_in[9];
    const float* bt0 = (const float*)d_in[10];
    const float* Wx1 = (const float*)d_in[11];
    const float* bx1 = (const float*)d_in[12];
    const float* Wv1 = (const float*)d_in[13];
    const float* bv1 = (const float*)d_in[14];
    const float* a1  = (const float*)d_in[15];
    const float* Wt1 = (const float*)d_in[16];
    const float* bt1 = (const float*)d_in[17];
    const float* Wf  = (const float*)d_in[18];
    const float* bf  = (const float*)d_in[19];

    const int H    = in_sizes[5];              // 256
    const int IN   = in_sizes[4] / H;          // 128
    const int N    = in_sizes[0] / IN;         // 50000
    const int NNZ  = in_sizes[1];              // 400000
    const int HS   = in_sizes[9] / H;          // 320
    const int STAR = HS - H;                   // 64
    const int M    = in_sizes[3] / STAR;       // 20000
    const int OUT  = in_sizes[19];             // 128

    void* p;
    cudaGetSymbolAddress(&p, g_Xinit); float* Xinit = (float*)p;
    cudaGetSymbolAddress(&p, g_score); float* score = (float*)p;
    cudaGetSymbolAddress(&p, g_Xfeat); __half* Xfeat = (__half*)p;
    cudaGetSymbolAddress(&p, g_Ye2);   __half* Ye2   = (__half*)p;
    cudaGetSymbolAddress(&p, g_A);  __half* Abuf = (__half*)p;
    cudaGetSymbolAddress(&p, g_B);  __half* Bbuf = (__half*)p;
    cudaGetSymbolAddress(&p, g_Ye); __half* Yeh  = (__half*)p;
    cudaGetSymbolAddress(&p, g_S);  __half* Sh   = (__half*)p;
    cudaGetSymbolAddress(&p, g_Wh); __half* Wh   = (__half*)p;
    cudaGetSymbolAddress(&p, g_Wl); __half* Wl   = (__half*)p;
    cudaGetSymbolAddress(&p, g_e_rowptr); int* e_rowptr = (int*)p;
    cudaGetSymbolAddress(&p, g_v_rowptr); int* v_rowptr = (int*)p;
    cudaGetSymbolAddress(&p, g_e_cursor); int* e_cursor = (int*)p;
    cudaGetSymbolAddress(&p, g_v_cursor); int* v_cursor = (int*)p;
    cudaGetSymbolAddress(&p, g_cntE);     int* cntE     = (int*)p;
    cudaGetSymbolAddress(&p, g_cntV);     int* cntV     = (int*)p;
    cudaGetSymbolAddress(&p, g_eV);       int* eV       = (int*)p;
    cudaGetSymbolAddress(&p, g_vE);       int* vE       = (int*)p;

    // one-time init (first call = correctness run, NOT under graph capture)
    static bool inited = false;
    static cudaStream_t s1 = 0, s2 = 0;
    static cudaEvent_t evFork, eW01, eWall, eCsr, eG1a, eX0, eG1b, eX1;
    if (!inited) {
        cudaFuncSetAttribute(gemm_fp16x2<false>, cudaFuncAttributeMaxDynamicSharedMemorySize, GEMM_SMEM);
        cudaFuncSetAttribute(gemm_fp16x2<true>,  cudaFuncAttributeMaxDynamicSharedMemorySize, GEMM_SMEM);
        if (cudaStreamCreateWithFlags(&s1, cudaStreamNonBlocking) != cudaSuccess) s1 = 0;
        if (cudaStreamCreateWithFlags(&s2, cudaStreamNonBlocking) != cudaSuccess) s2 = 0;
        cudaEventCreateWithFlags(&evFork, cudaEventDisableTiming);
        cudaEventCreateWithFlags(&eW01,  cudaEventDisableTiming);
        cudaEventCreateWithFlags(&eWall, cudaEventDisableTiming);
        cudaEventCreateWithFlags(&eCsr,  cudaEventDisableTiming);
        cudaEventCreateWithFlags(&eG1a,  cudaEventDisableTiming);
        cudaEventCreateWithFlags(&eX0,   cudaEventDisableTiming);
        cudaEventCreateWithFlags(&eG1b,  cudaEventDisableTiming);
        cudaEventCreateWithFlags(&eX1,   cudaEventDisableTiming);
        inited = true;
    }

    // weight offsets ([K,N] row-major, packed)
    const size_t o_wx0 = 0;
    const size_t o_wv0 = o_wx0 + (size_t)IN * H;
    const size_t o_wt0 = o_wv0 + (size_t)IN * H;
    const size_t o_wx1 = o_wt0 + (size_t)HS * H;
    const size_t o_wv1 = o_wx1 + (size_t)H * H;
    const size_t o_wt1 = o_wv1 + (size_t)H * H;
    const size_t o_wf  = o_wt1 + (size_t)HS * H;

    auto splitw = [&](const float* src, __half* dh, __half* dl, long nelem, cudaStream_t st) {
        long n4 = nelem / 4;
        int blocks = (int)((n4 + 255) / 256); if (blocks > 2048) blocks = 2048;
        splitw_kernel<<<blocks, 256, 0, st>>>(src, dh, dl, n4);
    };
    auto tohalf = [&](const float* src, __half* dst, long nelem, cudaStream_t st) {
        long n4 = nelem / 4;
        int blocks = (int)((n4 + 255) / 256); if (blocks > 2048) blocks = 2048;
        tohalf_kernel<<<blocks, 256, 0, st>>>(src, dst, n4);
    };

    auto gemmF = [&](const __half* a1, int K1, const __half* a2, int K2,
                     size_t woff, const float* bias, float* C, int Mrows, int Ncols,
                     cudaStream_t st) {
        dim3 grid(Ncols / 128, ceil_div(Mrows, 128));
        gemm_fp16x2<false><<<grid, 256, GEMM_SMEM, st>>>(a1, K1, a2, K2,
            Wh + woff, Wl + woff, bias, C, nullptr, Mrows, Ncols);
    };
    auto gemmH = [&](const __half* a1, int K1, const __half* a2, int K2,
                     size_t woff, const float* bias, __half* C, int Mrows, int Ncols,
                     cudaStream_t st) {
        dim3 grid(Ncols / 128, ceil_div(Mrows, 128));
        gemm_fp16x2<true><<<grid, 256, GEMM_SMEM, st>>>(a1, K1, a2, K2,
            Wh + woff, Wl + woff, bias, nullptr, C, Mrows, Ncols);
    };

    const int nnzBlocks      = ceil_div(NNZ, 256);
    const int edgeWarpBlocks = ceil_div(M, 8);
    const int nodeWarpBlocks = ceil_div(N, 8);

    // ---- fork ----
    cudaEventRecord(evFork, 0);
    cudaStreamWaitEvent(s1, evFork, 0);
    cudaStreamWaitEvent(s2, evFork, 0);

    // ---- s2: weight splits + S conversion ----
    splitw(Wv0, Wh + o_wv0, Wl + o_wv0, (long)IN * H, s2);
    splitw(Wx0, Wh + o_wx0, Wl + o_wx0, (long)IN * H, s2);
    cudaEventRecord(eW01, s2);
    splitw(Wt0, Wh + o_wt0, Wl + o_wt0, (long)HS * H, s2);
    splitw(Wx1, Wh + o_wx1, Wl + o_wx1, (long)H * H,  s2);
    splitw(Wv1, Wh + o_wv1, Wl + o_wv1, (long)H * H,  s2);
    splitw(Wt1, Wh + o_wt1, Wl + o_wt1, (long)HS * H, s2);
    splitw(Wf,  Wh + o_wf,  Wl + o_wf,  (long)H * OUT, s2);
    tohalf(S, Sh, (long)M * STAR, s2);
    cudaEventRecord(eWall, s2);

    // ---- s1: CSR build ----
    fill_int<<<ceil_div(M, 256), 256, 0, s1>>>(cntE, 0, M);
    fill_int<<<ceil_div(N, 256), 256, 0, s1>>>(cntV, 0, N);
    count_kernel<<<nnzBlocks, 256, 0, s1>>>(V, E, cntV, cntE, NNZ);
    scan_kernel<<<1, 1024, 0, s1>>>(cntE, e_rowptr, e_cursor, M);
    scan_kernel<<<1, 1024, 0, s1>>>(cntV, v_rowptr, v_cursor, N);
    fill_lists_kernel<<<nnzBlocks, 256, 0, s1>>>(V, E, e_cursor, v_cursor, eV, vE, NNZ);
    cudaEventRecord(eCsr, s1);

    // ---- s0: convert X, then layer 0 ----
    tohalf(X, Abuf, (long)N * IN, 0);
    cudaStreamWaitEvent(0, eW01, 0);
    gemmH(Abuf, IN, nullptr, 0, o_wv0, bv0, Xfeat, N, H, 0);
    cudaEventRecord(eG1a, 0);

    // s1: Xinit GEMM overlapped with score/v2e/Wt-GEMM
    cudaStreamWaitEvent(s1, eG1a, 0);
    gemmF(Abuf, IN, nullptr, 0, o_wx0, bx0, Xinit, N, H, s1);
    cudaEventRecord(eX0, s1);

    score_kernel<<<ceil_div(N, 8), 256>>>(Xfeat, a0, score, N, H);
    cudaStreamWaitEvent(0, eCsr, 0);
    cudaStreamWaitEvent(0, eWall, 0);
    v2e_softmax_kernel<<<edgeWarpBlocks, 256>>>(Xfeat, score, e_rowptr, eV, Yeh, M, H);
    gemmH(Yeh, H, Sh, STAR, o_wt0, bt0, Ye2, M, H, 0);
    cudaStreamWaitEvent(0, eX0, 0);
    e2v_mean_kernel<<<nodeWarpBlocks, 256>>>(Ye2, v_rowptr, vE, Xinit, Bbuf, N, H);

    // ---- layer 1 ----
    gemmH(Bbuf, H, nullptr, 0, o_wv1, bv1, Xfeat, N, H, 0);
    cudaEventRecord(eG1b, 0);

    cudaStreamWaitEvent(s1, eG1b, 0);
    gemmF(Bbuf, H, nullptr, 0, o_wx1, bx1, Xinit, N, H, s1);
    cudaEventRecord(eX1, s1);

    score_kernel<<<ceil_div(N, 8), 256>>>(Xfeat, a1, score, N, H);
    v2e_softmax_kernel<<<edgeWarpBlocks, 256>>>(Xfeat, score, e_rowptr, eV, Yeh, M, H);
    gemmH(Yeh, H, Sh, STAR, o_wt1, bt1, Ye2, M, H, 0);
    cudaStreamWaitEvent(0, eX1, 0);
    e2v_mean_kernel<<<nodeWarpBlocks, 256>>>(Ye2, v_rowptr, vE, Xinit, Abuf, N, H);

    // ---- hyperconv (s0) ----
    gemmH(Abuf, H, nullptr, 0, o_wf, bf, Xfeat, N, OUT, 0);
    hyper_edge_kernel<<<edgeWarpBlocks, 256>>>(Xfeat, e_rowptr, eV, v_rowptr, Yeh, M, OUT);
    hyper_node_kernel<<<nodeWarpBlocks, 256>>>(Yeh, v_rowptr, vE, (float*)d_out, N, OUT);
}

// round 9
// speedup vs baseline: 5.0956x; 1.0368x over previous
#include <cuda_runtime.h>
#include <cuda_fp16.h>
#include <mma.h>
#include <math.h>
#include <stdint.h>

using namespace nvcuda;

// ---------------------------------------------------------------------------
// Problem max sizes
// ---------------------------------------------------------------------------
#define NMAX   50000
#define MMAX   20000
#define NNZMAX 400000
#define HMAX   256
#define WTOTAL 393216

// ---------------------------------------------------------------------------
// Scratch (device globals)
// ---------------------------------------------------------------------------
__device__ float g_Xinit[NMAX * HMAX];
__device__ float g_score[NMAX];

__device__ __half g_Xfeat[NMAX * HMAX];  // fp16 GEMM outputs (Wv / Wf)
__device__ __half g_Ye2  [MMAX * HMAX];  // fp16 GEMM output (Wt)
__device__ __half g_A [NMAX * HMAX];     // activations (X / h2)
__device__ __half g_B [NMAX * HMAX];     // h1
__device__ __half g_Ye[MMAX * HMAX];     // v2e out / hyper_edge out
__device__ __half g_S [MMAX * 64];
__device__ __half g_Wh[WTOTAL];          // weight hi, [K,N] row-major packed
__device__ __half g_Wl[WTOTAL];          // weight lo

// CSR structures
__device__ int g_e_rowptr[MMAX + 1];
__device__ int g_v_rowptr[NMAX + 1];
__device__ int g_e_cursor[MMAX];
__device__ int g_v_cursor[NMAX];
__device__ int g_cntE[MMAX];
__device__ int g_cntV[NMAX];
__device__ int g_eV[NNZMAX];
__device__ int g_vE[NNZMAX];

// ---------------------------------------------------------------------------
// Helpers
// ---------------------------------------------------------------------------
__device__ __forceinline__ float eluf(float x)  { return x > 0.f ? x : expm1f(x); }
__device__ __forceinline__ float leakyf(float x){ return x > 0.f ? x : 0.2f * x; }

__device__ __forceinline__ uint32_t smem_to_u32(const void* p) {
    uint32_t a;
    asm("{ .reg .u64 t; cvta.to.shared.u64 t, %1; cvt.u32.u64 %0, t; }" : "=r"(a) : "l"(p));
    return a;
}
__device__ __forceinline__ void cp_async16(uint32_t dst, const void* src, int sz) {
    asm volatile("cp.async.cg.shared.global [%0], [%1], 16, %2;"
                 :: "r"(dst), "l"(src), "r"(sz) : "memory");
}
#define CP_COMMIT() asm volatile("cp.async.commit_group;" ::: "memory")
#define CP_WAIT(n)  asm volatile("cp.async.wait_group %0;" :: "n"(n) : "memory")

// activations: fp32 -> single fp16
__global__ void tohalf_kernel(const float* __restrict__ x, __half* __restrict__ out, long n4)
{
    long i = (long)blockIdx.x * blockDim.x + threadIdx.x;
    long stride = (long)gridDim.x * blockDim.x;
    for (; i < n4; i += stride) {
        float4 v = reinterpret_cast<const float4*>(x)[i];
        __half2 h0 = __floats2half2_rn(v.x, v.y);
        __half2 h1 = __floats2half2_rn(v.z, v.w);
        uint2 u;
        u.x = *reinterpret_cast<unsigned*>(&h0);
        u.y = *reinterpret_cast<unsigned*>(&h1);
        *reinterpret_cast<uint2*>(out + 4 * i) = u;
    }
}

// weights: fp32 -> fp16 hi + fp16 lo
__global__ void splitw_kernel(const float* __restrict__ w, __half* __restrict__ hi,
                              __half* __restrict__ lo, long n4)
{
    long i = (long)blockIdx.x * blockDim.x + threadIdx.x;
    long stride = (long)gridDim.x * blockDim.x;
    for (; i < n4; i += stride) {
        float4 v = reinterpret_cast<const float4*>(w)[i];
        __half h0 = __float2half_rn(v.x), h1 = __float2half_rn(v.y);
        __half h2 = __float2half_rn(v.z), h3 = __float2half_rn(v.w);
        __half l0 = __float2half_rn(v.x - __half2float(h0));
        __half l1 = __float2half_rn(v.y - __half2float(h1));
        __half l2 = __float2half_rn(v.z - __half2float(h2));
        __half l3 = __float2half_rn(v.w - __half2float(h3));
        __half2 ph0 = __halves2half2(h0, h1), ph1 = __halves2half2(h2, h3);
        __half2 pl0 = __halves2half2(l0, l1), pl1 = __halves2half2(l2, l3);
        uint2 uh, ul;
        uh.x = *reinterpret_cast<unsigned*>(&ph0); uh.y = *reinterpret_cast<unsigned*>(&ph1);
        ul.x = *reinterpret_cast<unsigned*>(&pl0); ul.y = *reinterpret_cast<unsigned*>(&pl1);
        *reinterpret_cast<uint2*>(hi + 4 * i) = uh;
        *reinterpret_cast<uint2*>(lo + 4 * i) = ul;
    }
}

__global__ void fill_int(int* __restrict__ p, int v, int n) {
    int i = blockIdx.x * blockDim.x + threadIdx.x;
    int stride = gridDim.x * blockDim.x;
    for (; i < n; i += stride) p[i] = v;
}
__global__ void fill_float(float* __restrict__ p, float v, int n) {
    int i = blockIdx.x * blockDim.x + threadIdx.x;
    int stride = gridDim.x * blockDim.x;
    for (; i < n; i += stride) p[i] = v;
}

// ---------------------------------------------------------------------------
// CSR construction
// ---------------------------------------------------------------------------
__global__ void count_kernel(const int* __restrict__ V, const int* __restrict__ E,
                             int* __restrict__ cntV, int* __restrict__ cntE, int nnz)
{
    int i = blockIdx.x * blockDim.x + threadIdx.x;
    if (i >= nnz) return;
    atomicAdd(&cntE[E[i]], 1);
    atomicAdd(&cntV[V[i]], 1);
}

__global__ __launch_bounds__(1024)
void scan_kernel(const int* __restrict__ cnt, int* __restrict__ rowptr,
                 int* __restrict__ cursor, int len)
{
    __shared__ int wsum[32];
    __shared__ int s_carry;
    const int tid = threadIdx.x, lane = tid & 31, wid = tid >> 5;
    if (tid == 0) s_carry = 0;
    __syncthreads();

    for (int base = 0; base < len; base += 4096) {
        int i0 = base + tid * 4;
        int v0 = (i0 + 0 < len) ? cnt[i0 + 0] : 0;
        int v1 = (i0 + 1 < len) ? cnt[i0 + 1] : 0;
        int v2 = (i0 + 2 < len) ? cnt[i0 + 2] : 0;
        int v3 = (i0 + 3 < len) ? cnt[i0 + 3] : 0;
        int t1 = v0 + v1, t2 = t1 + v2, t3 = t2 + v3;

        int inc = t3;
#pragma unroll
        for (int o = 1; o < 32; o <<= 1) {
            int u = __shfl_up_sync(0xffffffffu, inc, o);
            if (lane >= o) inc += u;
        }
        if (lane == 31) wsum[wid] = inc;
        __syncthreads();
        if (wid == 0) {
            int w = wsum[lane];
            int wi = w;
#pragma unroll
            for (int o = 1; o < 32; o <<= 1) {
                int u = __shfl_up_sync(0xffffffffu, wi, o);
                if (lane >= o) wi += u;
            }
            wsum[lane] = wi - w;
        }
        __syncthreads();
        int excl = s_carry + wsum[wid] + (inc - t3);
        if (i0 + 0 < len) { rowptr[i0 + 0] = excl;      cursor[i0 + 0] = excl; }
        if (i0 + 1 < len) { rowptr[i0 + 1] = excl + v0; cursor[i0 + 1] = excl + v0; }
        if (i0 + 2 < len) { rowptr[i0 + 2] = excl + t1; cursor[i0 + 2] = excl + t1; }
        if (i0 + 3 < len) { rowptr[i0 + 3] = excl + t2; cursor[i0 + 3] = excl + t2; }
        __syncthreads();
        if (tid == 1023) s_carry = s_carry + wsum[31] + inc;
        __syncthreads();
    }
    if (threadIdx.x == 0) rowptr[len] = s_carry;
}

__global__ void fill_lists_kernel(const int* __restrict__ V, const int* __restrict__ E,
                                  int* __restrict__ e_cursor, int* __restrict__ v_cursor,
                                  int* __restrict__ eV, int* __restrict__ vE, int nnz)
{
    int i = blockIdx.x * blockDim.x + threadIdx.x;
    if (i >= nnz) return;
    int v = V[i], e = E[i];
    int pe = atomicAdd(&e_cursor[e], 1);
    eV[pe] = v;
    int pv = atomicAdd(&v_cursor[v], 1);
    vE[pv] = e;
}

// ---------------------------------------------------------------------------
// fp16 tensor-core GEMM, cp.async double buffered.
// C[M,N] = [A1|A2] @ (Wh [+ Wl]) + bias; out fp32 or fp16.
// Optional fused row-score: score[r] += dot(C_row, avec) (fp32, atomic).
// ---------------------------------------------------------------------------
struct GemmStage {
    __half A [128][40];
    __half Bh[32][136];
    __half Bl[32][136];
};
static constexpr int GEMM_SMEM = 2 * sizeof(GemmStage);   // 55296

template <bool HALF_OUT, bool TWOB>
__global__ __launch_bounds__(256, 2)
void gemm_fp16(const __half* __restrict__ A1, int K1,
               const __half* __restrict__ A2, int K2,
               const __half* __restrict__ Bhg, const __half* __restrict__ Blg,
               const float* __restrict__ bias,
               float* __restrict__ Cf, __half* __restrict__ Ch,
               const float* __restrict__ avec, float* __restrict__ score_out,
               int M, int N)
{
    extern __shared__ char smem_raw[];
    GemmStage* st = reinterpret_cast<GemmStage*>(smem_raw);

    const int tid  = threadIdx.x;
    const int wid  = tid >> 5, lane = tid & 31;
    const int wm   = wid >> 1, wn = wid & 1;
    const int row0 = blockIdx.y * 128;
    const int col0 = blockIdx.x * 128;
    const int K = K1 + K2, nch = K >> 5;

    wmma::fragment<wmma::accumulator, 16, 16, 16, float> acc[2][4];
#pragma unroll
    for (int mt = 0; mt < 2; mt++)
#pragma unroll
        for (int nt = 0; nt < 4; nt++) wmma::fill_fragment(acc[mt][nt], 0.f);

    auto prefetch = [&](int c, int s) {
        const int k0 = c * 32;
        const __half* a; int lda, col;
        if (k0 < K1) { a = A1; lda = K1; col = k0; }
        else         { a = A2; lda = K2; col = k0 - K1; }
#pragma unroll
        for (int t = 0; t < 2; t++) {
            int u = tid + t * 256, r = u >> 2, q = u & 3;
            int gr = row0 + r;
            int sz = (gr < M) ? 16 : 0;
            size_t off = (size_t)(gr < M ? gr : 0) * lda + col + q * 8;
            cp_async16(smem_to_u32(&st[s].A[r][q * 8]), a + off, sz);
        }
#pragma unroll
        for (int t = 0; t < 2; t++) {
            int u = tid + t * 256, r = u >> 4, q = u & 15;
            size_t off = (size_t)(k0 + r) * N + col0 + q * 8;
            cp_async16(smem_to_u32(&st[s].Bh[r][q * 8]), Bhg + off, 16);
            if (TWOB)
                cp_async16(smem_to_u32(&st[s].Bl[r][q * 8]), Blg + off, 16);
        }
    };

    prefetch(0, 0);
    CP_COMMIT();

    for (int c = 0; c < nch; c++) {
        const int s = c & 1;
        if (c + 1 < nch) {
            prefetch(c + 1, s ^ 1);
            CP_COMMIT();
            CP_WAIT(1);
        } else {
            CP_WAIT(0);
        }
        __syncthreads();

#pragma unroll
        for (int ks = 0; ks < 2; ks++) {
            wmma::fragment<wmma::matrix_a, 16, 16, 16, __half, wmma::row_major> af[2];
#pragma unroll
            for (int mt = 0; mt < 2; mt++)
                wmma::load_matrix_sync(af[mt], &st[s].A[wm * 32 + mt * 16][ks * 16], 40);
#pragma unroll
            for (int nt = 0; nt < 4; nt++) {
                wmma::fragment<wmma::matrix_b, 16, 16, 16, __half, wmma::row_major> bh, bl;
                wmma::load_matrix_sync(bh, &st[s].Bh[ks * 16][wn * 64 + nt * 16], 136);
                if (TWOB)
                    wmma::load_matrix_sync(bl, &st[s].Bl[ks * 16][wn * 64 + nt * 16], 136);
#pragma unroll
                for (int mt = 0; mt < 2; mt++) {
                    wmma::mma_sync(acc[mt][nt], af[mt], bh, acc[mt][nt]);
                    if (TWOB)
                        wmma::mma_sync(acc[mt][nt], af[mt], bl, acc[mt][nt]);
                }
            }
        }
        __syncthreads();
    }

    // epilogue: stage each 16x16 tile in smem, add bias, optional score, store
    float* stg = reinterpret_cast<float*>(smem_raw) + wid * 320;
#pragma unroll
    for (int mt = 0; mt < 2; mt++) {
        float sacc = 0.f;
        int grow_last = -1;
#pragma unroll
        for (int nt = 0; nt < 4; nt++) {
            wmma::store_matrix_sync(stg, acc[mt][nt], 20, wmma::mem_row_major);
            __syncwarp();
            int r = lane >> 1, cofs = (lane & 1) * 8;
            int gr = row0 + wm * 32 + mt * 16 + r;
            int gc = col0 + wn * 64 + nt * 16 + cofs;
            grow_last = gr;
            if (gr < M) {
                float o[8];
#pragma unroll
                for (int j = 0; j < 8; j++) o[j] = stg[r * 20 + cofs + j] + __ldg(&bias[gc + j]);
                if (score_out) {
#pragma unroll
                    for (int j = 0; j < 8; j++) sacc += o[j] * __ldg(&avec[gc + j]);
                }
                if (HALF_OUT) {
                    uint4 u;
                    __half2 p0 = __floats2half2_rn(o[0], o[1]);
                    __half2 p1 = __floats2half2_rn(o[2], o[3]);
                    __half2 p2 = __floats2half2_rn(o[4], o[5]);
                    __half2 p3 = __floats2half2_rn(o[6], o[7]);
                    u.x = *reinterpret_cast<unsigned*>(&p0);
                    u.y = *reinterpret_cast<unsigned*>(&p1);
                    u.z = *reinterpret_cast<unsigned*>(&p2);
                    u.w = *reinterpret_cast<unsigned*>(&p3);
                    *reinterpret_cast<uint4*>(Ch + (size_t)gr * N + gc) = u;
                } else {
                    *reinterpret_cast<float4*>(Cf + (size_t)gr * N + gc)     = make_float4(o[0], o[1], o[2], o[3]);
                    *reinterpret_cast<float4*>(Cf + (size_t)gr * N + gc + 4) = make_float4(o[4], o[5], o[6], o[7]);
                }
            }
            __syncwarp();
        }
        if (score_out && grow_last >= 0 && grow_last < M)
            atomicAdd(&score_out[grow_last], sacc);
    }
}

// ---------------------------------------------------------------------------
// Fused v2e: segment softmax + weighted fp16 gather + elu -> fp16 out
// ---------------------------------------------------------------------------
__global__ __launch_bounds__(256)
void v2e_softmax_kernel(const __half* __restrict__ Xfeat, const float* __restrict__ score,
                        const int* __restrict__ e_rowptr, const int* __restrict__ eV,
                        __half* __restrict__ Ye, int M, int H)
{
    int warp = (blockIdx.x * blockDim.x + threadIdx.x) >> 5;
    int lane = threadIdx.x & 31;
    if (warp >= M) return;
    const int beg = e_rowptr[warp];
    const int end = e_rowptr[warp + 1];

    float m = -1e30f;
    for (int j = beg + lane; j < end; j += 32)
        m = fmaxf(m, leakyf(__ldg(&score[eV[j]])));
#pragma unroll
    for (int o = 16; o > 0; o >>= 1) m = fmaxf(m, __shfl_xor_sync(0xffffffffu, m, o));

    float den = 0.f;
    for (int j = beg + lane; j < end; j += 32)
        den += expf(leakyf(__ldg(&score[eV[j]])) - m);
#pragma unroll
    for (int o = 16; o > 0; o >>= 1) den += __shfl_xor_sync(0xffffffffu, den, o);
    float invden = (end > beg) ? 1.f / den : 0.f;

    float acc[8];
#pragma unroll
    for (int k = 0; k < 8; k++) acc[k] = 0.f;

    for (int j = beg; j < end; j++) {
        int v = eV[j];
        float w = expf(leakyf(__ldg(&score[v])) - m) * invden;
        uint4 u = __ldg(reinterpret_cast<const uint4*>(Xfeat + (size_t)v * H) + lane);
        const __half2* h = reinterpret_cast<const __half2*>(&u);
#pragma unroll
        for (int k = 0; k < 4; k++) {
            float2 f = __half22float2(h[k]);
            acc[2 * k + 0] = fmaf(f.x, w, acc[2 * k + 0]);
            acc[2 * k + 1] = fmaf(f.y, w, acc[2 * k + 1]);
        }
    }

    uint4 u;
    __half2 p0 = __floats2half2_rn(eluf(acc[0]), eluf(acc[1]));
    __half2 p1 = __floats2half2_rn(eluf(acc[2]), eluf(acc[3]));
    __half2 p2 = __floats2half2_rn(eluf(acc[4]), eluf(acc[5]));
    __half2 p3 = __floats2half2_rn(eluf(acc[6]), eluf(acc[7]));
    u.x = *reinterpret_cast<unsigned*>(&p0);
    u.y = *reinterpret_cast<unsigned*>(&p1);
    u.z = *reinterpret_cast<unsigned*>(&p2);
    u.w = *reinterpret_cast<unsigned*>(&p3);
    *(reinterpret_cast<uint4*>(Ye + (size_t)warp * H) + lane) = u;
}

// ---------------------------------------------------------------------------
// Fused e2v: mean (fp16 gather) + elu + residual (fp32) -> fp16 out
// ---------------------------------------------------------------------------
__global__ __launch_bounds__(256)
void e2v_mean_kernel(const __half* __restrict__ Ye2,
                     const int* __restrict__ v_rowptr, const int* __restrict__ vE,
                     const float* __restrict__ Xinit,
                     __half* __restrict__ hout, int N, int H)
{
    int warp = (blockIdx.x * blockDim.x + threadIdx.x) >> 5;
    int lane = threadIdx.x & 31;
    if (warp >= N) return;
    const int beg = v_rowptr[warp];
    const int end = v_rowptr[warp + 1];

    float acc[8];
#pragma unroll
    for (int k = 0; k < 8; k++) acc[k] = 0.f;

    for (int j = beg; j < end; j++) {
        int e = vE[j];
        uint4 u = __ldg(reinterpret_cast<const uint4*>(Ye2 + (size_t)e * H) + lane);
        const __half2* h = reinterpret_cast<const __half2*>(&u);
#pragma unroll
        for (int k = 0; k < 4; k++) {
            float2 f = __half22float2(h[k]);
            acc[2 * k + 0] += f.x;
            acc[2 * k + 1] += f.y;
        }
    }
    float inv = (end > beg) ? 1.f / (float)(end - beg) : 0.f;

    const float4* xi = reinterpret_cast<const float4*>(Xinit + (size_t)warp * H) + lane * 2;
    float4 r0 = __ldg(&xi[0]), r1 = __ldg(&xi[1]);
    float o[8];
    o[0] = eluf(acc[0] * inv) + r0.x; o[1] = eluf(acc[1] * inv) + r0.y;
    o[2] = eluf(acc[2] * inv) + r0.z; o[3] = eluf(acc[3] * inv) + r0.w;
    o[4] = eluf(acc[4] * inv) + r1.x; o[5] = eluf(acc[5] * inv) + r1.y;
    o[6] = eluf(acc[6] * inv) + r1.z; o[7] = eluf(acc[7] * inv) + r1.w;

    uint4 u;
    __half2 p0 = __floats2half2_rn(o[0], o[1]);
    __half2 p1 = __floats2half2_rn(o[2], o[3]);
    __half2 p2 = __floats2half2_rn(o[4], o[5]);
    __half2 p3 = __floats2half2_rn(o[6], o[7]);
    u.x = *reinterpret_cast<unsigned*>(&p0);
    u.y = *reinterpret_cast<unsigned*>(&p1);
    u.z = *reinterpret_cast<unsigned*>(&p2);
    u.w = *reinterpret_cast<unsigned*>(&p3);
    *(reinterpret_cast<uint4*>(hout + (size_t)warp * H) + lane) = u;
}

// ---------------------------------------------------------------------------
// Hyperconv edge: fp16 gather, fp16 out.  O == 128: uint2 per lane.
// ---------------------------------------------------------------------------
__global__ __launch_bounds__(256)
void hyper_edge_kernel(const __half* __restrict__ Xn,
                       const int* __restrict__ e_rowptr, const int* __restrict__ eV,
                       const int* __restrict__ v_rowptr,
                       __half* __restrict__ Ye, int M, int O)
{
    int warp = (blockIdx.x * blockDim.x + threadIdx.x) >> 5;
    int lane = threadIdx.x & 31;
    if (warp >= M) return;
    const int beg = e_rowptr[warp];
    const int end = e_rowptr[warp + 1];
    const int cnt = end - beg;

    float sumDv = 0.f;
    for (int j = beg + lane; j < end; j += 32) {
        int v = eV[j];
        sumDv += (float)(__ldg(&v_rowptr[v + 1]) - __ldg(&v_rowptr[v]));
    }
#pragma unroll
    for (int o = 16; o > 0; o >>= 1) sumDv += __shfl_xor_sync(0xffffffffu, sumDv, o);

    float acc[4];
#pragma unroll
    for (int k = 0; k < 4; k++) acc[k] = 0.f;

    for (int j = beg; j < end; j++) {
        int v = eV[j];
        uint2 u = __ldg(reinterpret_cast<const uint2*>(Xn + (size_t)v * O) + lane);
        const __half2* h = reinterpret_cast<const __half2*>(&u);
        float2 f0 = __half22float2(h[0]), f1 = __half22float2(h[1]);
        acc[0] += f0.x; acc[1] += f0.y; acc[2] += f1.x; acc[3] += f1.y;
    }

    float invc = (cnt > 0) ? 1.f / (float)cnt : 0.f;
    float De = sumDv / ((float)cnt + 1.f);
    float dinv = (De > 0.f) ? rsqrtf(De) : 1.f;
    float s = invc * dinv;

    uint2 u;
    __half2 p0 = __floats2half2_rn(acc[0] * s, acc[1] * s);
    __half2 p1 = __floats2half2_rn(acc[2] * s, acc[3] * s);
    u.x = *reinterpret_cast<unsigned*>(&p0);
    u.y = *reinterpret_cast<unsigned*>(&p1);
    *(reinterpret_cast<uint2*>(Ye + (size_t)warp * O) + lane) = u;
}

// ---------------------------------------------------------------------------
// Hyperconv node: fp16 gather, fp32 out (final output)
// ---------------------------------------------------------------------------
__global__ __launch_bounds__(256)
void hyper_node_kernel(const __half* __restrict__ Ye,
                       const int* __restrict__ v_rowptr, const int* __restrict__ vE,
                       float* __restrict__ out, int N, int O)
{
    int warp = (blockIdx.x * blockDim.x + threadIdx.x) >> 5;
    int lane = threadIdx.x & 31;
    if (warp >= N) return;
    const int beg = v_rowptr[warp];
    const int end = v_rowptr[warp + 1];
    const int deg = end - beg;

    float acc[4];
#pragma unroll
    for (int k = 0; k < 4; k++) acc[k] = 0.f;

    for (int j = beg; j < end; j++) {
        int e = vE[j];
        uint2 u = __ldg(reinterpret_cast<const uint2*>(Ye + (size_t)e * O) + lane);
        const __half2* h = reinterpret_cast<const __half2*>(&u);
        float2 f0 = __half22float2(h[0]), f1 = __half22float2(h[1]);
        acc[0] += f0.x; acc[1] += f0.y; acc[2] += f1.x; acc[3] += f1.y;
    }
    float dinv = (deg > 0) ? rsqrtf((float)deg) : 0.f;

    float4 o;
    o.x = acc[0] * dinv; o.y = acc[1] * dinv;
    o.z = acc[2] * dinv; o.w = acc[3] * dinv;
    *(reinterpret_cast<float4*>(out + (size_t)warp * O) + lane) = o;
}

// ---------------------------------------------------------------------------
// Host
// ---------------------------------------------------------------------------
static inline int ceil_div(int a, int b) { return (a + b - 1) / b; }

extern "C" void kernel_launch(void* const* d_in, const int* in_sizes, int n_in,
                              void* d_out, int out_size)
{
    const float* X   = (const float*)d_in[0];
    const int*   V   = (const int*)  d_in[1];
    const int*   E   = (const int*)  d_in[2];
    const float* S   = (const float*)d_in[3];
    const float* Wx0 = (const float*)d_in[4];
    const float* bx0 = (const float*)d_in[5];
    const float* Wv0 = (const float*)d_in[6];
    const float* bv0 = (const float*)d_in[7];
    const float* a0  = (const float*)d_in[8];
    const float* Wt0 = (const float*)d_in[9];
    const float* bt0 = (const float*)d_in[10];
    const float* Wx1 = (const float*)d_in[11];
    const float* bx1 = (const float*)d_in[12];
    const float* Wv1 = (const float*)d_in[13];
    const float* bv1 = (const float*)d_in[14];
    const float* a1  = (const float*)d_in[15];
    const float* Wt1 = (const float*)d_in[16];
    const float* bt1 = (const float*)d_in[17];
    const float* Wf  = (const float*)d_in[18];
    const float* bf  = (const float*)d_in[19];

    const int H    = in_sizes[5];              // 256
    const int IN   = in_sizes[4] / H;          // 128
    const int N    = in_sizes[0] / IN;         // 50000
    const int NNZ  = in_sizes[1];              // 400000
    const int HS   = in_sizes[9] / H;          // 320
    const int STAR = HS - H;                   // 64
    const int M    = in_sizes[3] / STAR;       // 20000
    const int OUT  = in_sizes[19];             // 128

    void* p;
    cudaGetSymbolAddress(&p, g_Xinit); float* Xinit = (float*)p;
    cudaGetSymbolAddress(&p, g_score); float* score = (float*)p;
    cudaGetSymbolAddress(&p, g_Xfeat); __half* Xfeat = (__half*)p;
    cudaGetSymbolAddress(&p, g_Ye2);   __half* Ye2   = (__half*)p;
    cudaGetSymbolAddress(&p, g_A);  __half* Abuf = (__half*)p;
    cudaGetSymbolAddress(&p, g_B);  __half* Bbuf = (__half*)p;
    cudaGetSymbolAddress(&p, g_Ye); __half* Yeh  = (__half*)p;
    cudaGetSymbolAddress(&p, g_S);  __half* Sh   = (__half*)p;
    cudaGetSymbolAddress(&p, g_Wh); __half* Wh   = (__half*)p;
    cudaGetSymbolAddress(&p, g_Wl); __half* Wl   = (__half*)p;
    cudaGetSymbolAddress(&p, g_e_rowptr); int* e_rowptr = (int*)p;
    cudaGetSymbolAddress(&p, g_v_rowptr); int* v_rowptr = (int*)p;
    cudaGetSymbolAddress(&p, g_e_cursor); int* e_cursor = (int*)p;
    cudaGetSymbolAddress(&p, g_v_cursor); int* v_cursor = (int*)p;
    cudaGetSymbolAddress(&p, g_cntE);     int* cntE     = (int*)p;
    cudaGetSymbolAddress(&p, g_cntV);     int* cntV     = (int*)p;
    cudaGetSymbolAddress(&p, g_eV);       int* eV       = (int*)p;
    cudaGetSymbolAddress(&p, g_vE);       int* vE       = (int*)p;

    // one-time init (first call = correctness run, NOT under graph capture)
    static bool inited = false;
    static cudaStream_t s1 = 0, s2 = 0;
    static cudaEvent_t evFork, eW01, eWall, eCsr, eG1a, eX0, eG1b, eX1;
    if (!inited) {
        cudaFuncSetAttribute(gemm_fp16<false, true>,  cudaFuncAttributeMaxDynamicSharedMemorySize, GEMM_SMEM);
        cudaFuncSetAttribute(gemm_fp16<true, true>,   cudaFuncAttributeMaxDynamicSharedMemorySize, GEMM_SMEM);
        cudaFuncSetAttribute(gemm_fp16<false, false>, cudaFuncAttributeMaxDynamicSharedMemorySize, GEMM_SMEM);
        if (cudaStreamCreateWithFlags(&s1, cudaStreamNonBlocking) != cudaSuccess) s1 = 0;
        if (cudaStreamCreateWithFlags(&s2, cudaStreamNonBlocking) != cudaSuccess) s2 = 0;
        cudaEventCreateWithFlags(&evFork, cudaEventDisableTiming);
        cudaEventCreateWithFlags(&eW01,  cudaEventDisableTiming);
        cudaEventCreateWithFlags(&eWall, cudaEventDisableTiming);
        cudaEventCreateWithFlags(&eCsr,  cudaEventDisableTiming);
        cudaEventCreateWithFlags(&eG1a,  cudaEventDisableTiming);
        cudaEventCreateWithFlags(&eX0,   cudaEventDisableTiming);
        cudaEventCreateWithFlags(&eG1b,  cudaEventDisableTiming);
        cudaEventCreateWithFlags(&eX1,   cudaEventDisableTiming);
        inited = true;
    }

    // weight offsets ([K,N] row-major, packed)
    const size_t o_wx0 = 0;
    const size_t o_wv0 = o_wx0 + (size_t)IN * H;
    const size_t o_wt0 = o_wv0 + (size_t)IN * H;
    const size_t o_wx1 = o_wt0 + (size_t)HS * H;
    const size_t o_wv1 = o_wx1 + (size_t)H * H;
    const size_t o_wt1 = o_wv1 + (size_t)H * H;
    const size_t o_wf  = o_wt1 + (size_t)HS * H;

    auto splitw = [&](const float* src, __half* dh, __half* dl, long nelem, cudaStream_t st) {
        long n4 = nelem / 4;
        int blocks = (int)((n4 + 255) / 256); if (blocks > 2048) blocks = 2048;
        splitw_kernel<<<blocks, 256, 0, st>>>(src, dh, dl, n4);
    };
    auto tohalf = [&](const float* src, __half* dst, long nelem, cudaStream_t st) {
        long n4 = nelem / 4;
        int blocks = (int)((n4 + 255) / 256); if (blocks > 2048) blocks = 2048;
        tohalf_kernel<<<blocks, 256, 0, st>>>(src, dst, n4);
    };

    // fp32-out, double-B (unused in scoring path)
    auto gemmF = [&](const __half* a1, int K1, const __half* a2, int K2,
                     size_t woff, const float* bias, float* C, int Mrows, int Ncols,
                     cudaStream_t st) {
        dim3 grid(Ncols / 128, ceil_div(Mrows, 128));
        gemm_fp16<false, true><<<grid, 256, GEMM_SMEM, st>>>(a1, K1, a2, K2,
            Wh + woff, Wl + woff, bias, C, nullptr, nullptr, nullptr, Mrows, Ncols);
    };
    // fp32-out, single-B (residual Xinit path)
    auto gemmF1 = [&](const __half* a1, int K1,
                      size_t woff, const float* bias, float* C, int Mrows, int Ncols,
                      cudaStream_t st) {
        dim3 grid(Ncols / 128, ceil_div(Mrows, 128));
        gemm_fp16<false, false><<<grid, 256, GEMM_SMEM, st>>>(a1, K1, nullptr, 0,
            Wh + woff, nullptr, bias, C, nullptr, nullptr, nullptr, Mrows, Ncols);
    };
    // fp16-out, double-B, optional fused score
    auto gemmH = [&](const __half* a1, int K1, const __half* a2, int K2,
                     size_t woff, const float* bias, __half* C, int Mrows, int Ncols,
                     const float* avec, float* sc, cudaStream_t st) {
        dim3 grid(Ncols / 128, ceil_div(Mrows, 128));
        gemm_fp16<true, true><<<grid, 256, GEMM_SMEM, st>>>(a1, K1, a2, K2,
            Wh + woff, Wl + woff, bias, nullptr, C, avec, sc, Mrows, Ncols);
    };

    const int nnzBlocks      = ceil_div(NNZ, 256);
    const int edgeWarpBlocks = ceil_div(M, 8);
    const int nodeWarpBlocks = ceil_div(N, 8);

    // ---- fork ----
    cudaEventRecord(evFork, 0);
    cudaStreamWaitEvent(s1, evFork, 0);
    cudaStreamWaitEvent(s2, evFork, 0);

    // ---- s2: weight splits + S conversion + score zero (layer 0) ----
    fill_float<<<ceil_div(N, 256), 256, 0, s2>>>(score, 0.f, N);
    splitw(Wv0, Wh + o_wv0, Wl + o_wv0, (long)IN * H, s2);
    splitw(Wx0, Wh + o_wx0, Wl + o_wx0, (long)IN * H, s2);
    cudaEventRecord(eW01, s2);
    splitw(Wt0, Wh + o_wt0, Wl + o_wt0, (long)HS * H, s2);
    splitw(Wx1, Wh + o_wx1, Wl + o_wx1, (long)H * H,  s2);
    splitw(Wv1, Wh + o_wv1, Wl + o_wv1, (long)H * H,  s2);
    splitw(Wt1, Wh + o_wt1, Wl + o_wt1, (long)HS * H, s2);
    splitw(Wf,  Wh + o_wf,  Wl + o_wf,  (long)H * OUT, s2);
    tohalf(S, Sh, (long)M * STAR, s2);
    cudaEventRecord(eWall, s2);

    // ---- s1: CSR build ----
    fill_int<<<ceil_div(M, 256), 256, 0, s1>>>(cntE, 0, M);
    fill_int<<<ceil_div(N, 256), 256, 0, s1>>>(cntV, 0, N);
    count_kernel<<<nnzBlocks, 256, 0, s1>>>(V, E, cntV, cntE, NNZ);
    scan_kernel<<<1, 1024, 0, s1>>>(cntE, e_rowptr, e_cursor, M);
    scan_kernel<<<1, 1024, 0, s1>>>(cntV, v_rowptr, v_cursor, N);
    fill_lists_kernel<<<nnzBlocks, 256, 0, s1>>>(V, E, e_cursor, v_cursor, eV, vE, NNZ);
    cudaEventRecord(eCsr, s1);

    // ---- s0: convert X, then layer 0 ----
    tohalf(X, Abuf, (long)N * IN, 0);
    cudaStreamWaitEvent(0, eW01, 0);
    gemmH(Abuf, IN, nullptr, 0, o_wv0, bv0, Xfeat, N, H, a0, score, 0);   // Wv0 + fused score
    cudaEventRecord(eG1a, 0);

    // s1: Xinit GEMM (single fp16) overlapped with v2e/Wt-GEMM
    cudaStreamWaitEvent(s1, eG1a, 0);
    gemmF1(Abuf, IN, o_wx0, bx0, Xinit, N, H, s1);
    cudaEventRecord(eX0, s1);

    cudaStreamWaitEvent(0, eCsr, 0);
    cudaStreamWaitEvent(0, eWall, 0);
    v2e_softmax_kernel<<<edgeWarpBlocks, 256>>>(Xfeat, score, e_rowptr, eV, Yeh, M, H);
    fill_float<<<ceil_div(N, 256), 256>>>(score, 0.f, N);   // re-zero for layer 1
    gemmH(Yeh, H, Sh, STAR, o_wt0, bt0, Ye2, M, H, nullptr, nullptr, 0);
    cudaStreamWaitEvent(0, eX0, 0);
    e2v_mean_kernel<<<nodeWarpBlocks, 256>>>(Ye2, v_rowptr, vE, Xinit, Bbuf, N, H);

    // ---- layer 1 ----
    gemmH(Bbuf, H, nullptr, 0, o_wv1, bv1, Xfeat, N, H, a1, score, 0);    // Wv1 + fused score
    cudaEventRecord(eG1b, 0);

    cudaStreamWaitEvent(s1, eG1b, 0);
    gemmF1(Bbuf, H, o_wx1, bx1, Xinit, N, H, s1);
    cudaEventRecord(eX1, s1);

    v2e_softmax_kernel<<<edgeWarpBlocks, 256>>>(Xfeat, score, e_rowptr, eV, Yeh, M, H);
    gemmH(Yeh, H, Sh, STAR, o_wt1, bt1, Ye2, M, H, nullptr, nullptr, 0);
    cudaStreamWaitEvent(0, eX1, 0);
    e2v_mean_kernel<<<nodeWarpBlocks, 256>>>(Ye2, v_rowptr, vE, Xinit, Abuf, N, H);

    // ---- hyperconv (s0) ----
    gemmH(Abuf, H, nullptr, 0, o_wf, bf, Xfeat, N, OUT, nullptr, nullptr, 0);
    hyper_edge_kernel<<<edgeWarpBlocks, 256>>>(Xfeat, e_rowptr, eV, v_rowptr, Yeh, M, OUT);
    hyper_node_kernel<<<nodeWarpBlocks, 256>>>(Yeh, v_rowptr, vE, (float*)d_out, N, OUT);
}

// round 10
// speedup vs baseline: 5.6816x; 1.1150x over previous
#include <cuda_runtime.h>
#include <cuda_fp16.h>
#include <mma.h>
#include <math.h>
#include <stdint.h>

using namespace nvcuda;

// ---------------------------------------------------------------------------
// Problem max sizes
// ---------------------------------------------------------------------------
#define NMAX   50000
#define MMAX   20000
#define NNZMAX 400000
#define HMAX   256
#define WTOTAL 393216

// ---------------------------------------------------------------------------
// Scratch (device globals)
// ---------------------------------------------------------------------------
__device__ float g_Xinit[NMAX * HMAX];
__device__ float g_score[NMAX];

__device__ __half g_Xfeat[NMAX * HMAX];  // fp16 GEMM outputs (Wv / Wf)
__device__ __half g_Ye2  [MMAX * HMAX];  // fp16 GEMM output (Wt)
__device__ __half g_A [NMAX * HMAX];     // activations (X / h2)
__device__ __half g_B [NMAX * HMAX];     // h1
__device__ __half g_Ye[MMAX * HMAX];     // v2e out / hyper_edge out
__device__ __half g_S [MMAX * 64];
__device__ __half g_Wh[WTOTAL];          // weights fp16, [K,N] row-major packed

// CSR structures
__device__ int g_e_rowptr[MMAX + 1];
__device__ int g_v_rowptr[NMAX + 1];
__device__ int g_e_cursor[MMAX];
__device__ int g_v_cursor[NMAX];
__device__ int g_cntE[MMAX];
__device__ int g_cntV[NMAX];
__device__ int g_eV[NNZMAX];
__device__ int g_vE[NNZMAX];

// ---------------------------------------------------------------------------
// Helpers
// ---------------------------------------------------------------------------
__device__ __forceinline__ float eluf(float x)  { return x > 0.f ? x : expm1f(x); }
__device__ __forceinline__ float leakyf(float x){ return x > 0.f ? x : 0.2f * x; }

__device__ __forceinline__ uint32_t smem_to_u32(const void* p) {
    uint32_t a;
    asm("{ .reg .u64 t; cvta.to.shared.u64 t, %1; cvt.u32.u64 %0, t; }" : "=r"(a) : "l"(p));
    return a;
}
__device__ __forceinline__ void cp_async16(uint32_t dst, const void* src, int sz) {
    asm volatile("cp.async.cg.shared.global [%0], [%1], 16, %2;"
                 :: "r"(dst), "l"(src), "r"(sz) : "memory");
}
#define CP_COMMIT() asm volatile("cp.async.commit_group;" ::: "memory")
#define CP_WAIT(n)  asm volatile("cp.async.wait_group %0;" :: "n"(n) : "memory")

// fp32 -> fp16 conversion (activations and weights)
__global__ void tohalf_kernel(const float* __restrict__ x, __half* __restrict__ out, long n4)
{
    long i = (long)blockIdx.x * blockDim.x + threadIdx.x;
    long stride = (long)gridDim.x * blockDim.x;
    for (; i < n4; i += stride) {
        float4 v = reinterpret_cast<const float4*>(x)[i];
        __half2 h0 = __floats2half2_rn(v.x, v.y);
        __half2 h1 = __floats2half2_rn(v.z, v.w);
        uint2 u;
        u.x = *reinterpret_cast<unsigned*>(&h0);
        u.y = *reinterpret_cast<unsigned*>(&h1);
        *reinterpret_cast<uint2*>(out + 4 * i) = u;
    }
}

__global__ void fill_int(int* __restrict__ p, int v, int n) {
    int i = blockIdx.x * blockDim.x + threadIdx.x;
    int stride = gridDim.x * blockDim.x;
    for (; i < n; i += stride) p[i] = v;
}
__global__ void fill_float(float* __restrict__ p, float v, int n) {
    int i = blockIdx.x * blockDim.x + threadIdx.x;
    int stride = gridDim.x * blockDim.x;
    for (; i < n; i += stride) p[i] = v;
}

// ---------------------------------------------------------------------------
// CSR construction
// ---------------------------------------------------------------------------
__global__ void count_kernel(const int* __restrict__ V, const int* __restrict__ E,
                             int* __restrict__ cntV, int* __restrict__ cntE, int nnz)
{
    int i = blockIdx.x * blockDim.x + threadIdx.x;
    if (i >= nnz) return;
    atomicAdd(&cntE[E[i]], 1);
    atomicAdd(&cntV[V[i]], 1);
}

__global__ __launch_bounds__(1024)
void scan_kernel(const int* __restrict__ cnt, int* __restrict__ rowptr,
                 int* __restrict__ cursor, int len)
{
    __shared__ int wsum[32];
    __shared__ int s_carry;
    const int tid = threadIdx.x, lane = tid & 31, wid = tid >> 5;
    if (tid == 0) s_carry = 0;
    __syncthreads();

    for (int base = 0; base < len; base += 4096) {
        int i0 = base + tid * 4;
        int v0 = (i0 + 0 < len) ? cnt[i0 + 0] : 0;
        int v1 = (i0 + 1 < len) ? cnt[i0 + 1] : 0;
        int v2 = (i0 + 2 < len) ? cnt[i0 + 2] : 0;
        int v3 = (i0 + 3 < len) ? cnt[i0 + 3] : 0;
        int t1 = v0 + v1, t2 = t1 + v2, t3 = t2 + v3;

        int inc = t3;
#pragma unroll
        for (int o = 1; o < 32; o <<= 1) {
            int u = __shfl_up_sync(0xffffffffu, inc, o);
            if (lane >= o) inc += u;
        }
        if (lane == 31) wsum[wid] = inc;
        __syncthreads();
        if (wid == 0) {
            int w = wsum[lane];
            int wi = w;
#pragma unroll
            for (int o = 1; o < 32; o <<= 1) {
                int u = __shfl_up_sync(0xffffffffu, wi, o);
                if (lane >= o) wi += u;
            }
            wsum[lane] = wi - w;
        }
        __syncthreads();
        int excl = s_carry + wsum[wid] + (inc - t3);
        if (i0 + 0 < len) { rowptr[i0 + 0] = excl;      cursor[i0 + 0] = excl; }
        if (i0 + 1 < len) { rowptr[i0 + 1] = excl + v0; cursor[i0 + 1] = excl + v0; }
        if (i0 + 2 < len) { rowptr[i0 + 2] = excl + t1; cursor[i0 + 2] = excl + t1; }
        if (i0 + 3 < len) { rowptr[i0 + 3] = excl + t2; cursor[i0 + 3] = excl + t2; }
        __syncthreads();
        if (tid == 1023) s_carry = s_carry + wsum[31] + inc;
        __syncthreads();
    }
    if (threadIdx.x == 0) rowptr[len] = s_carry;
}

__global__ void fill_lists_kernel(const int* __restrict__ V, const int* __restrict__ E,
                                  int* __restrict__ e_cursor, int* __restrict__ v_cursor,
                                  int* __restrict__ eV, int* __restrict__ vE, int nnz)
{
    int i = blockIdx.x * blockDim.x + threadIdx.x;
    if (i >= nnz) return;
    int v = V[i], e = E[i];
    int pe = atomicAdd(&e_cursor[e], 1);
    eV[pe] = v;
    int pv = atomicAdd(&v_cursor[v], 1);
    vE[pv] = e;
}

// ---------------------------------------------------------------------------
// fp16 tensor-core GEMM (single fp16 weights), cp.async double buffered.
// C[M,N] = [A1|A2] @ W + bias; out fp32 or fp16.
// Optional fused row-score: score[r] += dot(C_row, avec) (fp32, atomic).
// ---------------------------------------------------------------------------
struct GemmStage {
    __half A[128][40];
    __half B[32][136];
};
static constexpr int GEMM_SMEM = 2 * sizeof(GemmStage);   // 37888

template <bool HALF_OUT>
__global__ __launch_bounds__(256, 2)
void gemm_fp16(const __half* __restrict__ A1, int K1,
               const __half* __restrict__ A2, int K2,
               const __half* __restrict__ Bg,
               const float* __restrict__ bias,
               float* __restrict__ Cf, __half* __restrict__ Ch,
               const float* __restrict__ avec, float* __restrict__ score_out,
               int M, int N)
{
    extern __shared__ char smem_raw[];
    GemmStage* st = reinterpret_cast<GemmStage*>(smem_raw);

    const int tid  = threadIdx.x;
    const int wid  = tid >> 5, lane = tid & 31;
    const int wm   = wid >> 1, wn = wid & 1;
    const int row0 = blockIdx.y * 128;
    const int col0 = blockIdx.x * 128;
    const int K = K1 + K2, nch = K >> 5;

    wmma::fragment<wmma::accumulator, 16, 16, 16, float> acc[2][4];
#pragma unroll
    for (int mt = 0; mt < 2; mt++)
#pragma unroll
        for (int nt = 0; nt < 4; nt++) wmma::fill_fragment(acc[mt][nt], 0.f);

    auto prefetch = [&](int c, int s) {
        const int k0 = c * 32;
        const __half* a; int lda, col;
        if (k0 < K1) { a = A1; lda = K1; col = k0; }
        else         { a = A2; lda = K2; col = k0 - K1; }
#pragma unroll
        for (int t = 0; t < 2; t++) {
            int u = tid + t * 256, r = u >> 2, q = u & 3;
            int gr = row0 + r;
            int sz = (gr < M) ? 16 : 0;
            size_t off = (size_t)(gr < M ? gr : 0) * lda + col + q * 8;
            cp_async16(smem_to_u32(&st[s].A[r][q * 8]), a + off, sz);
        }
#pragma unroll
        for (int t = 0; t < 2; t++) {
            int u = tid + t * 256, r = u >> 4, q = u & 15;
            size_t off = (size_t)(k0 + r) * N + col0 + q * 8;
            cp_async16(smem_to_u32(&st[s].B[r][q * 8]), Bg + off, 16);
        }
    };

    prefetch(0, 0);
    CP_COMMIT();

    for (int c = 0; c < nch; c++) {
        const int s = c & 1;
        if (c + 1 < nch) {
            prefetch(c + 1, s ^ 1);
            CP_COMMIT();
            CP_WAIT(1);
        } else {
            CP_WAIT(0);
        }
        __syncthreads();

#pragma unroll
        for (int ks = 0; ks < 2; ks++) {
            wmma::fragment<wmma::matrix_a, 16, 16, 16, __half, wmma::row_major> af[2];
#pragma unroll
            for (int mt = 0; mt < 2; mt++)
                wmma::load_matrix_sync(af[mt], &st[s].A[wm * 32 + mt * 16][ks * 16], 40);
#pragma unroll
            for (int nt = 0; nt < 4; nt++) {
                wmma::fragment<wmma::matrix_b, 16, 16, 16, __half, wmma::row_major> bf;
                wmma::load_matrix_sync(bf, &st[s].B[ks * 16][wn * 64 + nt * 16], 136);
#pragma unroll
                for (int mt = 0; mt < 2; mt++)
                    wmma::mma_sync(acc[mt][nt], af[mt], bf, acc[mt][nt]);
            }
        }
        __syncthreads();
    }

    // epilogue: stage each 16x16 tile in smem, add bias, optional score, store
    float* stg = reinterpret_cast<float*>(smem_raw) + wid * 320;
#pragma unroll
    for (int mt = 0; mt < 2; mt++) {
        float sacc = 0.f;
        int grow_last = -1;
#pragma unroll
        for (int nt = 0; nt < 4; nt++) {
            wmma::store_matrix_sync(stg, acc[mt][nt], 20, wmma::mem_row_major);
            __syncwarp();
            int r = lane >> 1, cofs = (lane & 1) * 8;
            int gr = row0 + wm * 32 + mt * 16 + r;
            int gc = col0 + wn * 64 + nt * 16 + cofs;
            grow_last = gr;
            if (gr < M) {
                float o[8];
#pragma unroll
                for (int j = 0; j < 8; j++) o[j] = stg[r * 20 + cofs + j] + __ldg(&bias[gc + j]);
                if (score_out) {
#pragma unroll
                    for (int j = 0; j < 8; j++) sacc += o[j] * __ldg(&avec[gc + j]);
                }
                if (HALF_OUT) {
                    uint4 u;
                    __half2 p0 = __floats2half2_rn(o[0], o[1]);
                    __half2 p1 = __floats2half2_rn(o[2], o[3]);
                    __half2 p2 = __floats2half2_rn(o[4], o[5]);
                    __half2 p3 = __floats2half2_rn(o[6], o[7]);
                    u.x = *reinterpret_cast<unsigned*>(&p0);
                    u.y = *reinterpret_cast<unsigned*>(&p1);
                    u.z = *reinterpret_cast<unsigned*>(&p2);
                    u.w = *reinterpret_cast<unsigned*>(&p3);
                    *reinterpret_cast<uint4*>(Ch + (size_t)gr * N + gc) = u;
                } else {
                    *reinterpret_cast<float4*>(Cf + (size_t)gr * N + gc)     = make_float4(o[0], o[1], o[2], o[3]);
                    *reinterpret_cast<float4*>(Cf + (size_t)gr * N + gc + 4) = make_float4(o[4], o[5], o[6], o[7]);
                }
            }
            __syncwarp();
        }
        if (score_out && grow_last >= 0 && grow_last < M)
            atomicAdd(&score_out[grow_last], sacc);
    }
}

// ---------------------------------------------------------------------------
// Fused v2e: segment softmax + weighted fp16 gather + elu -> fp16 out
// Member loop unrolled x2 for MLP.
// ---------------------------------------------------------------------------
__global__ __launch_bounds__(256)
void v2e_softmax_kernel(const __half* __restrict__ Xfeat, const float* __restrict__ score,
                        const int* __restrict__ e_rowptr, const int* __restrict__ eV,
                        __half* __restrict__ Ye, int M, int H)
{
    int warp = (blockIdx.x * blockDim.x + threadIdx.x) >> 5;
    int lane = threadIdx.x & 31;
    if (warp >= M) return;
    const int beg = e_rowptr[warp];
    const int end = e_rowptr[warp + 1];

    float m = -1e30f;
    for (int j = beg + lane; j < end; j += 32)
        m = fmaxf(m, leakyf(__ldg(&score[eV[j]])));
#pragma unroll
    for (int o = 16; o > 0; o >>= 1) m = fmaxf(m, __shfl_xor_sync(0xffffffffu, m, o));

    float den = 0.f;
    for (int j = beg + lane; j < end; j += 32)
        den += expf(leakyf(__ldg(&score[eV[j]])) - m);
#pragma unroll
    for (int o = 16; o > 0; o >>= 1) den += __shfl_xor_sync(0xffffffffu, den, o);
    float invden = (end > beg) ? 1.f / den : 0.f;

    float acc[8];
#pragma unroll
    for (int k = 0; k < 8; k++) acc[k] = 0.f;

    int j = beg;
    for (; j + 2 <= end; j += 2) {
        int v0 = eV[j], v1 = eV[j + 1];
        float w0 = expf(leakyf(__ldg(&score[v0])) - m) * invden;
        float w1 = expf(leakyf(__ldg(&score[v1])) - m) * invden;
        uint4 u0 = __ldg(reinterpret_cast<const uint4*>(Xfeat + (size_t)v0 * H) + lane);
        uint4 u1 = __ldg(reinterpret_cast<const uint4*>(Xfeat + (size_t)v1 * H) + lane);
        const __half2* h0 = reinterpret_cast<const __half2*>(&u0);
        const __half2* h1 = reinterpret_cast<const __half2*>(&u1);
#pragma unroll
        for (int k = 0; k < 4; k++) {
            float2 f0 = __half22float2(h0[k]);
            float2 f1 = __half22float2(h1[k]);
            acc[2 * k + 0] = fmaf(f0.x, w0, fmaf(f1.x, w1, acc[2 * k + 0]));
            acc[2 * k + 1] = fmaf(f0.y, w0, fmaf(f1.y, w1, acc[2 * k + 1]));
        }
    }
    if (j < end) {
        int v = eV[j];
        float w = expf(leakyf(__ldg(&score[v])) - m) * invden;
        uint4 u = __ldg(reinterpret_cast<const uint4*>(Xfeat + (size_t)v * H) + lane);
        const __half2* h = reinterpret_cast<const __half2*>(&u);
#pragma unroll
        for (int k = 0; k < 4; k++) {
            float2 f = __half22float2(h[k]);
            acc[2 * k + 0] = fmaf(f.x, w, acc[2 * k + 0]);
            acc[2 * k + 1] = fmaf(f.y, w, acc[2 * k + 1]);
        }
    }

    uint4 u;
    __half2 p0 = __floats2half2_rn(eluf(acc[0]), eluf(acc[1]));
    __half2 p1 = __floats2half2_rn(eluf(acc[2]), eluf(acc[3]));
    __half2 p2 = __floats2half2_rn(eluf(acc[4]), eluf(acc[5]));
    __half2 p3 = __floats2half2_rn(eluf(acc[6]), eluf(acc[7]));
    u.x = *reinterpret_cast<unsigned*>(&p0);
    u.y = *reinterpret_cast<unsigned*>(&p1);
    u.z = *reinterpret_cast<unsigned*>(&p2);
    u.w = *reinterpret_cast<unsigned*>(&p3);
    *(reinterpret_cast<uint4*>(Ye + (size_t)warp * H) + lane) = u;
}

// ---------------------------------------------------------------------------
// Fused e2v: mean (fp16 gather, x2 unrolled) + elu + residual (fp32) -> fp16
// ---------------------------------------------------------------------------
__global__ __launch_bounds__(256)
void e2v_mean_kernel(const __half* __restrict__ Ye2,
                     const int* __restrict__ v_rowptr, const int* __restrict__ vE,
                     const float* __restrict__ Xinit,
                     __half* __restrict__ hout, int N, int H)
{
    int warp = (blockIdx.x * blockDim.x + threadIdx.x) >> 5;
    int lane = threadIdx.x & 31;
    if (warp >= N) return;
    const int beg = v_rowptr[warp];
    const int end = v_rowptr[warp + 1];

    float acc[8];
#pragma unroll
    for (int k = 0; k < 8; k++) acc[k] = 0.f;

    int j = beg;
    for (; j + 2 <= end; j += 2) {
        int e0 = vE[j], e1 = vE[j + 1];
        uint4 u0 = __ldg(reinterpret_cast<const uint4*>(Ye2 + (size_t)e0 * H) + lane);
        uint4 u1 = __ldg(reinterpret_cast<const uint4*>(Ye2 + (size_t)e1 * H) + lane);
        const __half2* h0 = reinterpret_cast<const __half2*>(&u0);
        const __half2* h1 = reinterpret_cast<const __half2*>(&u1);
#pragma unroll
        for (int k = 0; k < 4; k++) {
            float2 f0 = __half22float2(h0[k]);
            float2 f1 = __half22float2(h1[k]);
            acc[2 * k + 0] += f0.x + f1.x;
            acc[2 * k + 1] += f0.y + f1.y;
        }
    }
    if (j < end) {
        int e = vE[j];
        uint4 u = __ldg(reinterpret_cast<const uint4*>(Ye2 + (size_t)e * H) + lane);
        const __half2* h = reinterpret_cast<const __half2*>(&u);
#pragma unroll
        for (int k = 0; k < 4; k++) {
            float2 f = __half22float2(h[k]);
            acc[2 * k + 0] += f.x;
            acc[2 * k + 1] += f.y;
        }
    }
    float inv = (end > beg) ? 1.f / (float)(end - beg) : 0.f;

    const float4* xi = reinterpret_cast<const float4*>(Xinit + (size_t)warp * H) + lane * 2;
    float4 r0 = __ldg(&xi[0]), r1 = __ldg(&xi[1]);
    float o[8];
    o[0] = eluf(acc[0] * inv) + r0.x; o[1] = eluf(acc[1] * inv) + r0.y;
    o[2] = eluf(acc[2] * inv) + r0.z; o[3] = eluf(acc[3] * inv) + r0.w;
    o[4] = eluf(acc[4] * inv) + r1.x; o[5] = eluf(acc[5] * inv) + r1.y;
    o[6] = eluf(acc[6] * inv) + r1.z; o[7] = eluf(acc[7] * inv) + r1.w;

    uint4 u;
    __half2 p0 = __floats2half2_rn(o[0], o[1]);
    __half2 p1 = __floats2half2_rn(o[2], o[3]);
    __half2 p2 = __floats2half2_rn(o[4], o[5]);
    __half2 p3 = __floats2half2_rn(o[6], o[7]);
    u.x = *reinterpret_cast<unsigned*>(&p0);
    u.y = *reinterpret_cast<unsigned*>(&p1);
    u.z = *reinterpret_cast<unsigned*>(&p2);
    u.w = *reinterpret_cast<unsigned*>(&p3);
    *(reinterpret_cast<uint4*>(hout + (size_t)warp * H) + lane) = u;
}

// ---------------------------------------------------------------------------
// Hyperconv edge: fp16 gather (x2 unrolled), fp16 out.  O == 128.
// ---------------------------------------------------------------------------
__global__ __launch_bounds__(256)
void hyper_edge_kernel(const __half* __restrict__ Xn,
                       const int* __restrict__ e_rowptr, const int* __restrict__ eV,
                       const int* __restrict__ v_rowptr,
                       __half* __restrict__ Ye, int M, int O)
{
    int warp = (blockIdx.x * blockDim.x + threadIdx.x) >> 5;
    int lane = threadIdx.x & 31;
    if (warp >= M) return;
    const int beg = e_rowptr[warp];
    const int end = e_rowptr[warp + 1];
    const int cnt = end - beg;

    float sumDv = 0.f;
    for (int j = beg + lane; j < end; j += 32) {
        int v = eV[j];
        sumDv += (float)(__ldg(&v_rowptr[v + 1]) - __ldg(&v_rowptr[v]));
    }
#pragma unroll
    for (int o = 16; o > 0; o >>= 1) sumDv += __shfl_xor_sync(0xffffffffu, sumDv, o);

    float acc[4];
#pragma unroll
    for (int k = 0; k < 4; k++) acc[k] = 0.f;

    int j = beg;
    for (; j + 2 <= end; j += 2) {
        int v0 = eV[j], v1 = eV[j + 1];
        uint2 u0 = __ldg(reinterpret_cast<const uint2*>(Xn + (size_t)v0 * O) + lane);
        uint2 u1 = __ldg(reinterpret_cast<const uint2*>(Xn + (size_t)v1 * O) + lane);
        const __half2* h0 = reinterpret_cast<const __half2*>(&u0);
        const __half2* h1 = reinterpret_cast<const __half2*>(&u1);
        float2 a0 = __half22float2(h0[0]), a1 = __half22float2(h0[1]);
        float2 b0 = __half22float2(h1[0]), b1 = __half22float2(h1[1]);
        acc[0] += a0.x + b0.x; acc[1] += a0.y + b0.y;
        acc[2] += a1.x + b1.x; acc[3] += a1.y + b1.y;
    }
    if (j < end) {
        int v = eV[j];
        uint2 u = __ldg(reinterpret_cast<const uint2*>(Xn + (size_t)v * O) + lane);
        const __half2* h = reinterpret_cast<const __half2*>(&u);
        float2 f0 = __half22float2(h[0]), f1 = __half22float2(h[1]);
        acc[0] += f0.x; acc[1] += f0.y; acc[2] += f1.x; acc[3] += f1.y;
    }

    float invc = (cnt > 0) ? 1.f / (float)cnt : 0.f;
    float De = sumDv / ((float)cnt + 1.f);
    float dinv = (De > 0.f) ? rsqrtf(De) : 1.f;
    float s = invc * dinv;

    uint2 u;
    __half2 p0 = __floats2half2_rn(acc[0] * s, acc[1] * s);
    __half2 p1 = __floats2half2_rn(acc[2] * s, acc[3] * s);
    u.x = *reinterpret_cast<unsigned*>(&p0);
    u.y = *reinterpret_cast<unsigned*>(&p1);
    *(reinterpret_cast<uint2*>(Ye + (size_t)warp * O) + lane) = u;
}

// ---------------------------------------------------------------------------
// Hyperconv node: fp16 gather (x2 unrolled), fp32 out (final output)
// ---------------------------------------------------------------------------
__global__ __launch_bounds__(256)
void hyper_node_kernel(const __half* __restrict__ Ye,
                       const int* __restrict__ v_rowptr, const int* __restrict__ vE,
                       float* __restrict__ out, int N, int O)
{
    int warp = (blockIdx.x * blockDim.x + threadIdx.x) >> 5;
    int lane = threadIdx.x & 31;
    if (warp >= N) return;
    const int beg = v_rowptr[warp];
    const int end = v_rowptr[warp + 1];
    const int deg = end - beg;

    float acc[4];
#pragma unroll
    for (int k = 0; k < 4; k++) acc[k] = 0.f;

    int j = beg;
    for (; j + 2 <= end; j += 2) {
        int e0 = vE[j], e1 = vE[j + 1];
        uint2 u0 = __ldg(reinterpret_cast<const uint2*>(Ye + (size_t)e0 * O) + lane);
        uint2 u1 = __ldg(reinterpret_cast<const uint2*>(Ye + (size_t)e1 * O) + lane);
        const __half2* h0 = reinterpret_cast<const __half2*>(&u0);
        const __half2* h1 = reinterpret_cast<const __half2*>(&u1);
        float2 a0 = __half22float2(h0[0]), a1 = __half22float2(h0[1]);
        float2 b0 = __half22float2(h1[0]), b1 = __half22float2(h1[1]);
        acc[0] += a0.x + b0.x; acc[1] += a0.y + b0.y;
        acc[2] += a1.x + b1.x; acc[3] += a1.y + b1.y;
    }
    if (j < end) {
        int e = vE[j];
        uint2 u = __ldg(reinterpret_cast<const uint2*>(Ye + (size_t)e * O) + lane);
        const __half2* h = reinterpret_cast<const __half2*>(&u);
        float2 f0 = __half22float2(h[0]), f1 = __half22float2(h[1]);
        acc[0] += f0.x; acc[1] += f0.y; acc[2] += f1.x; acc[3] += f1.y;
    }
    float dinv = (deg > 0) ? rsqrtf((float)deg) : 0.f;

    float4 o;
    o.x = acc[0] * dinv; o.y = acc[1] * dinv;
    o.z = acc[2] * dinv; o.w = acc[3] * dinv;
    *(reinterpret_cast<float4*>(out + (size_t)warp * O) + lane) = o;
}

// ---------------------------------------------------------------------------
// Host
// ---------------------------------------------------------------------------
static inline int ceil_div(int a, int b) { return (a + b - 1) / b; }

extern "C" void kernel_launch(void* const* d_in, const int* in_sizes, int n_in,
                              void* d_out, int out_size)
{
    const float* X   = (const float*)d_in[0];
    const int*   V   = (const int*)  d_in[1];
    const int*   E   = (const int*)  d_in[2];
    const float* S   = (const float*)d_in[3];
    const float* Wx0 = (const float*)d_in[4];
    const float* bx0 = (const float*)d_in[5];
    const float* Wv0 = (const float*)d_in[6];
    const float* bv0 = (const float*)d_in[7];
    const float* a0  = (const float*)d_in[8];
    const float* Wt0 = (const float*)d_in[9];
    const float* bt0 = (const float*)d_in[10];
    const float* Wx1 = (const float*)d_in[11];
    const float* bx1 = (const float*)d_in[12];
    const float* Wv1 = (const float*)d_in[13];
    const float* bv1 = (const float*)d_in[14];
    const float* a1  = (const float*)d_in[15];
    const float* Wt1 = (const float*)d_in[16];
    const float* bt1 = (const float*)d_in[17];
    const float* Wf  = (const float*)d_in[18];
    const float* bf  = (const float*)d_in[19];

    const int H    = in_sizes[5];              // 256
    const int IN   = in_sizes[4] / H;          // 128
    const int N    = in_sizes[0] / IN;         // 50000
    const int NNZ  = in_sizes[1];              // 400000
    const int HS   = in_sizes[9] / H;          // 320
    const int STAR = HS - H;                   // 64
    const int M    = in_sizes[3] / STAR;       // 20000
    const int OUT  = in_sizes[19];             // 128

    void* p;
    cudaGetSymbolAddress(&p, g_Xinit); float* Xinit = (float*)p;
    cudaGetSymbolAddress(&p, g_score); float* score = (float*)p;
    cudaGetSymbolAddress(&p, g_Xfeat); __half* Xfeat = (__half*)p;
    cudaGetSymbolAddress(&p, g_Ye2);   __half* Ye2   = (__half*)p;
    cudaGetSymbolAddress(&p, g_A);  __half* Abuf = (__half*)p;
    cudaGetSymbolAddress(&p, g_B);  __half* Bbuf = (__half*)p;
    cudaGetSymbolAddress(&p, g_Ye); __half* Yeh  = (__half*)p;
    cudaGetSymbolAddress(&p, g_S);  __half* Sh   = (__half*)p;
    cudaGetSymbolAddress(&p, g_Wh); __half* Wh   = (__half*)p;
    cudaGetSymbolAddress(&p, g_e_rowptr); int* e_rowptr = (int*)p;
    cudaGetSymbolAddress(&p, g_v_rowptr); int* v_rowptr = (int*)p;
    cudaGetSymbolAddress(&p, g_e_cursor); int* e_cursor = (int*)p;
    cudaGetSymbolAddress(&p, g_v_cursor); int* v_cursor = (int*)p;
    cudaGetSymbolAddress(&p, g_cntE);     int* cntE     = (int*)p;
    cudaGetSymbolAddress(&p, g_cntV);     int* cntV     = (int*)p;
    cudaGetSymbolAddress(&p, g_eV);       int* eV       = (int*)p;
    cudaGetSymbolAddress(&p, g_vE);       int* vE       = (int*)p;

    // one-time init (first call = correctness run, NOT under graph capture)
    static bool inited = false;
    static cudaStream_t s1 = 0, s2 = 0;
    static cudaEvent_t evFork, eW01, eWall, eCsr, eG1a, eX0, eG1b, eX1;
    if (!inited) {
        cudaFuncSetAttribute(gemm_fp16<false>, cudaFuncAttributeMaxDynamicSharedMemorySize, GEMM_SMEM);
        cudaFuncSetAttribute(gemm_fp16<true>,  cudaFuncAttributeMaxDynamicSharedMemorySize, GEMM_SMEM);
        if (cudaStreamCreateWithFlags(&s1, cudaStreamNonBlocking) != cudaSuccess) s1 = 0;
        if (cudaStreamCreateWithFlags(&s2, cudaStreamNonBlocking) != cudaSuccess) s2 = 0;
        cudaEventCreateWithFlags(&evFork, cudaEventDisableTiming);
        cudaEventCreateWithFlags(&eW01,  cudaEventDisableTiming);
        cudaEventCreateWithFlags(&eWall, cudaEventDisableTiming);
        cudaEventCreateWithFlags(&eCsr,  cudaEventDisableTiming);
        cudaEventCreateWithFlags(&eG1a,  cudaEventDisableTiming);
        cudaEventCreateWithFlags(&eX0,   cudaEventDisableTiming);
        cudaEventCreateWithFlags(&eG1b,  cudaEventDisableTiming);
        cudaEventCreateWithFlags(&eX1,   cudaEventDisableTiming);
        inited = true;
    }

    // weight offsets ([K,N] row-major, packed)
    const size_t o_wx0 = 0;
    const size_t o_wv0 = o_wx0 + (size_t)IN * H;
    const size_t o_wt0 = o_wv0 + (size_t)IN * H;
    const size_t o_wx1 = o_wt0 + (size_t)HS * H;
    const size_t o_wv1 = o_wx1 + (size_t)H * H;
    const size_t o_wt1 = o_wv1 + (size_t)H * H;
    const size_t o_wf  = o_wt1 + (size_t)HS * H;

    auto tohalf = [&](const float* src, __half* dst, long nelem, cudaStream_t st) {
        long n4 = nelem / 4;
        int blocks = (int)((n4 + 255) / 256); if (blocks > 2048) blocks = 2048;
        tohalf_kernel<<<blocks, 256, 0, st>>>(src, dst, n4);
    };

    auto gemmF = [&](const __half* a1, int K1,
                     size_t woff, const float* bias, float* C, int Mrows, int Ncols,
                     cudaStream_t st) {
        dim3 grid(Ncols / 128, ceil_div(Mrows, 128));
        gemm_fp16<false><<<grid, 256, GEMM_SMEM, st>>>(a1, K1, nullptr, 0,
            Wh + woff, bias, C, nullptr, nullptr, nullptr, Mrows, Ncols);
    };
    auto gemmH = [&](const __half* a1, int K1, const __half* a2, int K2,
                     size_t woff, const float* bias, __half* C, int Mrows, int Ncols,
                     const float* avec, float* sc, cudaStream_t st) {
        dim3 grid(Ncols / 128, ceil_div(Mrows, 128));
        gemm_fp16<true><<<grid, 256, GEMM_SMEM, st>>>(a1, K1, a2, K2,
            Wh + woff, bias, nullptr, C, avec, sc, Mrows, Ncols);
    };

    const int nnzBlocks      = ceil_div(NNZ, 256);
    const int edgeWarpBlocks = ceil_div(M, 8);
    const int nodeWarpBlocks = ceil_div(N, 8);

    // ---- fork ----
    cudaEventRecord(evFork, 0);
    cudaStreamWaitEvent(s1, evFork, 0);
    cudaStreamWaitEvent(s2, evFork, 0);

    // ---- s2: weight conversions + S conversion + score zero (layer 0) ----
    fill_float<<<ceil_div(N, 256), 256, 0, s2>>>(score, 0.f, N);
    tohalf(Wv0, Wh + o_wv0, (long)IN * H, s2);
    tohalf(Wx0, Wh + o_wx0, (long)IN * H, s2);
    cudaEventRecord(eW01, s2);
    tohalf(Wt0, Wh + o_wt0, (long)HS * H, s2);
    tohalf(Wx1, Wh + o_wx1, (long)H * H,  s2);
    tohalf(Wv1, Wh + o_wv1, (long)H * H,  s2);
    tohalf(Wt1, Wh + o_wt1, (long)HS * H, s2);
    tohalf(Wf,  Wh + o_wf,  (long)H * OUT, s2);
    tohalf(S, Sh, (long)M * STAR, s2);
    cudaEventRecord(eWall, s2);

    // ---- s1: CSR build ----
    fill_int<<<ceil_div(M, 256), 256, 0, s1>>>(cntE, 0, M);
    fill_int<<<ceil_div(N, 256), 256, 0, s1>>>(cntV, 0, N);
    count_kernel<<<nnzBlocks, 256, 0, s1>>>(V, E, cntV, cntE, NNZ);
    scan_kernel<<<1, 1024, 0, s1>>>(cntE, e_rowptr, e_cursor, M);
    scan_kernel<<<1, 1024, 0, s1>>>(cntV, v_rowptr, v_cursor, N);
    fill_lists_kernel<<<nnzBlocks, 256, 0, s1>>>(V, E, e_cursor, v_cursor, eV, vE, NNZ);
    cudaEventRecord(eCsr, s1);

    // ---- s0: convert X, then layer 0 ----
    tohalf(X, Abuf, (long)N * IN, 0);
    cudaStreamWaitEvent(0, eW01, 0);
    gemmH(Abuf, IN, nullptr, 0, o_wv0, bv0, Xfeat, N, H, a0, score, 0);   // Wv0 + fused score
    cudaEventRecord(eG1a, 0);

    // s1: Xinit GEMM overlapped with v2e/Wt-GEMM
    cudaStreamWaitEvent(s1, eG1a, 0);
    gemmF(Abuf, IN, o_wx0, bx0, Xinit, N, H, s1);
    cudaEventRecord(eX0, s1);

    cudaStreamWaitEvent(0, eCsr, 0);
    cudaStreamWaitEvent(0, eWall, 0);
    v2e_softmax_kernel<<<edgeWarpBlocks, 256>>>(Xfeat, score, e_rowptr, eV, Yeh, M, H);
    fill_float<<<ceil_div(N, 256), 256>>>(score, 0.f, N);   // re-zero for layer 1
    gemmH(Yeh, H, Sh, STAR, o_wt0, bt0, Ye2, M, H, nullptr, nullptr, 0);
    cudaStreamWaitEvent(0, eX0, 0);
    e2v_mean_kernel<<<nodeWarpBlocks, 256>>>(Ye2, v_rowptr, vE, Xinit, Bbuf, N, H);

    // ---- layer 1 ----
    gemmH(Bbuf, H, nullptr, 0, o_wv1, bv1, Xfeat, N, H, a1, score, 0);    // Wv1 + fused score
    cudaEventRecord(eG1b, 0);

    cudaStreamWaitEvent(s1, eG1b, 0);
    gemmF(Bbuf, H, o_wx1, bx1, Xinit, N, H, s1);
    cudaEventRecord(eX1, s1);

    v2e_softmax_kernel<<<edgeWarpBlocks, 256>>>(Xfeat, score, e_rowptr, eV, Yeh, M, H);
    gemmH(Yeh, H, Sh, STAR, o_wt1, bt1, Ye2, M, H, nullptr, nullptr, 0);
    cudaStreamWaitEvent(0, eX1, 0);
    e2v_mean_kernel<<<nodeWarpBlocks, 256>>>(Ye2, v_rowptr, vE, Xinit, Abuf, N, H);

    // ---- hyperconv (s0) ----
    gemmH(Abuf, H, nullptr, 0, o_wf, bf, Xfeat, N, OUT, nullptr, nullptr, 0);
    hyper_edge_kernel<<<edgeWarpBlocks, 256>>>(Xfeat, e_rowptr, eV, v_rowptr, Yeh, M, OUT);
    hyper_node_kernel<<<nodeWarpBlocks, 256>>>(Yeh, v_rowptr, vE, (float*)d_out, N, OUT);
}

// round 11
// speedup vs baseline: 6.1952x; 1.0904x over previous
#include <cuda_runtime.h>
#include <cuda_fp16.h>
#include <mma.h>
#include <math.h>
#include <stdint.h>

using namespace nvcuda;

// ---------------------------------------------------------------------------
// Problem max sizes
// ---------------------------------------------------------------------------
#define NMAX   50000
#define MMAX   20000
#define NNZMAX 400000
#define HMAX   256
#define WTOTAL 393216

// ---------------------------------------------------------------------------
// Scratch (device globals)
// ---------------------------------------------------------------------------
__device__ float g_score0[NMAX];
__device__ float g_score1[NMAX];

__device__ __half g_Xinit[NMAX * HMAX];  // fp16 residual
__device__ __half g_Xfeat[NMAX * HMAX];  // fp16 GEMM outputs (Wv / Wf)
__device__ __half g_Ye2  [MMAX * HMAX];  // fp16 GEMM output (Wt)
__device__ __half g_A [NMAX * HMAX];     // activations (X / h2)
__device__ __half g_B [NMAX * HMAX];     // h1
__device__ __half g_Ye[MMAX * HMAX];     // v2e out / hyper_edge out
__device__ __half g_S [MMAX * 64];
__device__ __half g_Wh[WTOTAL];          // weights fp16, [K,N] row-major packed

// CSR structures
__device__ int g_e_rowptr[MMAX + 1];
__device__ int g_v_rowptr[NMAX + 1];
__device__ int g_e_cursor[MMAX];
__device__ int g_v_cursor[NMAX];
__device__ int g_cntE[MMAX];
__device__ int g_cntV[NMAX];
__device__ int g_eV[NNZMAX];
__device__ int g_vE[NNZMAX];

// ---------------------------------------------------------------------------
// Helpers
// ---------------------------------------------------------------------------
__device__ __forceinline__ float eluf(float x)  { return x > 0.f ? x : expm1f(x); }
__device__ __forceinline__ float leakyf(float x){ return x > 0.f ? x : 0.2f * x; }

__device__ __forceinline__ uint32_t smem_to_u32(const void* p) {
    uint32_t a;
    asm("{ .reg .u64 t; cvta.to.shared.u64 t, %1; cvt.u32.u64 %0, t; }" : "=r"(a) : "l"(p));
    return a;
}
__device__ __forceinline__ void cp_async16(uint32_t dst, const void* src, int sz) {
    asm volatile("cp.async.cg.shared.global [%0], [%1], 16, %2;"
                 :: "r"(dst), "l"(src), "r"(sz) : "memory");
}
#define CP_COMMIT() asm volatile("cp.async.commit_group;" ::: "memory")
#define CP_WAIT(n)  asm volatile("cp.async.wait_group %0;" :: "n"(n) : "memory")

__device__ __forceinline__ void conv_store4(float4 v, __half* p) {
    __half2 h0 = __floats2half2_rn(v.x, v.y);
    __half2 h1 = __floats2half2_rn(v.z, v.w);
    uint2 u;
    u.x = *reinterpret_cast<unsigned*>(&h0);
    u.y = *reinterpret_cast<unsigned*>(&h1);
    *reinterpret_cast<uint2*>(p) = u;
}

// activations: fp32 -> fp16 (X only; weights go through conv_pack_kernel)
__global__ void tohalf_kernel(const float* __restrict__ x, __half* __restrict__ out, long n4)
{
    long i = (long)blockIdx.x * blockDim.x + threadIdx.x;
    long stride = (long)gridDim.x * blockDim.x;
    for (; i < n4; i += stride)
        conv_store4(reinterpret_cast<const float4*>(x)[i], out + 4 * i);
}

// one kernel: 8 fp32->fp16 conversions + zero both score buffers
struct ConvJob { const float* src; __half* dst; long n4; };
struct ConvJobs {
    ConvJob j[8];
    float* sc0; float* sc1; int n_sc;
};
__global__ void conv_pack_kernel(ConvJobs jobs)
{
    int job = blockIdx.y;
    long i = (long)blockIdx.x * blockDim.x + threadIdx.x;
    long stride = (long)gridDim.x * blockDim.x;
    if (job < 8) {
        const float* src = jobs.j[job].src;
        __half* dst = jobs.j[job].dst;
        long n4 = jobs.j[job].n4;
        for (; i < n4; i += stride)
            conv_store4(reinterpret_cast<const float4*>(src)[i], dst + 4 * i);
    } else {
        for (; i < jobs.n_sc; i += stride) {
            jobs.sc0[i] = 0.f;
            jobs.sc1[i] = 0.f;
        }
    }
}

// zero both CSR count arrays in one kernel
__global__ void fill2_int(int* __restrict__ p0, int n0, int* __restrict__ p1, int n1)
{
    int i = blockIdx.x * blockDim.x + threadIdx.x;
    int stride = gridDim.x * blockDim.x;
    for (int k = i; k < n0; k += stride) p0[k] = 0;
    for (int k = i; k < n1; k += stride) p1[k] = 0;
}

// ---------------------------------------------------------------------------
// CSR construction
// ---------------------------------------------------------------------------
__global__ void count_kernel(const int* __restrict__ V, const int* __restrict__ E,
                             int* __restrict__ cntV, int* __restrict__ cntE, int nnz)
{
    int i = blockIdx.x * blockDim.x + threadIdx.x;
    if (i >= nnz) return;
    atomicAdd(&cntE[E[i]], 1);
    atomicAdd(&cntV[V[i]], 1);
}

__device__ void scan_body(const int* __restrict__ cnt, int* __restrict__ rowptr,
                          int* __restrict__ cursor, int len)
{
    __shared__ int wsum[32];
    __shared__ int s_carry;
    const int tid = threadIdx.x, lane = tid & 31, wid = tid >> 5;
    if (tid == 0) s_carry = 0;
    __syncthreads();

    for (int base = 0; base < len; base += 4096) {
        int i0 = base + tid * 4;
        int v0 = (i0 + 0 < len) ? cnt[i0 + 0] : 0;
        int v1 = (i0 + 1 < len) ? cnt[i0 + 1] : 0;
        int v2 = (i0 + 2 < len) ? cnt[i0 + 2] : 0;
        int v3 = (i0 + 3 < len) ? cnt[i0 + 3] : 0;
        int t1 = v0 + v1, t2 = t1 + v2, t3 = t2 + v3;

        int inc = t3;
#pragma unroll
        for (int o = 1; o < 32; o <<= 1) {
            int u = __shfl_up_sync(0xffffffffu, inc, o);
            if (lane >= o) inc += u;
        }
        if (lane == 31) wsum[wid] = inc;
        __syncthreads();
        if (wid == 0) {
            int w = wsum[lane];
            int wi = w;
#pragma unroll
            for (int o = 1; o < 32; o <<= 1) {
                int u = __shfl_up_sync(0xffffffffu, wi, o);
                if (lane >= o) wi += u;
            }
            wsum[lane] = wi - w;
        }
        __syncthreads();
        int excl = s_carry + wsum[wid] + (inc - t3);
        if (i0 + 0 < len) { rowptr[i0 + 0] = excl;      cursor[i0 + 0] = excl; }
        if (i0 + 1 < len) { rowptr[i0 + 1] = excl + v0; cursor[i0 + 1] = excl + v0; }
        if (i0 + 2 < len) { rowptr[i0 + 2] = excl + t1; cursor[i0 + 2] = excl + t1; }
        if (i0 + 3 < len) { rowptr[i0 + 3] = excl + t2; cursor[i0 + 3] = excl + t2; }
        __syncthreads();
        if (tid == 1023) s_carry = s_carry + wsum[31] + inc;
        __syncthreads();
    }
    if (threadIdx.x == 0) rowptr[len] = s_carry;
}

// both scans in one launch (block 0: edges, block 1: nodes)
__global__ __launch_bounds__(1024)
void scan2_kernel(const int* cntE, int* e_rowptr, int* e_cursor, int lenE,
                  const int* cntV, int* v_rowptr, int* v_cursor, int lenV)
{
    if (blockIdx.x == 0) scan_body(cntE, e_rowptr, e_cursor, lenE);
    else                 scan_body(cntV, v_rowptr, v_cursor, lenV);
}

__global__ void fill_lists_kernel(const int* __restrict__ V, const int* __restrict__ E,
                                  int* __restrict__ e_cursor, int* __restrict__ v_cursor,
                                  int* __restrict__ eV, int* __restrict__ vE, int nnz)
{
    int i = blockIdx.x * blockDim.x + threadIdx.x;
    if (i >= nnz) return;
    int v = V[i], e = E[i];
    int pe = atomicAdd(&e_cursor[e], 1);
    eV[pe] = v;
    int pv = atomicAdd(&v_cursor[v], 1);
    vE[pv] = e;
}

// ---------------------------------------------------------------------------
// fp16 tensor-core GEMM (fp16 weights, fp16 out), cp.async double buffered.
// C[M,N] = [A1|A2] @ W + bias.
// Optional fused row-score: score[r] += dot(C_row_fp32, avec) (atomic).
// ---------------------------------------------------------------------------
struct GemmStage {
    __half A[128][40];
    __half B[32][136];
};
static constexpr int GEMM_SMEM = 2 * sizeof(GemmStage);   // 37888

__global__ __launch_bounds__(256, 2)
void gemm_fp16(const __half* __restrict__ A1, int K1,
               const __half* __restrict__ A2, int K2,
               const __half* __restrict__ Bg,
               const float* __restrict__ bias,
               __half* __restrict__ Ch,
               const float* __restrict__ avec, float* __restrict__ score_out,
               int M, int N)
{
    extern __shared__ char smem_raw[];
    GemmStage* st = reinterpret_cast<GemmStage*>(smem_raw);

    const int tid  = threadIdx.x;
    const int wid  = tid >> 5, lane = tid & 31;
    const int wm   = wid >> 1, wn = wid & 1;
    const int row0 = blockIdx.y * 128;
    const int col0 = blockIdx.x * 128;
    const int K = K1 + K2, nch = K >> 5;

    wmma::fragment<wmma::accumulator, 16, 16, 16, float> acc[2][4];
#pragma unroll
    for (int mt = 0; mt < 2; mt++)
#pragma unroll
        for (int nt = 0; nt < 4; nt++) wmma::fill_fragment(acc[mt][nt], 0.f);

    auto prefetch = [&](int c, int s) {
        const int k0 = c * 32;
        const __half* a; int lda, col;
        if (k0 < K1) { a = A1; lda = K1; col = k0; }
        else         { a = A2; lda = K2; col = k0 - K1; }
#pragma unroll
        for (int t = 0; t < 2; t++) {
            int u = tid + t * 256, r = u >> 2, q = u & 3;
            int gr = row0 + r;
            int sz = (gr < M) ? 16 : 0;
            size_t off = (size_t)(gr < M ? gr : 0) * lda + col + q * 8;
            cp_async16(smem_to_u32(&st[s].A[r][q * 8]), a + off, sz);
        }
#pragma unroll
        for (int t = 0; t < 2; t++) {
            int u = tid + t * 256, r = u >> 4, q = u & 15;
            size_t off = (size_t)(k0 + r) * N + col0 + q * 8;
            cp_async16(smem_to_u32(&st[s].B[r][q * 8]), Bg + off, 16);
        }
    };

    prefetch(0, 0);
    CP_COMMIT();

    for (int c = 0; c < nch; c++) {
        const int s = c & 1;
        if (c + 1 < nch) {
            prefetch(c + 1, s ^ 1);
            CP_COMMIT();
            CP_WAIT(1);
        } else {
            CP_WAIT(0);
        }
        __syncthreads();

#pragma unroll
        for (int ks = 0; ks < 2; ks++) {
            wmma::fragment<wmma::matrix_a, 16, 16, 16, __half, wmma::row_major> af[2];
#pragma unroll
            for (int mt = 0; mt < 2; mt++)
                wmma::load_matrix_sync(af[mt], &st[s].A[wm * 32 + mt * 16][ks * 16], 40);
#pragma unroll
            for (int nt = 0; nt < 4; nt++) {
                wmma::fragment<wmma::matrix_b, 16, 16, 16, __half, wmma::row_major> bf;
                wmma::load_matrix_sync(bf, &st[s].B[ks * 16][wn * 64 + nt * 16], 136);
#pragma unroll
                for (int mt = 0; mt < 2; mt++)
                    wmma::mma_sync(acc[mt][nt], af[mt], bf, acc[mt][nt]);
            }
        }
        __syncthreads();
    }

    // epilogue: stage 16x16 tiles in smem, add bias, optional score, store fp16
    float* stg = reinterpret_cast<float*>(smem_raw) + wid * 320;
#pragma unroll
    for (int mt = 0; mt < 2; mt++) {
        float sacc = 0.f;
        int grow_last = -1;
#pragma unroll
        for (int nt = 0; nt < 4; nt++) {
            wmma::store_matrix_sync(stg, acc[mt][nt], 20, wmma::mem_row_major);
            __syncwarp();
            int r = lane >> 1, cofs = (lane & 1) * 8;
            int gr = row0 + wm * 32 + mt * 16 + r;
            int gc = col0 + wn * 64 + nt * 16 + cofs;
            grow_last = gr;
            if (gr < M) {
                float o[8];
#pragma unroll
                for (int j = 0; j < 8; j++) o[j] = stg[r * 20 + cofs + j] + __ldg(&bias[gc + j]);
                if (score_out) {
#pragma unroll
                    for (int j = 0; j < 8; j++) sacc += o[j] * __ldg(&avec[gc + j]);
                }
                uint4 u;
                __half2 p0 = __floats2half2_rn(o[0], o[1]);
                __half2 p1 = __floats2half2_rn(o[2], o[3]);
                __half2 p2 = __floats2half2_rn(o[4], o[5]);
                __half2 p3 = __floats2half2_rn(o[6], o[7]);
                u.x = *reinterpret_cast<unsigned*>(&p0);
                u.y = *reinterpret_cast<unsigned*>(&p1);
                u.z = *reinterpret_cast<unsigned*>(&p2);
                u.w = *reinterpret_cast<unsigned*>(&p3);
                *reinterpret_cast<uint4*>(Ch + (size_t)gr * N + gc) = u;
            }
            __syncwarp();
        }
        if (score_out && grow_last >= 0 && grow_last < M)
            atomicAdd(&score_out[grow_last], sacc);
    }
}

// ---------------------------------------------------------------------------
// Fused v2e: segment softmax + weighted fp16 gather + elu -> fp16 out
// Member loop unrolled x4.
// ---------------------------------------------------------------------------
__global__ __launch_bounds__(256)
void v2e_softmax_kernel(const __half* __restrict__ Xfeat, const float* __restrict__ score,
                        const int* __restrict__ e_rowptr, const int* __restrict__ eV,
                        __half* __restrict__ Ye, int M, int H)
{
    int warp = (blockIdx.x * blockDim.x + threadIdx.x) >> 5;
    int lane = threadIdx.x & 31;
    if (warp >= M) return;
    const int beg = e_rowptr[warp];
    const int end = e_rowptr[warp + 1];

    float m = -1e30f;
    for (int j = beg + lane; j < end; j += 32)
        m = fmaxf(m, leakyf(__ldg(&score[eV[j]])));
#pragma unroll
    for (int o = 16; o > 0; o >>= 1) m = fmaxf(m, __shfl_xor_sync(0xffffffffu, m, o));

    float den = 0.f;
    for (int j = beg + lane; j < end; j += 32)
        den += expf(leakyf(__ldg(&score[eV[j]])) - m);
#pragma unroll
    for (int o = 16; o > 0; o >>= 1) den += __shfl_xor_sync(0xffffffffu, den, o);
    float invden = (end > beg) ? 1.f / den : 0.f;

    float acc[8];
#pragma unroll
    for (int k = 0; k < 8; k++) acc[k] = 0.f;

    int j = beg;
    for (; j + 4 <= end; j += 4) {
        int v0 = eV[j], v1 = eV[j + 1], v2 = eV[j + 2], v3 = eV[j + 3];
        float w0 = expf(leakyf(__ldg(&score[v0])) - m) * invden;
        float w1 = expf(leakyf(__ldg(&score[v1])) - m) * invden;
        float w2 = expf(leakyf(__ldg(&score[v2])) - m) * invden;
        float w3 = expf(leakyf(__ldg(&score[v3])) - m) * invden;
        uint4 u0 = __ldg(reinterpret_cast<const uint4*>(Xfeat + (size_t)v0 * H) + lane);
        uint4 u1 = __ldg(reinterpret_cast<const uint4*>(Xfeat + (size_t)v1 * H) + lane);
        uint4 u2 = __ldg(reinterpret_cast<const uint4*>(Xfeat + (size_t)v2 * H) + lane);
        uint4 u3 = __ldg(reinterpret_cast<const uint4*>(Xfeat + (size_t)v3 * H) + lane);
        const __half2* h0 = reinterpret_cast<const __half2*>(&u0);
        const __half2* h1 = reinterpret_cast<const __half2*>(&u1);
        const __half2* h2 = reinterpret_cast<const __half2*>(&u2);
        const __half2* h3 = reinterpret_cast<const __half2*>(&u3);
#pragma unroll
        for (int k = 0; k < 4; k++) {
            float2 f0 = __half22float2(h0[k]);
            float2 f1 = __half22float2(h1[k]);
            float2 f2 = __half22float2(h2[k]);
            float2 f3 = __half22float2(h3[k]);
            acc[2 * k + 0] = fmaf(f0.x, w0, fmaf(f1.x, w1, fmaf(f2.x, w2, fmaf(f3.x, w3, acc[2 * k + 0]))));
            acc[2 * k + 1] = fmaf(f0.y, w0, fmaf(f1.y, w1, fmaf(f2.y, w2, fmaf(f3.y, w3, acc[2 * k + 1]))));
        }
    }
    for (; j < end; j++) {
        int v = eV[j];
        float w = expf(leakyf(__ldg(&score[v])) - m) * invden;
        uint4 u = __ldg(reinterpret_cast<const uint4*>(Xfeat + (size_t)v * H) + lane);
        const __half2* h = reinterpret_cast<const __half2*>(&u);
#pragma unroll
        for (int k = 0; k < 4; k++) {
            float2 f = __half22float2(h[k]);
            acc[2 * k + 0] = fmaf(f.x, w, acc[2 * k + 0]);
            acc[2 * k + 1] = fmaf(f.y, w, acc[2 * k + 1]);
        }
    }

    uint4 u;
    __half2 p0 = __floats2half2_rn(eluf(acc[0]), eluf(acc[1]));
    __half2 p1 = __floats2half2_rn(eluf(acc[2]), eluf(acc[3]));
    __half2 p2 = __floats2half2_rn(eluf(acc[4]), eluf(acc[5]));
    __half2 p3 = __floats2half2_rn(eluf(acc[6]), eluf(acc[7]));
    u.x = *reinterpret_cast<unsigned*>(&p0);
    u.y = *reinterpret_cast<unsigned*>(&p1);
    u.z = *reinterpret_cast<unsigned*>(&p2);
    u.w = *reinterpret_cast<unsigned*>(&p3);
    *(reinterpret_cast<uint4*>(Ye + (size_t)warp * H) + lane) = u;
}

// ---------------------------------------------------------------------------
// Fused e2v: mean (fp16 gather, x4) + elu + residual (fp16) -> fp16 out
// ---------------------------------------------------------------------------
__global__ __launch_bounds__(256)
void e2v_mean_kernel(const __half* __restrict__ Ye2,
                     const int* __restrict__ v_rowptr, const int* __restrict__ vE,
                     const __half* __restrict__ Xinit,
                     __half* __restrict__ hout, int N, int H)
{
    int warp = (blockIdx.x * blockDim.x + threadIdx.x) >> 5;
    int lane = threadIdx.x & 31;
    if (warp >= N) return;
    const int beg = v_rowptr[warp];
    const int end = v_rowptr[warp + 1];

    float acc[8];
#pragma unroll
    for (int k = 0; k < 8; k++) acc[k] = 0.f;

    int j = beg;
    for (; j + 4 <= end; j += 4) {
        int e0 = vE[j], e1 = vE[j + 1], e2 = vE[j + 2], e3 = vE[j + 3];
        uint4 u0 = __ldg(reinterpret_cast<const uint4*>(Ye2 + (size_t)e0 * H) + lane);
        uint4 u1 = __ldg(reinterpret_cast<const uint4*>(Ye2 + (size_t)e1 * H) + lane);
        uint4 u2 = __ldg(reinterpret_cast<const uint4*>(Ye2 + (size_t)e2 * H) + lane);
        uint4 u3 = __ldg(reinterpret_cast<const uint4*>(Ye2 + (size_t)e3 * H) + lane);
        const __half2* h0 = reinterpret_cast<const __half2*>(&u0);
        const __half2* h1 = reinterpret_cast<const __half2*>(&u1);
        const __half2* h2 = reinterpret_cast<const __half2*>(&u2);
        const __half2* h3 = reinterpret_cast<const __half2*>(&u3);
#pragma unroll
        for (int k = 0; k < 4; k++) {
            float2 f0 = __half22float2(h0[k]);
            float2 f1 = __half22float2(h1[k]);
            float2 f2 = __half22float2(h2[k]);
            float2 f3 = __half22float2(h3[k]);
            acc[2 * k + 0] += (f0.x + f1.x) + (f2.x + f3.x);
            acc[2 * k + 1] += (f0.y + f1.y) + (f2.y + f3.y);
        }
    }
    for (; j < end; j++) {
        int e = vE[j];
        uint4 u = __ldg(reinterpret_cast<const uint4*>(Ye2 + (size_t)e * H) + lane);
        const __half2* h = reinterpret_cast<const __half2*>(&u);
#pragma unroll
        for (int k = 0; k < 4; k++) {
            float2 f = __half22float2(h[k]);
            acc[2 * k + 0] += f.x;
            acc[2 * k + 1] += f.y;
        }
    }
    float inv = (end > beg) ? 1.f / (float)(end - beg) : 0.f;

    uint4 ri = __ldg(reinterpret_cast<const uint4*>(Xinit + (size_t)warp * H) + lane);
    const __half2* rh = reinterpret_cast<const __half2*>(&ri);
    float o[8];
#pragma unroll
    for (int k = 0; k < 4; k++) {
        float2 r = __half22float2(rh[k]);
        o[2 * k + 0] = eluf(acc[2 * k + 0] * inv) + r.x;
        o[2 * k + 1] = eluf(acc[2 * k + 1] * inv) + r.y;
    }

    uint4 u;
    __half2 p0 = __floats2half2_rn(o[0], o[1]);
    __half2 p1 = __floats2half2_rn(o[2], o[3]);
    __half2 p2 = __floats2half2_rn(o[4], o[5]);
    __half2 p3 = __floats2half2_rn(o[6], o[7]);
    u.x = *reinterpret_cast<unsigned*>(&p0);
    u.y = *reinterpret_cast<unsigned*>(&p1);
    u.z = *reinterpret_cast<unsigned*>(&p2);
    u.w = *reinterpret_cast<unsigned*>(&p3);
    *(reinterpret_cast<uint4*>(hout + (size_t)warp * H) + lane) = u;
}

// ---------------------------------------------------------------------------
// Hyperconv edge: fp16 gather (x4), fp16 out.  O == 128.
// ---------------------------------------------------------------------------
__global__ __launch_bounds__(256)
void hyper_edge_kernel(const __half* __restrict__ Xn,
                       const int* __restrict__ e_rowptr, const int* __restrict__ eV,
                       const int* __restrict__ v_rowptr,
                       __half* __restrict__ Ye, int M, int O)
{
    int warp = (blockIdx.x * blockDim.x + threadIdx.x) >> 5;
    int lane = threadIdx.x & 31;
    if (warp >= M) return;
    const int beg = e_rowptr[warp];
    const int end = e_rowptr[warp + 1];
    const int cnt = end - beg;

    float sumDv = 0.f;
    for (int j = beg + lane; j < end; j += 32) {
        int v = eV[j];
        sumDv += (float)(__ldg(&v_rowptr[v + 1]) - __ldg(&v_rowptr[v]));
    }
#pragma unroll
    for (int o = 16; o > 0; o >>= 1) sumDv += __shfl_xor_sync(0xffffffffu, sumDv, o);

    float acc[4];
#pragma unroll
    for (int k = 0; k < 4; k++) acc[k] = 0.f;

    int j = beg;
    for (; j + 4 <= end; j += 4) {
        int v0 = eV[j], v1 = eV[j + 1], v2 = eV[j + 2], v3 = eV[j + 3];
        uint2 u0 = __ldg(reinterpret_cast<const uint2*>(Xn + (size_t)v0 * O) + lane);
        uint2 u1 = __ldg(reinterpret_cast<const uint2*>(Xn + (size_t)v1 * O) + lane);
        uint2 u2 = __ldg(reinterpret_cast<const uint2*>(Xn + (size_t)v2 * O) + lane);
        uint2 u3 = __ldg(reinterpret_cast<const uint2*>(Xn + (size_t)v3 * O) + lane);
        const __half2* h0 = reinterpret_cast<const __half2*>(&u0);
        const __half2* h1 = reinterpret_cast<const __half2*>(&u1);
        const __half2* h2 = reinterpret_cast<const __half2*>(&u2);
        const __half2* h3 = reinterpret_cast<const __half2*>(&u3);
#pragma unroll
        for (int k = 0; k < 2; k++) {
            float2 f0 = __half22float2(h0[k]);
            float2 f1 = __half22float2(h1[k]);
            float2 f2 = __half22float2(h2[k]);
            float2 f3 = __half22float2(h3[k]);
            acc[2 * k + 0] += (f0.x + f1.x) + (f2.x + f3.x);
            acc[2 * k + 1] += (f0.y + f1.y) + (f2.y + f3.y);
        }
    }
    for (; j < end; j++) {
        int v = eV[j];
        uint2 u = __ldg(reinterpret_cast<const uint2*>(Xn + (size_t)v * O) + lane);
        const __half2* h = reinterpret_cast<const __half2*>(&u);
        float2 f0 = __half22float2(h[0]), f1 = __half22float2(h[1]);
        acc[0] += f0.x; acc[1] += f0.y; acc[2] += f1.x; acc[3] += f1.y;
    }

    float invc = (cnt > 0) ? 1.f / (float)cnt : 0.f;
    float De = sumDv / ((float)cnt + 1.f);
    float dinv = (De > 0.f) ? rsqrtf(De) : 1.f;
    float s = invc * dinv;

    uint2 u;
    __half2 p0 = __floats2half2_rn(acc[0] * s, acc[1] * s);
    __half2 p1 = __floats2half2_rn(acc[2] * s, acc[3] * s);
    u.x = *reinterpret_cast<unsigned*>(&p0);
    u.y = *reinterpret_cast<unsigned*>(&p1);
    *(reinterpret_cast<uint2*>(Ye + (size_t)warp * O) + lane) = u;
}

// ---------------------------------------------------------------------------
// Hyperconv node: fp16 gather (x4), fp32 out (final output)
// ---------------------------------------------------------------------------
__global__ __launch_bounds__(256)
void hyper_node_kernel(const __half* __restrict__ Ye,
                       const int* __restrict__ v_rowptr, const int* __restrict__ vE,
                       float* __restrict__ out, int N, int O)
{
    int warp = (blockIdx.x * blockDim.x + threadIdx.x) >> 5;
    int lane = threadIdx.x & 31;
    if (warp >= N) return;
    const int beg = v_rowptr[warp];
    const int end = v_rowptr[warp + 1];
    const int deg = end - beg;

    float acc[4];
#pragma unroll
    for (int k = 0; k < 4; k++) acc[k] = 0.f;

    int j = beg;
    for (; j + 4 <= end; j += 4) {
        int e0 = vE[j], e1 = vE[j + 1], e2 = vE[j + 2], e3 = vE[j + 3];
        uint2 u0 = __ldg(reinterpret_cast<const uint2*>(Ye + (size_t)e0 * O) + lane);
        uint2 u1 = __ldg(reinterpret_cast<const uint2*>(Ye + (size_t)e1 * O) + lane);
        uint2 u2 = __ldg(reinterpret_cast<const uint2*>(Ye + (size_t)e2 * O) + lane);
        uint2 u3 = __ldg(reinterpret_cast<const uint2*>(Ye + (size_t)e3 * O) + lane);
        const __half2* h0 = reinterpret_cast<const __half2*>(&u0);
        const __half2* h1 = reinterpret_cast<const __half2*>(&u1);
        const __half2* h2 = reinterpret_cast<const __half2*>(&u2);
        const __half2* h3 = reinterpret_cast<const __half2*>(&u3);
#pragma unroll
        for (int k = 0; k < 2; k++) {
            float2 f0 = __half22float2(h0[k]);
            float2 f1 = __half22float2(h1[k]);
            float2 f2 = __half22float2(h2[k]);
            float2 f3 = __half22float2(h3[k]);
            acc[2 * k + 0] += (f0.x + f1.x) + (f2.x + f3.x);
            acc[2 * k + 1] += (f0.y + f1.y) + (f2.y + f3.y);
        }
    }
    for (; j < end; j++) {
        int e = vE[j];
        uint2 u = __ldg(reinterpret_cast<const uint2*>(Ye + (size_t)e * O) + lane);
        const __half2* h = reinterpret_cast<const __half2*>(&u);
        float2 f0 = __half22float2(h[0]), f1 = __half22float2(h[1]);
        acc[0] += f0.x; acc[1] += f0.y; acc[2] += f1.x; acc[3] += f1.y;
    }
    float dinv = (deg > 0) ? rsqrtf((float)deg) : 0.f;

    float4 o;
    o.x = acc[0] * dinv; o.y = acc[1] * dinv;
    o.z = acc[2] * dinv; o.w = acc[3] * dinv;
    *(reinterpret_cast<float4*>(out + (size_t)warp * O) + lane) = o;
}

// ---------------------------------------------------------------------------
// Host
// ---------------------------------------------------------------------------
static inline int ceil_div(int a, int b) { return (a + b - 1) / b; }

extern "C" void kernel_launch(void* const* d_in, const int* in_sizes, int n_in,
                              void* d_out, int out_size)
{
    const float* X   = (const float*)d_in[0];
    const int*   V   = (const int*)  d_in[1];
    const int*   E   = (const int*)  d_in[2];
    const float* S   = (const float*)d_in[3];
    const float* Wx0 = (const float*)d_in[4];
    const float* bx0 = (const float*)d_in[5];
    const float* Wv0 = (const float*)d_in[6];
    const float* bv0 = (const float*)d_in[7];
    const float* a0  = (const float*)d_in[8];
    const float* Wt0 = (const float*)d_in[9];
    const float* bt0 = (const float*)d_in[10];
    const float* Wx1 = (const float*)d_in[11];
    const float* bx1 = (const float*)d_in[12];
    const float* Wv1 = (const float*)d_in[13];
    const float* bv1 = (const float*)d_in[14];
    const float* a1  = (const float*)d_in[15];
    const float* Wt1 = (const float*)d_in[16];
    const float* bt1 = (const float*)d_in[17];
    const float* Wf  = (const float*)d_in[18];
    const float* bf  = (const float*)d_in[19];

    const int H    = in_sizes[5];              // 256
    const int IN   = in_sizes[4] / H;          // 128
    const int N    = in_sizes[0] / IN;         // 50000
    const int NNZ  = in_sizes[1];              // 400000
    const int HS   = in_sizes[9] / H;          // 320
    const int STAR = HS - H;                   // 64
    const int M    = in_sizes[3] / STAR;       // 20000
    const int OUT  = in_sizes[19];             // 128

    void* p;
    cudaGetSymbolAddress(&p, g_score0); float* score0 = (float*)p;
    cudaGetSymbolAddress(&p, g_score1); float* score1 = (float*)p;
    cudaGetSymbolAddress(&p, g_Xinit); __half* Xinit = (__half*)p;
    cudaGetSymbolAddress(&p, g_Xfeat); __half* Xfeat = (__half*)p;
    cudaGetSymbolAddress(&p, g_Ye2);   __half* Ye2   = (__half*)p;
    cudaGetSymbolAddress(&p, g_A);  __half* Abuf = (__half*)p;
    cudaGetSymbolAddress(&p, g_B);  __half* Bbuf = (__half*)p;
    cudaGetSymbolAddress(&p, g_Ye); __half* Yeh  = (__half*)p;
    cudaGetSymbolAddress(&p, g_S);  __half* Sh   = (__half*)p;
    cudaGetSymbolAddress(&p, g_Wh); __half* Wh   = (__half*)p;
    cudaGetSymbolAddress(&p, g_e_rowptr); int* e_rowptr = (int*)p;
    cudaGetSymbolAddress(&p, g_v_rowptr); int* v_rowptr = (int*)p;
    cudaGetSymbolAddress(&p, g_e_cursor); int* e_cursor = (int*)p;
    cudaGetSymbolAddress(&p, g_v_cursor); int* v_cursor = (int*)p;
    cudaGetSymbolAddress(&p, g_cntE);     int* cntE     = (int*)p;
    cudaGetSymbolAddress(&p, g_cntV);     int* cntV     = (int*)p;
    cudaGetSymbolAddress(&p, g_eV);       int* eV       = (int*)p;
    cudaGetSymbolAddress(&p, g_vE);       int* vE       = (int*)p;

    // one-time init (first call = correctness run, NOT under graph capture)
    static bool inited = false;
    static cudaStream_t s1 = 0, s2 = 0;
    static cudaEvent_t evFork, eWall, eCsr, eG1a, eX0, eG1b, eX1;
    if (!inited) {
        cudaFuncSetAttribute(gemm_fp16, cudaFuncAttributeMaxDynamicSharedMemorySize, GEMM_SMEM);
        if (cudaStreamCreateWithFlags(&s1, cudaStreamNonBlocking) != cudaSuccess) s1 = 0;
        if (cudaStreamCreateWithFlags(&s2, cudaStreamNonBlocking) != cudaSuccess) s2 = 0;
        cudaEventCreateWithFlags(&evFork, cudaEventDisableTiming);
        cudaEventCreateWithFlags(&eWall, cudaEventDisableTiming);
        cudaEventCreateWithFlags(&eCsr,  cudaEventDisableTiming);
        cudaEventCreateWithFlags(&eG1a,  cudaEventDisableTiming);
        cudaEventCreateWithFlags(&eX0,   cudaEventDisableTiming);
        cudaEventCreateWithFlags(&eG1b,  cudaEventDisableTiming);
        cudaEventCreateWithFlags(&eX1,   cudaEventDisableTiming);
        inited = true;
    }

    // weight offsets ([K,N] row-major, packed)
    const size_t o_wx0 = 0;
    const size_t o_wv0 = o_wx0 + (size_t)IN * H;
    const size_t o_wt0 = o_wv0 + (size_t)IN * H;
    const size_t o_wx1 = o_wt0 + (size_t)HS * H;
    const size_t o_wv1 = o_wx1 + (size_t)H * H;
    const size_t o_wt1 = o_wv1 + (size_t)H * H;
    const size_t o_wf  = o_wt1 + (size_t)HS * H;

    auto gemm = [&](const __half* a1, int K1, const __half* a2, int K2,
                    size_t woff, const float* bias, __half* C, int Mrows, int Ncols,
                    const float* avec, float* sc, cudaStream_t st) {
        dim3 grid(Ncols / 128, ceil_div(Mrows, 128));
        gemm_fp16<<<grid, 256, GEMM_SMEM, st>>>(a1, K1, a2, K2,
            Wh + woff, bias, C, avec, sc, Mrows, Ncols);
    };

    const int nnzBlocks      = ceil_div(NNZ, 256);
    const int edgeWarpBlocks = ceil_div(M, 8);
    const int nodeWarpBlocks = ceil_div(N, 8);

    // ---- fork ----
    cudaEventRecord(evFork, 0);
    cudaStreamWaitEvent(s1, evFork, 0);
    cudaStreamWaitEvent(s2, evFork, 0);

    // ---- s2: ONE kernel for all weight/S conversions + both score zeros ----
    {
        ConvJobs jobs;
        jobs.j[0] = { Wv0, Wh + o_wv0, (long)IN * H / 4 };
        jobs.j[1] = { Wx0, Wh + o_wx0, (long)IN * H / 4 };
        jobs.j[2] = { Wt0, Wh + o_wt0, (long)HS * H / 4 };
        jobs.j[3] = { Wx1, Wh + o_wx1, (long)H * H / 4 };
        jobs.j[4] = { Wv1, Wh + o_wv1, (long)H * H / 4 };
        jobs.j[5] = { Wt1, Wh + o_wt1, (long)HS * H / 4 };
        jobs.j[6] = { Wf,  Wh + o_wf,  (long)H * OUT / 4 };
        jobs.j[7] = { S,   Sh,         (long)M * STAR / 4 };
        jobs.sc0 = score0; jobs.sc1 = score1; jobs.n_sc = N;
        dim3 grid(80, 9);
        conv_pack_kernel<<<grid, 256, 0, s2>>>(jobs);
        cudaEventRecord(eWall, s2);
    }

    // ---- s1: CSR build (4 nodes) ----
    fill2_int<<<ceil_div(N, 256), 256, 0, s1>>>(cntE, M, cntV, N);
    count_kernel<<<nnzBlocks, 256, 0, s1>>>(V, E, cntV, cntE, NNZ);
    scan2_kernel<<<2, 1024, 0, s1>>>(cntE, e_rowptr, e_cursor, M,
                                     cntV, v_rowptr, v_cursor, N);
    fill_lists_kernel<<<nnzBlocks, 256, 0, s1>>>(V, E, e_cursor, v_cursor, eV, vE, NNZ);
    cudaEventRecord(eCsr, s1);

    // ---- s0: convert X, then layer 0 ----
    {
        long n4 = (long)N * IN / 4;
        int blocks = (int)((n4 + 255) / 256); if (blocks > 2048) blocks = 2048;
        tohalf_kernel<<<blocks, 256>>>(X, Abuf, n4);
    }
    cudaStreamWaitEvent(0, eWall, 0);
    gemm(Abuf, IN, nullptr, 0, o_wv0, bv0, Xfeat, N, H, a0, score0, 0);   // Wv0 + fused score
    cudaEventRecord(eG1a, 0);

    // s1: Xinit GEMM (fp16 out) overlapped with v2e/Wt-GEMM
    cudaStreamWaitEvent(s1, eG1a, 0);
    gemm(Abuf, IN, nullptr, 0, o_wx0, bx0, Xinit, N, H, nullptr, nullptr, s1);
    cudaEventRecord(eX0, s1);

    cudaStreamWaitEvent(0, eCsr, 0);
    v2e_softmax_kernel<<<edgeWarpBlocks, 256>>>(Xfeat, score0, e_rowptr, eV, Yeh, M, H);
    gemm(Yeh, H, Sh, STAR, o_wt0, bt0, Ye2, M, H, nullptr, nullptr, 0);
    cudaStreamWaitEvent(0, eX0, 0);
    e2v_mean_kernel<<<nodeWarpBlocks, 256>>>(Ye2, v_rowptr, vE, Xinit, Bbuf, N, H);

    // ---- layer 1 ----
    gemm(Bbuf, H, nullptr, 0, o_wv1, bv1, Xfeat, N, H, a1, score1, 0);    // Wv1 + fused score
    cudaEventRecord(eG1b, 0);

    cudaStreamWaitEvent(s1, eG1b, 0);
    gemm(Bbuf, H, nullptr, 0, o_wx1, bx1, Xinit, N, H, nullptr, nullptr, s1);
    cudaEventRecord(eX1, s1);

    v2e_softmax_kernel<<<edgeWarpBlocks, 256>>>(Xfeat, score1, e_rowptr, eV, Yeh, M, H);
    gemm(Yeh, H, Sh, STAR, o_wt1, bt1, Ye2, M, H, nullptr, nullptr, 0);
    cudaStreamWaitEvent(0, eX1, 0);
    e2v_mean_kernel<<<nodeWarpBlocks, 256>>>(Ye2, v_rowptr, vE, Xinit, Abuf, N, H);

    // ---- hyperconv (s0) ----
    gemm(Abuf, H, nullptr, 0, o_wf, bf, Xfeat, N, OUT, nullptr, nullptr, 0);
    hyper_edge_kernel<<<edgeWarpBlocks, 256>>>(Xfeat, e_rowptr, eV, v_rowptr, Yeh, M, OUT);
    hyper_node_kernel<<<nodeWarpBlocks, 256>>>(Yeh, v_rowptr, vE, (float*)d_out, N, OUT);
}

// round 12
// speedup vs baseline: 6.3649x; 1.0274x over previous
#include <cuda_runtime.h>
#include <cuda_fp16.h>
#include <mma.h>
#include <math.h>
#include <stdint.h>

using namespace nvcuda;

// ---------------------------------------------------------------------------
// Problem max sizes
// ---------------------------------------------------------------------------
#define NMAX   50000
#define MMAX   20000
#define NNZMAX 400000
#define HMAX   256
#define WTOTAL 393216

// ---------------------------------------------------------------------------
// Scratch (device globals)
// ---------------------------------------------------------------------------
__device__ float g_score0[NMAX];
__device__ float g_score1[NMAX];

__device__ __half g_Xinit[NMAX * HMAX];  // fp16 residual
__device__ __half g_Xfeat[NMAX * HMAX];  // fp16 GEMM outputs (Wv / Wf)
__device__ __half g_Ye2  [MMAX * HMAX];  // fp16 GEMM output (Wt)
__device__ __half g_A [NMAX * HMAX];     // activations (X / h2)
__device__ __half g_B [NMAX * HMAX];     // h1
__device__ __half g_Ye[MMAX * HMAX];     // v2e out / hyper_edge out
__device__ __half g_S [MMAX * 64];
__device__ __half g_Wh[WTOTAL];          // weights fp16, [K,N] row-major packed

// CSR structures
__device__ int g_e_rowptr[MMAX + 1];
__device__ int g_v_rowptr[NMAX + 1];
__device__ int g_e_cursor[MMAX];
__device__ int g_v_cursor[NMAX];
__device__ int g_cntE[MMAX];
__device__ int g_cntV[NMAX];
__device__ int g_eV[NNZMAX];
__device__ int g_vE[NNZMAX];

// ---------------------------------------------------------------------------
// Helpers
// ---------------------------------------------------------------------------
__device__ __forceinline__ float eluf(float x)  { return x > 0.f ? x : expm1f(x); }
__device__ __forceinline__ float leakyf(float x){ return x > 0.f ? x : 0.2f * x; }

__device__ __forceinline__ uint32_t smem_to_u32(const void* p) {
    uint32_t a;
    asm("{ .reg .u64 t; cvta.to.shared.u64 t, %1; cvt.u32.u64 %0, t; }" : "=r"(a) : "l"(p));
    return a;
}
__device__ __forceinline__ void cp_async16(uint32_t dst, const void* src, int sz) {
    asm volatile("cp.async.cg.shared.global [%0], [%1], 16, %2;"
                 :: "r"(dst), "l"(src), "r"(sz) : "memory");
}
#define CP_COMMIT() asm volatile("cp.async.commit_group;" ::: "memory")
#define CP_WAIT(n)  asm volatile("cp.async.wait_group %0;" :: "n"(n) : "memory")

__device__ __forceinline__ void conv_store4(float4 v, __half* p) {
    __half2 h0 = __floats2half2_rn(v.x, v.y);
    __half2 h1 = __floats2half2_rn(v.z, v.w);
    uint2 u;
    u.x = *reinterpret_cast<unsigned*>(&h0);
    u.y = *reinterpret_cast<unsigned*>(&h1);
    *reinterpret_cast<uint2*>(p) = u;
}

// activations: fp32 -> fp16 (X only)
__global__ void tohalf_kernel(const float* __restrict__ x, __half* __restrict__ out, long n4)
{
    long i = (long)blockIdx.x * blockDim.x + threadIdx.x;
    long stride = (long)gridDim.x * blockDim.x;
    for (; i < n4; i += stride)
        conv_store4(reinterpret_cast<const float4*>(x)[i], out + 4 * i);
}

// one kernel: 8 fp32->fp16 conversions + zero both score buffers
struct ConvJob { const float* src; __half* dst; long n4; };
struct ConvJobs {
    ConvJob j[8];
    float* sc0; float* sc1; int n_sc;
};
__global__ void conv_pack_kernel(ConvJobs jobs)
{
    int job = blockIdx.y;
    long i = (long)blockIdx.x * blockDim.x + threadIdx.x;
    long stride = (long)gridDim.x * blockDim.x;
    if (job < 8) {
        const float* src = jobs.j[job].src;
        __half* dst = jobs.j[job].dst;
        long n4 = jobs.j[job].n4;
        for (; i < n4; i += stride)
            conv_store4(reinterpret_cast<const float4*>(src)[i], dst + 4 * i);
    } else {
        for (; i < jobs.n_sc; i += stride) {
            jobs.sc0[i] = 0.f;
            jobs.sc1[i] = 0.f;
        }
    }
}

// zero both CSR count arrays in one kernel
__global__ void fill2_int(int* __restrict__ p0, int n0, int* __restrict__ p1, int n1)
{
    int i = blockIdx.x * blockDim.x + threadIdx.x;
    int stride = gridDim.x * blockDim.x;
    for (int k = i; k < n0; k += stride) p0[k] = 0;
    for (int k = i; k < n1; k += stride) p1[k] = 0;
}

// ---------------------------------------------------------------------------
// CSR construction
// ---------------------------------------------------------------------------
__global__ void count_kernel(const int* __restrict__ V, const int* __restrict__ E,
                             int* __restrict__ cntV, int* __restrict__ cntE, int nnz)
{
    int i = blockIdx.x * blockDim.x + threadIdx.x;
    if (i >= nnz) return;
    atomicAdd(&cntE[E[i]], 1);
    atomicAdd(&cntV[V[i]], 1);
}

// Warp-parallel 3-phase exclusive scan inside one block (1024 threads).
// len must be a multiple of 4 (M=20000, N=50000 both are).
__device__ void scan_body_par(const int* __restrict__ cnt, int* __restrict__ rowptr,
                              int* __restrict__ cursor, int len)
{
    __shared__ int wbase[33];
    const int tid = threadIdx.x, lane = tid & 31, wid = tid >> 5;
    // region size per warp: multiple of 128 covering len/32
    const int R = ((len + 32 * 128 - 1) / (32 * 128)) * 128;
    const int beg = wid * R;
    const int lim = (beg + R < len) ? beg + R : len;

    // Phase A: warp sums its region
    int s = 0;
    for (int i = beg + lane * 4; i < lim; i += 128) {
        int4 v = *reinterpret_cast<const int4*>(cnt + i);
        s += v.x + v.y + v.z + v.w;
    }
#pragma unroll
    for (int o = 16; o > 0; o >>= 1) s += __shfl_xor_sync(0xffffffffu, s, o);
    if (lane == 0) wbase[wid + 1] = s;
    if (tid == 0) wbase[0] = 0;
    __syncthreads();

    // Phase B: warp 0 scans the 32 warp totals (inclusive -> bases)
    if (wid == 0) {
        int t = wbase[lane + 1];
        int inc = t;
#pragma unroll
        for (int o = 1; o < 32; o <<= 1) {
            int u = __shfl_up_sync(0xffffffffu, inc, o);
            if (lane >= o) inc += u;
        }
        wbase[lane + 1] = inc;
    }
    __syncthreads();

    // Phase C: each warp independently writes prefixes for its region
    int carry = wbase[wid];
    for (int i0 = beg; i0 < lim; i0 += 128) {
        int i = i0 + lane * 4;
        int4 v = (i < lim) ? *reinterpret_cast<const int4*>(cnt + i)
                           : make_int4(0, 0, 0, 0);
        int t1 = v.x + v.y, t2 = t1 + v.z, t3 = t2 + v.w;
        int inc = t3;
#pragma unroll
        for (int o = 1; o < 32; o <<= 1) {
            int u = __shfl_up_sync(0xffffffffu, inc, o);
            if (lane >= o) inc += u;
        }
        int excl = carry + inc - t3;
        if (i < lim) {
            rowptr[i + 0] = excl;       cursor[i + 0] = excl;
            rowptr[i + 1] = excl + v.x; cursor[i + 1] = excl + v.x;
            rowptr[i + 2] = excl + t1;  cursor[i + 2] = excl + t1;
            rowptr[i + 3] = excl + t2;  cursor[i + 3] = excl + t2;
        }
        carry += __shfl_sync(0xffffffffu, inc, 31);
    }
    if (tid == 0) rowptr[len] = wbase[32];
}

// both scans in one launch (block 0: edges, block 1: nodes)
__global__ __launch_bounds__(1024)
void scan2_kernel(const int* cntE, int* e_rowptr, int* e_cursor, int lenE,
                  const int* cntV, int* v_rowptr, int* v_cursor, int lenV)
{
    if (blockIdx.x == 0) scan_body_par(cntE, e_rowptr, e_cursor, lenE);
    else                 scan_body_par(cntV, v_rowptr, v_cursor, lenV);
}

__global__ void fill_lists_kernel(const int* __restrict__ V, const int* __restrict__ E,
                                  int* __restrict__ e_cursor, int* __restrict__ v_cursor,
                                  int* __restrict__ eV, int* __restrict__ vE, int nnz)
{
    int i = blockIdx.x * blockDim.x + threadIdx.x;
    if (i >= nnz) return;
    int v = V[i], e = E[i];
    int pe = atomicAdd(&e_cursor[e], 1);
    eV[pe] = v;
    int pv = atomicAdd(&v_cursor[v], 1);
    vE[pv] = e;
}

// ---------------------------------------------------------------------------
// fp16 tensor-core GEMM (fp16 weights, fp16 out), cp.async double buffered.
// C[M,N] = [A1|A2] @ W + bias.
// Optional fused row-score: score[r] += dot(C_row_fp32, avec) (atomic).
// ---------------------------------------------------------------------------
struct GemmStage {
    __half A[128][40];
    __half B[32][136];
};
static constexpr int GEMM_SMEM = 2 * sizeof(GemmStage);   // 37888

__global__ __launch_bounds__(256, 2)
void gemm_fp16(const __half* __restrict__ A1, int K1,
               const __half* __restrict__ A2, int K2,
               const __half* __restrict__ Bg,
               const float* __restrict__ bias,
               __half* __restrict__ Ch,
               const float* __restrict__ avec, float* __restrict__ score_out,
               int M, int N)
{
    extern __shared__ char smem_raw[];
    GemmStage* st = reinterpret_cast<GemmStage*>(smem_raw);

    const int tid  = threadIdx.x;
    const int wid  = tid >> 5, lane = tid & 31;
    const int wm   = wid >> 1, wn = wid & 1;
    const int row0 = blockIdx.y * 128;
    const int col0 = blockIdx.x * 128;
    const int K = K1 + K2, nch = K >> 5;

    wmma::fragment<wmma::accumulator, 16, 16, 16, float> acc[2][4];
#pragma unroll
    for (int mt = 0; mt < 2; mt++)
#pragma unroll
        for (int nt = 0; nt < 4; nt++) wmma::fill_fragment(acc[mt][nt], 0.f);

    auto prefetch = [&](int c, int s) {
        const int k0 = c * 32;
        const __half* a; int lda, col;
        if (k0 < K1) { a = A1; lda = K1; col = k0; }
        else         { a = A2; lda = K2; col = k0 - K1; }
#pragma unroll
        for (int t = 0; t < 2; t++) {
            int u = tid + t * 256, r = u >> 2, q = u & 3;
            int gr = row0 + r;
            int sz = (gr < M) ? 16 : 0;
            size_t off = (size_t)(gr < M ? gr : 0) * lda + col + q * 8;
            cp_async16(smem_to_u32(&st[s].A[r][q * 8]), a + off, sz);
        }
#pragma unroll
        for (int t = 0; t < 2; t++) {
            int u = tid + t * 256, r = u >> 4, q = u & 15;
            size_t off = (size_t)(k0 + r) * N + col0 + q * 8;
            cp_async16(smem_to_u32(&st[s].B[r][q * 8]), Bg + off, 16);
        }
    };

    prefetch(0, 0);
    CP_COMMIT();

    for (int c = 0; c < nch; c++) {
        const int s = c & 1;
        if (c + 1 < nch) {
            prefetch(c + 1, s ^ 1);
            CP_COMMIT();
            CP_WAIT(1);
        } else {
            CP_WAIT(0);
        }
        __syncthreads();

#pragma unroll
        for (int ks = 0; ks < 2; ks++) {
            wmma::fragment<wmma::matrix_a, 16, 16, 16, __half, wmma::row_major> af[2];
#pragma unroll
            for (int mt = 0; mt < 2; mt++)
                wmma::load_matrix_sync(af[mt], &st[s].A[wm * 32 + mt * 16][ks * 16], 40);
#pragma unroll
            for (int nt = 0; nt < 4; nt++) {
                wmma::fragment<wmma::matrix_b, 16, 16, 16, __half, wmma::row_major> bf;
                wmma::load_matrix_sync(bf, &st[s].B[ks * 16][wn * 64 + nt * 16], 136);
#pragma unroll
                for (int mt = 0; mt < 2; mt++)
                    wmma::mma_sync(acc[mt][nt], af[mt], bf, acc[mt][nt]);
            }
        }
        __syncthreads();
    }

    // epilogue: stage 16x16 tiles in smem, add bias, optional score, store fp16
    float* stg = reinterpret_cast<float*>(smem_raw) + wid * 320;
#pragma unroll
    for (int mt = 0; mt < 2; mt++) {
        float sacc = 0.f;
        int grow_last = -1;
#pragma unroll
        for (int nt = 0; nt < 4; nt++) {
            wmma::store_matrix_sync(stg, acc[mt][nt], 20, wmma::mem_row_major);
            __syncwarp();
            int r = lane >> 1, cofs = (lane & 1) * 8;
            int gr = row0 + wm * 32 + mt * 16 + r;
            int gc = col0 + wn * 64 + nt * 16 + cofs;
            grow_last = gr;
            if (gr < M) {
                float o[8];
#pragma unroll
                for (int j = 0; j < 8; j++) o[j] = stg[r * 20 + cofs + j] + __ldg(&bias[gc + j]);
                if (score_out) {
#pragma unroll
                    for (int j = 0; j < 8; j++) sacc += o[j] * __ldg(&avec[gc + j]);
                }
                uint4 u;
                __half2 p0 = __floats2half2_rn(o[0], o[1]);
                __half2 p1 = __floats2half2_rn(o[2], o[3]);
                __half2 p2 = __floats2half2_rn(o[4], o[5]);
                __half2 p3 = __floats2half2_rn(o[6], o[7]);
                u.x = *reinterpret_cast<unsigned*>(&p0);
                u.y = *reinterpret_cast<unsigned*>(&p1);
                u.z = *reinterpret_cast<unsigned*>(&p2);
                u.w = *reinterpret_cast<unsigned*>(&p3);
                *reinterpret_cast<uint4*>(Ch + (size_t)gr * N + gc) = u;
            }
            __syncwarp();
        }
        if (score_out && grow_last >= 0 && grow_last < M)
            atomicAdd(&score_out[grow_last], sacc);
    }
}

// ---------------------------------------------------------------------------
// Fused v2e: segment softmax + weighted fp16 gather + elu -> fp16 out (x4)
// ---------------------------------------------------------------------------
__global__ __launch_bounds__(256)
void v2e_softmax_kernel(const __half* __restrict__ Xfeat, const float* __restrict__ score,
                        const int* __restrict__ e_rowptr, const int* __restrict__ eV,
                        __half* __restrict__ Ye, int M, int H)
{
    int warp = (blockIdx.x * blockDim.x + threadIdx.x) >> 5;
    int lane = threadIdx.x & 31;
    if (warp >= M) return;
    const int beg = e_rowptr[warp];
    const int end = e_rowptr[warp + 1];

    float m = -1e30f;
    for (int j = beg + lane; j < end; j += 32)
        m = fmaxf(m, leakyf(__ldg(&score[eV[j]])));
#pragma unroll
    for (int o = 16; o > 0; o >>= 1) m = fmaxf(m, __shfl_xor_sync(0xffffffffu, m, o));

    float den = 0.f;
    for (int j = beg + lane; j < end; j += 32)
        den += expf(leakyf(__ldg(&score[eV[j]])) - m);
#pragma unroll
    for (int o = 16; o > 0; o >>= 1) den += __shfl_xor_sync(0xffffffffu, den, o);
    float invden = (end > beg) ? 1.f / den : 0.f;

    float acc[8];
#pragma unroll
    for (int k = 0; k < 8; k++) acc[k] = 0.f;

    int j = beg;
    for (; j + 4 <= end; j += 4) {
        int v0 = eV[j], v1 = eV[j + 1], v2 = eV[j + 2], v3 = eV[j + 3];
        float w0 = expf(leakyf(__ldg(&score[v0])) - m) * invden;
        float w1 = expf(leakyf(__ldg(&score[v1])) - m) * invden;
        float w2 = expf(leakyf(__ldg(&score[v2])) - m) * invden;
        float w3 = expf(leakyf(__ldg(&score[v3])) - m) * invden;
        uint4 u0 = __ldg(reinterpret_cast<const uint4*>(Xfeat + (size_t)v0 * H) + lane);
        uint4 u1 = __ldg(reinterpret_cast<const uint4*>(Xfeat + (size_t)v1 * H) + lane);
        uint4 u2 = __ldg(reinterpret_cast<const uint4*>(Xfeat + (size_t)v2 * H) + lane);
        uint4 u3 = __ldg(reinterpret_cast<const uint4*>(Xfeat + (size_t)v3 * H) + lane);
        const __half2* h0 = reinterpret_cast<const __half2*>(&u0);
        const __half2* h1 = reinterpret_cast<const __half2*>(&u1);
        const __half2* h2 = reinterpret_cast<const __half2*>(&u2);
        const __half2* h3 = reinterpret_cast<const __half2*>(&u3);
#pragma unroll
        for (int k = 0; k < 4; k++) {
            float2 f0 = __half22float2(h0[k]);
            float2 f1 = __half22float2(h1[k]);
            float2 f2 = __half22float2(h2[k]);
            float2 f3 = __half22float2(h3[k]);
            acc[2 * k + 0] = fmaf(f0.x, w0, fmaf(f1.x, w1, fmaf(f2.x, w2, fmaf(f3.x, w3, acc[2 * k + 0]))));
            acc[2 * k + 1] = fmaf(f0.y, w0, fmaf(f1.y, w1, fmaf(f2.y, w2, fmaf(f3.y, w3, acc[2 * k + 1]))));
        }
    }
    for (; j < end; j++) {
        int v = eV[j];
        float w = expf(leakyf(__ldg(&score[v])) - m) * invden;
        uint4 u = __ldg(reinterpret_cast<const uint4*>(Xfeat + (size_t)v * H) + lane);
        const __half2* h = reinterpret_cast<const __half2*>(&u);
#pragma unroll
        for (int k = 0; k < 4; k++) {
            float2 f = __half22float2(h[k]);
            acc[2 * k + 0] = fmaf(f.x, w, acc[2 * k + 0]);
            acc[2 * k + 1] = fmaf(f.y, w, acc[2 * k + 1]);
        }
    }

    uint4 u;
    __half2 p0 = __floats2half2_rn(eluf(acc[0]), eluf(acc[1]));
    __half2 p1 = __floats2half2_rn(eluf(acc[2]), eluf(acc[3]));
    __half2 p2 = __floats2half2_rn(eluf(acc[4]), eluf(acc[5]));
    __half2 p3 = __floats2half2_rn(eluf(acc[6]), eluf(acc[7]));
    u.x = *reinterpret_cast<unsigned*>(&p0);
    u.y = *reinterpret_cast<unsigned*>(&p1);
    u.z = *reinterpret_cast<unsigned*>(&p2);
    u.w = *reinterpret_cast<unsigned*>(&p3);
    *(reinterpret_cast<uint4*>(Ye + (size_t)warp * H) + lane) = u;
}

// ---------------------------------------------------------------------------
// Fused e2v: mean (fp16 gather, x4) + elu + residual (fp16) -> fp16 out
// ---------------------------------------------------------------------------
__global__ __launch_bounds__(256)
void e2v_mean_kernel(const __half* __restrict__ Ye2,
                     const int* __restrict__ v_rowptr, const int* __restrict__ vE,
                     const __half* __restrict__ Xinit,
                     __half* __restrict__ hout, int N, int H)
{
    int warp = (blockIdx.x * blockDim.x + threadIdx.x) >> 5;
    int lane = threadIdx.x & 31;
    if (warp >= N) return;
    const int beg = v_rowptr[warp];
    const int end = v_rowptr[warp + 1];

    float acc[8];
#pragma unroll
    for (int k = 0; k < 8; k++) acc[k] = 0.f;

    int j = beg;
    for (; j + 4 <= end; j += 4) {
        int e0 = vE[j], e1 = vE[j + 1], e2 = vE[j + 2], e3 = vE[j + 3];
        uint4 u0 = __ldg(reinterpret_cast<const uint4*>(Ye2 + (size_t)e0 * H) + lane);
        uint4 u1 = __ldg(reinterpret_cast<const uint4*>(Ye2 + (size_t)e1 * H) + lane);
        uint4 u2 = __ldg(reinterpret_cast<const uint4*>(Ye2 + (size_t)e2 * H) + lane);
        uint4 u3 = __ldg(reinterpret_cast<const uint4*>(Ye2 + (size_t)e3 * H) + lane);
        const __half2* h0 = reinterpret_cast<const __half2*>(&u0);
        const __half2* h1 = reinterpret_cast<const __half2*>(&u1);
        const __half2* h2 = reinterpret_cast<const __half2*>(&u2);
        const __half2* h3 = reinterpret_cast<const __half2*>(&u3);
#pragma unroll
        for (int k = 0; k < 4; k++) {
            float2 f0 = __half22float2(h0[k]);
            float2 f1 = __half22float2(h1[k]);
            float2 f2 = __half22float2(h2[k]);
            float2 f3 = __half22float2(h3[k]);
            acc[2 * k + 0] += (f0.x + f1.x) + (f2.x + f3.x);
            acc[2 * k + 1] += (f0.y + f1.y) + (f2.y + f3.y);
        }
    }
    for (; j < end; j++) {
        int e = vE[j];
        uint4 u = __ldg(reinterpret_cast<const uint4*>(Ye2 + (size_t)e * H) + lane);
        const __half2* h = reinterpret_cast<const __half2*>(&u);
#pragma unroll
        for (int k = 0; k < 4; k++) {
            float2 f = __half22float2(h[k]);
            acc[2 * k + 0] += f.x;
            acc[2 * k + 1] += f.y;
        }
    }
    float inv = (end > beg) ? 1.f / (float)(end - beg) : 0.f;

    uint4 ri = __ldg(reinterpret_cast<const uint4*>(Xinit + (size_t)warp * H) + lane);
    const __half2* rh = reinterpret_cast<const __half2*>(&ri);
    float o[8];
#pragma unroll
    for (int k = 0; k < 4; k++) {
        float2 r = __half22float2(rh[k]);
        o[2 * k + 0] = eluf(acc[2 * k + 0] * inv) + r.x;
        o[2 * k + 1] = eluf(acc[2 * k + 1] * inv) + r.y;
    }

    uint4 u;
    __half2 p0 = __floats2half2_rn(o[0], o[1]);
    __half2 p1 = __floats2half2_rn(o[2], o[3]);
    __half2 p2 = __floats2half2_rn(o[4], o[5]);
    __half2 p3 = __floats2half2_rn(o[6], o[7]);
    u.x = *reinterpret_cast<unsigned*>(&p0);
    u.y = *reinterpret_cast<unsigned*>(&p1);
    u.z = *reinterpret_cast<unsigned*>(&p2);
    u.w = *reinterpret_cast<unsigned*>(&p3);
    *(reinterpret_cast<uint4*>(hout + (size_t)warp * H) + lane) = u;
}

// ---------------------------------------------------------------------------
// Hyperconv edge: fp16 gather (x4), fp16 out.  O == 128.
// ---------------------------------------------------------------------------
__global__ __launch_bounds__(256)
void hyper_edge_kernel(const __half* __restrict__ Xn,
                       const int* __restrict__ e_rowptr, const int* __restrict__ eV,
                       const int* __restrict__ v_rowptr,
                       __half* __restrict__ Ye, int M, int O)
{
    int warp = (blockIdx.x * blockDim.x + threadIdx.x) >> 5;
    int lane = threadIdx.x & 31;
    if (warp >= M) return;
    const int beg = e_rowptr[warp];
    const int end = e_rowptr[warp + 1];
    const int cnt = end - beg;

    float sumDv = 0.f;
    for (int j = beg + lane; j < end; j += 32) {
        int v = eV[j];
        sumDv += (float)(__ldg(&v_rowptr[v + 1]) - __ldg(&v_rowptr[v]));
    }
#pragma unroll
    for (int o = 16; o > 0; o >>= 1) sumDv += __shfl_xor_sync(0xffffffffu, sumDv, o);

    float acc[4];
#pragma unroll
    for (int k = 0; k < 4; k++) acc[k] = 0.f;

    int j = beg;
    for (; j + 4 <= end; j += 4) {
        int v0 = eV[j], v1 = eV[j + 1], v2 = eV[j + 2], v3 = eV[j + 3];
        uint2 u0 = __ldg(reinterpret_cast<const uint2*>(Xn + (size_t)v0 * O) + lane);
        uint2 u1 = __ldg(reinterpret_cast<const uint2*>(Xn + (size_t)v1 * O) + lane);
        uint2 u2 = __ldg(reinterpret_cast<const uint2*>(Xn + (size_t)v2 * O) + lane);
        uint2 u3 = __ldg(reinterpret_cast<const uint2*>(Xn + (size_t)v3 * O) + lane);
        const __half2* h0 = reinterpret_cast<const __half2*>(&u0);
        const __half2* h1 = reinterpret_cast<const __half2*>(&u1);
        const __half2* h2 = reinterpret_cast<const __half2*>(&u2);
        const __half2* h3 = reinterpret_cast<const __half2*>(&u3);
#pragma unroll
        for (int k = 0; k < 2; k++) {
            float2 f0 = __half22float2(h0[k]);
            float2 f1 = __half22float2(h1[k]);
            float2 f2 = __half22float2(h2[k]);
            float2 f3 = __half22float2(h3[k]);
            acc[2 * k + 0] += (f0.x + f1.x) + (f2.x + f3.x);
            acc[2 * k + 1] += (f0.y + f1.y) + (f2.y + f3.y);
        }
    }
    for (; j < end; j++) {
        int v = eV[j];
        uint2 u = __ldg(reinterpret_cast<const uint2*>(Xn + (size_t)v * O) + lane);
        const __half2* h = reinterpret_cast<const __half2*>(&u);
        float2 f0 = __half22float2(h[0]), f1 = __half22float2(h[1]);
        acc[0] += f0.x; acc[1] += f0.y; acc[2] += f1.x; acc[3] += f1.y;
    }

    float invc = (cnt > 0) ? 1.f / (float)cnt : 0.f;
    float De = sumDv / ((float)cnt + 1.f);
    float dinv = (De > 0.f) ? rsqrtf(De) : 1.f;
    float s = invc * dinv;

    uint2 u;
    __half2 p0 = __floats2half2_rn(acc[0] * s, acc[1] * s);
    __half2 p1 = __floats2half2_rn(acc[2] * s, acc[3] * s);
    u.x = *reinterpret_cast<unsigned*>(&p0);
    u.y = *reinterpret_cast<unsigned*>(&p1);
    *(reinterpret_cast<uint2*>(Ye + (size_t)warp * O) + lane) = u;
}

// ---------------------------------------------------------------------------
// Hyperconv node: fp16 gather (x4), fp32 out (final output)
// ---------------------------------------------------------------------------
__global__ __launch_bounds__(256)
void hyper_node_kernel(const __half* __restrict__ Ye,
                       const int* __restrict__ v_rowptr, const int* __restrict__ vE,
                       float* __restrict__ out, int N, int O)
{
    int warp = (blockIdx.x * blockDim.x + threadIdx.x) >> 5;
    int lane = threadIdx.x & 31;
    if (warp >= N) return;
    const int beg = v_rowptr[warp];
    const int end = v_rowptr[warp + 1];
    const int deg = end - beg;

    float acc[4];
#pragma unroll
    for (int k = 0; k < 4; k++) acc[k] = 0.f;

    int j = beg;
    for (; j + 4 <= end; j += 4) {
        int e0 = vE[j], e1 = vE[j + 1], e2 = vE[j + 2], e3 = vE[j + 3];
        uint2 u0 = __ldg(reinterpret_cast<const uint2*>(Ye + (size_t)e0 * O) + lane);
        uint2 u1 = __ldg(reinterpret_cast<const uint2*>(Ye + (size_t)e1 * O) + lane);
        uint2 u2 = __ldg(reinterpret_cast<const uint2*>(Ye + (size_t)e2 * O) + lane);
        uint2 u3 = __ldg(reinterpret_cast<const uint2*>(Ye + (size_t)e3 * O) + lane);
        const __half2* h0 = reinterpret_cast<const __half2*>(&u0);
        const __half2* h1 = reinterpret_cast<const __half2*>(&u1);
        const __half2* h2 = reinterpret_cast<const __half2*>(&u2);
        const __half2* h3 = reinterpret_cast<const __half2*>(&u3);
#pragma unroll
        for (int k = 0; k < 2; k++) {
            float2 f0 = __half22float2(h0[k]);
            float2 f1 = __half22float2(h1[k]);
            float2 f2 = __half22float2(h2[k]);
            float2 f3 = __half22float2(h3[k]);
            acc[2 * k + 0] += (f0.x + f1.x) + (f2.x + f3.x);
            acc[2 * k + 1] += (f0.y + f1.y) + (f2.y + f3.y);
        }
    }
    for (; j < end; j++) {
        int e = vE[j];
        uint2 u = __ldg(reinterpret_cast<const uint2*>(Ye + (size_t)e * O) + lane);
        const __half2* h = reinterpret_cast<const __half2*>(&u);
        float2 f0 = __half22float2(h[0]), f1 = __half22float2(h[1]);
        acc[0] += f0.x; acc[1] += f0.y; acc[2] += f1.x; acc[3] += f1.y;
    }
    float dinv = (deg > 0) ? rsqrtf((float)deg) : 0.f;

    float4 o;
    o.x = acc[0] * dinv; o.y = acc[1] * dinv;
    o.z = acc[2] * dinv; o.w = acc[3] * dinv;
    *(reinterpret_cast<float4*>(out + (size_t)warp * O) + lane) = o;
}

// ---------------------------------------------------------------------------
// Host
// ---------------------------------------------------------------------------
static inline int ceil_div(int a, int b) { return (a + b - 1) / b; }

extern "C" void kernel_launch(void* const* d_in, const int* in_sizes, int n_in,
                              void* d_out, int out_size)
{
    const float* X   = (const float*)d_in[0];
    const int*   V   = (const int*)  d_in[1];
    const int*   E   = (const int*)  d_in[2];
    const float* S   = (const float*)d_in[3];
    const float* Wx0 = (const float*)d_in[4];
    const float* bx0 = (const float*)d_in[5];
    const float* Wv0 = (const float*)d_in[6];
    const float* bv0 = (const float*)d_in[7];
    const float* a0  = (const float*)d_in[8];
    const float* Wt0 = (const float*)d_in[9];
    const float* bt0 = (const float*)d_in[10];
    const float* Wx1 = (const float*)d_in[11];
    const float* bx1 = (const float*)d_in[12];
    const float* Wv1 = (const float*)d_in[13];
    const float* bv1 = (const float*)d_in[14];
    const float* a1  = (const float*)d_in[15];
    const float* Wt1 = (const float*)d_in[16];
    const float* bt1 = (const float*)d_in[17];
    const float* Wf  = (const float*)d_in[18];
    const float* bf  = (const float*)d_in[19];

    const int H    = in_sizes[5];              // 256
    const int IN   = in_sizes[4] / H;          // 128
    const int N    = in_sizes[0] / IN;         // 50000
    const int NNZ  = in_sizes[1];              // 400000
    const int HS   = in_sizes[9] / H;          // 320
    const int STAR = HS - H;                   // 64
    const int M    = in_sizes[3] / STAR;       // 20000
    const int OUT  = in_sizes[19];             // 128

    void* p;
    cudaGetSymbolAddress(&p, g_score0); float* score0 = (float*)p;
    cudaGetSymbolAddress(&p, g_score1); float* score1 = (float*)p;
    cudaGetSymbolAddress(&p, g_Xinit); __half* Xinit = (__half*)p;
    cudaGetSymbolAddress(&p, g_Xfeat); __half* Xfeat = (__half*)p;
    cudaGetSymbolAddress(&p, g_Ye2);   __half* Ye2   = (__half*)p;
    cudaGetSymbolAddress(&p, g_A);  __half* Abuf = (__half*)p;
    cudaGetSymbolAddress(&p, g_B);  __half* Bbuf = (__half*)p;
    cudaGetSymbolAddress(&p, g_Ye); __half* Yeh  = (__half*)p;
    cudaGetSymbolAddress(&p, g_S);  __half* Sh   = (__half*)p;
    cudaGetSymbolAddress(&p, g_Wh); __half* Wh   = (__half*)p;
    cudaGetSymbolAddress(&p, g_e_rowptr); int* e_rowptr = (int*)p;
    cudaGetSymbolAddress(&p, g_v_rowptr); int* v_rowptr = (int*)p;
    cudaGetSymbolAddress(&p, g_e_cursor); int* e_cursor = (int*)p;
    cudaGetSymbolAddress(&p, g_v_cursor); int* v_cursor = (int*)p;
    cudaGetSymbolAddress(&p, g_cntE);     int* cntE     = (int*)p;
    cudaGetSymbolAddress(&p, g_cntV);     int* cntV     = (int*)p;
    cudaGetSymbolAddress(&p, g_eV);       int* eV       = (int*)p;
    cudaGetSymbolAddress(&p, g_vE);       int* vE       = (int*)p;

    // one-time init (first call = correctness run, NOT under graph capture)
    static bool inited = false;
    static cudaStream_t s1 = 0, s2 = 0;
    static cudaEvent_t evFork, eWall, eCsr, eG1a, eX0, eG1b, eX1;
    if (!inited) {
        cudaFuncSetAttribute(gemm_fp16, cudaFuncAttributeMaxDynamicSharedMemorySize, GEMM_SMEM);
        int prLo = 0, prHi = 0;
        cudaDeviceGetStreamPriorityRange(&prLo, &prHi);
        if (cudaStreamCreateWithPriority(&s1, cudaStreamNonBlocking, prHi) != cudaSuccess) s1 = 0;
        if (cudaStreamCreateWithPriority(&s2, cudaStreamNonBlocking, prHi) != cudaSuccess) s2 = 0;
        cudaEventCreateWithFlags(&evFork, cudaEventDisableTiming);
        cudaEventCreateWithFlags(&eWall, cudaEventDisableTiming);
        cudaEventCreateWithFlags(&eCsr,  cudaEventDisableTiming);
        cudaEventCreateWithFlags(&eG1a,  cudaEventDisableTiming);
        cudaEventCreateWithFlags(&eX0,   cudaEventDisableTiming);
        cudaEventCreateWithFlags(&eG1b,  cudaEventDisableTiming);
        cudaEventCreateWithFlags(&eX1,   cudaEventDisableTiming);
        inited = true;
    }

    // weight offsets ([K,N] row-major, packed)
    const size_t o_wx0 = 0;
    const size_t o_wv0 = o_wx0 + (size_t)IN * H;
    const size_t o_wt0 = o_wv0 + (size_t)IN * H;
    const size_t o_wx1 = o_wt0 + (size_t)HS * H;
    const size_t o_wv1 = o_wx1 + (size_t)H * H;
    const size_t o_wt1 = o_wv1 + (size_t)H * H;
    const size_t o_wf  = o_wt1 + (size_t)HS * H;

    auto gemm = [&](const __half* a1, int K1, const __half* a2, int K2,
                    size_t woff, const float* bias, __half* C, int Mrows, int Ncols,
                    const float* avec, float* sc, cudaStream_t st) {
        dim3 grid(Ncols / 128, ceil_div(Mrows, 128));
        gemm_fp16<<<grid, 256, GEMM_SMEM, st>>>(a1, K1, a2, K2,
            Wh + woff, bias, C, avec, sc, Mrows, Ncols);
    };

    const int nnzBlocks      = ceil_div(NNZ, 256);
    const int edgeWarpBlocks = ceil_div(M, 8);
    const int nodeWarpBlocks = ceil_div(N, 8);

    // ---- fork ----
    cudaEventRecord(evFork, 0);
    cudaStreamWaitEvent(s1, evFork, 0);
    cudaStreamWaitEvent(s2, evFork, 0);

    // ---- s2: ONE kernel for all weight/S conversions + both score zeros ----
    {
        ConvJobs jobs;
        jobs.j[0] = { Wv0, Wh + o_wv0, (long)IN * H / 4 };
        jobs.j[1] = { Wx0, Wh + o_wx0, (long)IN * H / 4 };
        jobs.j[2] = { Wt0, Wh + o_wt0, (long)HS * H / 4 };
        jobs.j[3] = { Wx1, Wh + o_wx1, (long)H * H / 4 };
        jobs.j[4] = { Wv1, Wh + o_wv1, (long)H * H / 4 };
        jobs.j[5] = { Wt1, Wh + o_wt1, (long)HS * H / 4 };
        jobs.j[6] = { Wf,  Wh + o_wf,  (long)H * OUT / 4 };
        jobs.j[7] = { S,   Sh,         (long)M * STAR / 4 };
        jobs.sc0 = score0; jobs.sc1 = score1; jobs.n_sc = N;
        dim3 grid(80, 9);
        conv_pack_kernel<<<grid, 256, 0, s2>>>(jobs);
        cudaEventRecord(eWall, s2);
    }

    // ---- s1: CSR build (4 nodes, parallel scan) ----
    fill2_int<<<ceil_div(N, 256), 256, 0, s1>>>(cntE, M, cntV, N);
    count_kernel<<<nnzBlocks, 256, 0, s1>>>(V, E, cntV, cntE, NNZ);
    scan2_kernel<<<2, 1024, 0, s1>>>(cntE, e_rowptr, e_cursor, M,
                                     cntV, v_rowptr, v_cursor, N);
    fill_lists_kernel<<<nnzBlocks, 256, 0, s1>>>(V, E, e_cursor, v_cursor, eV, vE, NNZ);
    cudaEventRecord(eCsr, s1);

    // ---- s0: convert X, then layer 0 ----
    {
        long n4 = (long)N * IN / 4;
        int blocks = (int)((n4 + 255) / 256); if (blocks > 2048) blocks = 2048;
        tohalf_kernel<<<blocks, 256>>>(X, Abuf, n4);
    }
    cudaStreamWaitEvent(0, eWall, 0);
    gemm(Abuf, IN, nullptr, 0, o_wv0, bv0, Xfeat, N, H, a0, score0, 0);   // Wv0 + fused score
    cudaEventRecord(eG1a, 0);

    // s1: Xinit GEMM (fp16 out) overlapped with v2e/Wt-GEMM
    cudaStreamWaitEvent(s1, eG1a, 0);
    gemm(Abuf, IN, nullptr, 0, o_wx0, bx0, Xinit, N, H, nullptr, nullptr, s1);
    cudaEventRecord(eX0, s1);

    cudaStreamWaitEvent(0, eCsr, 0);
    v2e_softmax_kernel<<<edgeWarpBlocks, 256>>>(Xfeat, score0, e_rowptr, eV, Yeh, M, H);
    gemm(Yeh, H, Sh, STAR, o_wt0, bt0, Ye2, M, H, nullptr, nullptr, 0);
    cudaStreamWaitEvent(0, eX0, 0);
    e2v_mean_kernel<<<nodeWarpBlocks, 256>>>(Ye2, v_rowptr, vE, Xinit, Bbuf, N, H);

    // ---- layer 1 ----
    gemm(Bbuf, H, nullptr, 0, o_wv1, bv1, Xfeat, N, H, a1, score1, 0);    // Wv1 + fused score
    cudaEventRecord(eG1b, 0);

    cudaStreamWaitEvent(s1, eG1b, 0);
    gemm(Bbuf, H, nullptr, 0, o_wx1, bx1, Xinit, N, H, nullptr, nullptr, s1);
    cudaEventRecord(eX1, s1);

    v2e_softmax_kernel<<<edgeWarpBlocks, 256>>>(Xfeat, score1, e_rowptr, eV, Yeh, M, H);
    gemm(Yeh, H, Sh, STAR, o_wt1, bt1, Ye2, M, H, nullptr, nullptr, 0);
    cudaStreamWaitEvent(0, eX1, 0);
    e2v_mean_kernel<<<nodeWarpBlocks, 256>>>(Ye2, v_rowptr, vE, Xinit, Abuf, N, H);

    // ---- hyperconv (s0) ----
    gemm(Abuf, H, nullptr, 0, o_wf, bf, Xfeat, N, OUT, nullptr, nullptr, 0);
    hyper_edge_kernel<<<edgeWarpBlocks, 256>>>(Xfeat, e_rowptr, eV, v_rowptr, Yeh, M, OUT);
    hyper_node_kernel<<<nodeWarpBlocks, 256>>>(Yeh, v_rowptr, vE, (float*)d_out, N, OUT);
}